// round 1
// baseline (speedup 1.0000x reference)
#include <cuda_runtime.h>

// Problem constants
#define S_LEN   2048
#define D_MODEL 1024
#define NHEAD   16
#define DKH     64
#define BATCH   2
#define M_TOK   (BATCH * S_LEN)   // 4096

// Scratch (device globals: allocation-guard safe)
__device__ float g_Q[BATCH * NHEAD * S_LEN * DKH];   // [B,H,S,DK]  (Q == V per reference)
__device__ float g_K[BATCH * NHEAD * S_LEN * DKH];   // [B,H,S,DK]
__device__ float g_att[BATCH * S_LEN * D_MODEL];     // [B,S,D]

// ---------------------------------------------------------------------------
// SGEMM: C = A[M,K] @ W[K,N] + bias[N]
//   MODE 0: scatter output into head layout [B,H,S,DK]  (for Q/K projections)
//   MODE 1: plain row-major [M,N]                        (for output projection)
// BM=128, BN=128, BK=8, 256 threads, 8x8 per-thread microtile.
// M=4096, N=1024, K=1024 fixed (all tile-divisible; no bounds checks).
// ---------------------------------------------------------------------------
template <int MODE>
__global__ __launch_bounds__(256) void sgemm_bias(const float* __restrict__ A,
                                                  const float* __restrict__ W,
                                                  const float* __restrict__ bias,
                                                  float* __restrict__ out)
{
    const int K = 1024, N = 1024;
    __shared__ float As[8][128];   // transposed A tile: As[k][m]
    __shared__ float Bs[8][128];   // Bs[k][n]

    const int tid = threadIdx.x;
    const int tx = tid & 15;       // 16 thread cols
    const int ty = tid >> 4;       // 16 thread rows

    // load indices
    const int aRow = tid >> 1;            // 0..127
    const int aCol = (tid & 1) * 4;       // 0 or 4
    const int bRow = tid >> 5;            // 0..7
    const int bCol = (tid & 31) * 4;      // 0..124

    const float* Ap = A + (long)(blockIdx.y * 128) * K;
    const float* Wp = W + blockIdx.x * 128;

    float acc[8][8] = {};

    for (int k0 = 0; k0 < K; k0 += 8) {
        float4 a4 = *(const float4*)(Ap + (long)aRow * K + k0 + aCol);
        As[aCol + 0][aRow] = a4.x;
        As[aCol + 1][aRow] = a4.y;
        As[aCol + 2][aRow] = a4.z;
        As[aCol + 3][aRow] = a4.w;
        float4 b4 = *(const float4*)(Wp + (long)(k0 + bRow) * N + bCol);
        *(float4*)&Bs[bRow][bCol] = b4;
        __syncthreads();

#pragma unroll
        for (int kk = 0; kk < 8; kk++) {
            float4 a0 = *(float4*)&As[kk][ty * 8];
            float4 a1 = *(float4*)&As[kk][ty * 8 + 4];
            float4 b0 = *(float4*)&Bs[kk][tx * 8];
            float4 b1 = *(float4*)&Bs[kk][tx * 8 + 4];
            float ra[8] = {a0.x, a0.y, a0.z, a0.w, a1.x, a1.y, a1.z, a1.w};
            float rb[8] = {b0.x, b0.y, b0.z, b0.w, b1.x, b1.y, b1.z, b1.w};
#pragma unroll
            for (int i = 0; i < 8; i++)
#pragma unroll
                for (int j = 0; j < 8; j++)
                    acc[i][j] += ra[i] * rb[j];
        }
        __syncthreads();
    }

    // epilogue: bias + store
#pragma unroll
    for (int i = 0; i < 8; i++) {
        const int m = blockIdx.y * 128 + ty * 8 + i;
#pragma unroll
        for (int j = 0; j < 8; j += 4) {
            const int n = blockIdx.x * 128 + tx * 8 + j;
            float4 v;
            v.x = acc[i][j + 0] + bias[n + 0];
            v.y = acc[i][j + 1] + bias[n + 1];
            v.z = acc[i][j + 2] + bias[n + 2];
            v.w = acc[i][j + 3] + bias[n + 3];
            if (MODE == 1) {
                *(float4*)&out[(long)m * N + n] = v;
            } else {
                // m = b*S + s ; n = h*64 + dk   (dk%4==0, never crosses head)
                const int b  = m >> 11;        // /2048
                const int s  = m & 2047;
                const int h  = n >> 6;
                const int dk = n & 63;
                *(float4*)&out[(((long)(b * NHEAD + h)) * S_LEN + s) * DKH + dk] = v;
            }
        }
    }
}

// ---------------------------------------------------------------------------
// Flash attention (causal), V = Q (reference quirk).
// Block: 256 threads (16x16), BQ=BKV=64, DK=64. Per-thread 4x4 microtiles.
// Grid: (S/64, B*H).
// Dynamic smem layout (floats, rows padded to 68):
//   sQ  [64][68]  (r,d)      sKT [64][68] (d,c)
//   sV  [64][68]  (c,d)      sP  [64][68] (r,c)
//   sM[64], sL[64]
// ---------------------------------------------------------------------------
__global__ __launch_bounds__(256) void attn_kernel()
{
    extern __shared__ float sm[];
    float* sQ  = sm;                 // 64*68
    float* sKT = sQ  + 64 * 68;
    float* sV  = sKT + 64 * 68;
    float* sP  = sV  + 64 * 68;
    float* sM  = sP  + 64 * 68;
    float* sL  = sM  + 64;

    const int tid = threadIdx.x;
    const int tx = tid & 15;
    const int ty = tid >> 4;
    const int r0 = ty * 4;           // this thread's 4 q-rows
    const int c0 = tx * 4;           // this thread's 4 kv-cols / dk-cols
    const int qi = blockIdx.x;       // q tile index
    const int bh = blockIdx.y;       // b*H + h

    // load Q tile (row-major, float4)
    const float* Qb = g_Q + ((long)bh * S_LEN + qi * 64) * DKH;
    for (int f = tid; f < 1024; f += 256) {
        const int r = f >> 4, d0 = (f & 15) << 2;
        *(float4*)&sQ[r * 68 + d0] = *(const float4*)(Qb + r * 64 + d0);
    }
    if (tid < 64) { sM[tid] = -1e30f; sL[tid] = 0.0f; }

    float O[4][4] = {};

    for (int j = 0; j <= qi; j++) {
        __syncthreads();   // prev PV done; also covers sQ/sM init on iter 0

        const float* Kb = g_K + ((long)bh * S_LEN + j * 64) * DKH;
        const float* Vb = g_Q + ((long)bh * S_LEN + j * 64) * DKH;  // V = Q

        // K transposed into smem (conflict-free smem stores)
        for (int f = tid; f < 1024; f += 256) {
            const int c = f & 63, d0 = (f >> 6) << 2;
            float4 v = *(const float4*)(Kb + c * 64 + d0);
            sKT[(d0 + 0) * 68 + c] = v.x;
            sKT[(d0 + 1) * 68 + c] = v.y;
            sKT[(d0 + 2) * 68 + c] = v.z;
            sKT[(d0 + 3) * 68 + c] = v.w;
        }
        // V row-major
        for (int f = tid; f < 1024; f += 256) {
            const int c = f >> 4, d0 = (f & 15) << 2;
            *(float4*)&sV[c * 68 + d0] = *(const float4*)(Vb + c * 64 + d0);
        }
        __syncthreads();

        // S = Q K^T (scalar Q broadcast, float4 K conflict-free)
        float s[4][4] = {};
#pragma unroll 16
        for (int d = 0; d < 64; d++) {
            float4 k4 = *(float4*)&sKT[d * 68 + c0];
            float kk[4] = {k4.x, k4.y, k4.z, k4.w};
#pragma unroll
            for (int i = 0; i < 4; i++) {
                float q = sQ[(r0 + i) * 68 + d];
#pragma unroll
                for (int jj = 0; jj < 4; jj++) s[i][jj] += q * kk[jj];
            }
        }
#pragma unroll
        for (int i = 0; i < 4; i++)
#pragma unroll
            for (int jj = 0; jj < 4; jj++) s[i][jj] *= 0.125f;  // 1/sqrt(64)

        if (j == qi) {  // diagonal tile causal mask
#pragma unroll
            for (int i = 0; i < 4; i++)
#pragma unroll
                for (int jj = 0; jj < 4; jj++)
                    if (c0 + jj > r0 + i) s[i][jj] = -1e30f;
        }

        // online softmax per row (16 lanes per row-group, shfl reduce)
#pragma unroll
        for (int i = 0; i < 4; i++) {
            float rm = fmaxf(fmaxf(s[i][0], s[i][1]), fmaxf(s[i][2], s[i][3]));
            rm = fmaxf(rm, __shfl_xor_sync(0xffffffffu, rm, 1));
            rm = fmaxf(rm, __shfl_xor_sync(0xffffffffu, rm, 2));
            rm = fmaxf(rm, __shfl_xor_sync(0xffffffffu, rm, 4));
            rm = fmaxf(rm, __shfl_xor_sync(0xffffffffu, rm, 8));
            const float mo = sM[r0 + i];
            const float mn = fmaxf(mo, rm);
            const float alpha = __expf(mo - mn);
            float4 p;
            p.x = __expf(s[i][0] - mn);
            p.y = __expf(s[i][1] - mn);
            p.z = __expf(s[i][2] - mn);
            p.w = __expf(s[i][3] - mn);
            *(float4*)&sP[(r0 + i) * 68 + c0] = p;
            float rs = p.x + p.y + p.z + p.w;
            rs += __shfl_xor_sync(0xffffffffu, rs, 1);
            rs += __shfl_xor_sync(0xffffffffu, rs, 2);
            rs += __shfl_xor_sync(0xffffffffu, rs, 4);
            rs += __shfl_xor_sync(0xffffffffu, rs, 8);
            __syncwarp();   // all lanes read sM before owner rewrites it
            if (tx == 0) {
                sM[r0 + i] = mn;
                sL[r0 + i] = sL[r0 + i] * alpha + rs;
            }
#pragma unroll
            for (int jj = 0; jj < 4; jj++) O[i][jj] *= alpha;
        }

        __syncthreads();   // sP visible

        // O += P @ V
#pragma unroll 16
        for (int c = 0; c < 64; c++) {
            float4 v4 = *(float4*)&sV[c * 68 + c0];
            float vv[4] = {v4.x, v4.y, v4.z, v4.w};
#pragma unroll
            for (int i = 0; i < 4; i++) {
                float p = sP[(r0 + i) * 68 + c];
#pragma unroll
                for (int jj = 0; jj < 4; jj++) O[i][jj] += p * vv[jj];
            }
        }
    }

    // epilogue: divide by l, write [B,S,D]
    const int b = bh >> 4, h = bh & 15;
#pragma unroll
    for (int i = 0; i < 4; i++) {
        const float inv = 1.0f / sL[r0 + i];
        const int srow = qi * 64 + r0 + i;
        float4 o;
        o.x = O[i][0] * inv; o.y = O[i][1] * inv;
        o.z = O[i][2] * inv; o.w = O[i][3] * inv;
        *(float4*)&g_att[((long)(b * S_LEN + srow)) * D_MODEL + h * DKH + c0] = o;
    }
}

// ---------------------------------------------------------------------------
extern "C" void kernel_launch(void* const* d_in, const int* in_sizes, int n_in,
                              void* d_out, int out_size)
{
    const float* x  = (const float*)d_in[0];
    const float* Wq = (const float*)d_in[1];
    const float* bq = (const float*)d_in[2];
    const float* Wk = (const float*)d_in[3];
    const float* bk = (const float*)d_in[4];
    const float* W0 = (const float*)d_in[5];
    const float* b0 = (const float*)d_in[6];
    float* out = (float*)d_out;

    float *dQ = nullptr, *dK = nullptr, *dA = nullptr;
    cudaGetSymbolAddress((void**)&dQ, g_Q);
    cudaGetSymbolAddress((void**)&dK, g_K);
    cudaGetSymbolAddress((void**)&dA, g_att);

    const int attn_smem = (4 * 64 * 68 + 128) * (int)sizeof(float);  // 70144 B
    cudaFuncSetAttribute(attn_kernel, cudaFuncAttributeMaxDynamicSharedMemorySize,
                         attn_smem);

    dim3 gemm_grid(D_MODEL / 128, M_TOK / 128);  // (8, 32)
    sgemm_bias<0><<<gemm_grid, 256>>>(x, Wq, bq, dQ);   // Q (== V)
    sgemm_bias<0><<<gemm_grid, 256>>>(x, Wk, bk, dK);   // K

    dim3 attn_grid(S_LEN / 64, BATCH * NHEAD);           // (32, 32)
    attn_kernel<<<attn_grid, 256, attn_smem>>>();

    sgemm_bias<1><<<gemm_grid, 256>>>(dA, W0, b0, out);  // output projection
}

// round 2
// speedup vs baseline: 1.0728x; 1.0728x over previous
#include <cuda_runtime.h>

#define S_LEN   2048
#define D_MODEL 1024
#define NHEAD   16
#define DKH     64
#define BATCH   2
#define M_TOK   (BATCH * S_LEN)   // 4096

typedef unsigned long long u64;

// Scratch (device globals: allocation-guard safe)
__device__ float g_Q[BATCH * NHEAD * S_LEN * DKH];   // [B,H,S,DK]  (Q == V per reference)
__device__ float g_K[BATCH * NHEAD * S_LEN * DKH];   // [B,H,S,DK]
__device__ float g_att[BATCH * S_LEN * D_MODEL];     // [B,S,D]

// ---------------- packed f32x2 helpers -------------------------------------
__device__ __forceinline__ u64 ffma2(u64 a, u64 b, u64 c) {
    u64 d;
    asm("fma.rn.f32x2 %0, %1, %2, %3;" : "=l"(d) : "l"(a), "l"(b), "l"(c));
    return d;
}
__device__ __forceinline__ u64 mul2(u64 a, u64 b) {
    u64 d;
    asm("mul.rn.f32x2 %0, %1, %2;" : "=l"(d) : "l"(a), "l"(b));
    return d;
}
__device__ __forceinline__ u64 bcast2(float x) {
    unsigned xi = __float_as_uint(x);
    u64 d;
    asm("mov.b64 %0, {%1, %2};" : "=l"(d) : "r"(xi), "r"(xi));
    return d;
}
__device__ __forceinline__ float lo2(u64 v) { return __uint_as_float((unsigned)v); }
__device__ __forceinline__ float hi2(u64 v) { return __uint_as_float((unsigned)(v >> 32)); }

// ---------------------------------------------------------------------------
// SGEMM body: C = A[M,K] @ W[K,N] + bias[N]   (M=4096,N=1024,K=1024)
// BM=128, BN=128, BK=8, 256 threads, 8x8 per-thread microtile via FFMA2.
//   MODE 0: scatter output into head layout [B,H,S,DK]
//   MODE 1: plain row-major [M,N]
// ---------------------------------------------------------------------------
template <int MODE>
__device__ __forceinline__ void gemm_body(const float* __restrict__ A,
                                          const float* __restrict__ W,
                                          const float* __restrict__ bias,
                                          float* __restrict__ out)
{
    const int K = 1024, N = 1024;
    __shared__ float As[8][128];   // transposed A tile: As[k][m]
    __shared__ float Bs[8][128];   // Bs[k][n]

    const int tid = threadIdx.x;
    const int tx = tid & 15;
    const int ty = tid >> 4;

    const int aRow = tid >> 1;
    const int aCol = (tid & 1) * 4;
    const int bRow = tid >> 5;
    const int bCol = (tid & 31) * 4;

    const float* Ap = A + (long)(blockIdx.y * 128) * K;
    const float* Wp = W + blockIdx.x * 128;

    u64 acc2[8][4] = {};

    for (int k0 = 0; k0 < K; k0 += 8) {
        float4 a4 = *(const float4*)(Ap + (long)aRow * K + k0 + aCol);
        As[aCol + 0][aRow] = a4.x;
        As[aCol + 1][aRow] = a4.y;
        As[aCol + 2][aRow] = a4.z;
        As[aCol + 3][aRow] = a4.w;
        float4 b4 = *(const float4*)(Wp + (long)(k0 + bRow) * N + bCol);
        *(float4*)&Bs[bRow][bCol] = b4;
        __syncthreads();

#pragma unroll
        for (int kk = 0; kk < 8; kk++) {
            float4 a0 = *(float4*)&As[kk][ty * 8];
            float4 a1 = *(float4*)&As[kk][ty * 8 + 4];
            ulonglong2 b01 = *(ulonglong2*)&Bs[kk][tx * 8];
            ulonglong2 b23 = *(ulonglong2*)&Bs[kk][tx * 8 + 4];
            u64 rb[4] = {b01.x, b01.y, b23.x, b23.y};
            float ra[8] = {a0.x, a0.y, a0.z, a0.w, a1.x, a1.y, a1.z, a1.w};
#pragma unroll
            for (int i = 0; i < 8; i++) {
                u64 a2 = bcast2(ra[i]);
#pragma unroll
                for (int jj = 0; jj < 4; jj++)
                    acc2[i][jj] = ffma2(a2, rb[jj], acc2[i][jj]);
            }
        }
        __syncthreads();
    }

    // epilogue: unpack, add bias, store
#pragma unroll
    for (int i = 0; i < 8; i++) {
        const int m = blockIdx.y * 128 + ty * 8 + i;
#pragma unroll
        for (int jq = 0; jq < 2; jq++) {            // two float4 stores
            const int n = blockIdx.x * 128 + tx * 8 + jq * 4;
            float4 v;
            v.x = lo2(acc2[i][jq * 2 + 0]) + bias[n + 0];
            v.y = hi2(acc2[i][jq * 2 + 0]) + bias[n + 1];
            v.z = lo2(acc2[i][jq * 2 + 1]) + bias[n + 2];
            v.w = hi2(acc2[i][jq * 2 + 1]) + bias[n + 3];
            if (MODE == 1) {
                *(float4*)&out[(long)m * N + n] = v;
            } else {
                const int b  = m >> 11;
                const int s  = m & 2047;
                const int h  = n >> 6;
                const int dk = n & 63;
                *(float4*)&out[(((long)(b * NHEAD + h)) * S_LEN + s) * DKH + dk] = v;
            }
        }
    }
}

// Fused Q+K projection: blockIdx.z selects weight set (better wave packing).
__global__ __launch_bounds__(256) void qk_gemm(const float* __restrict__ x,
                                               const float* __restrict__ Wq,
                                               const float* __restrict__ bq,
                                               const float* __restrict__ Wk,
                                               const float* __restrict__ bk)
{
    if (blockIdx.z == 0) gemm_body<0>(x, Wq, bq, g_Q);
    else                 gemm_body<0>(x, Wk, bk, g_K);
}

__global__ __launch_bounds__(256) void out_gemm(const float* __restrict__ W0,
                                                const float* __restrict__ b0,
                                                float* __restrict__ out)
{
    gemm_body<1>(g_att, W0, b0, out);
}

// ---------------------------------------------------------------------------
// Flash attention (causal), V = Q (reference quirk).
// 256 threads (16x16), BQ=BKV=128, DK=64, 8x8 per-thread microtiles (FFMA2).
// PV splits the 128 kv cols between lane halves (tx<8 / tx>=8); partial O
// combined with shfl_xor(...,8) at the epilogue.
// Dynamic smem: sQ[128][68] sKT[64][132] sV[128][68] sP[128][132] sM/sL[128]
// ---------------------------------------------------------------------------
#define AT_SMEM_FLOATS (128*68 + 64*132 + 128*68 + 128*132 + 256)

__global__ __launch_bounds__(256, 1) void attn_kernel()
{
    extern __shared__ float smf[];
    float* sQ  = smf;                    // 128*68
    float* sKT = sQ  + 128 * 68;         // 64*132
    float* sV  = sKT + 64 * 132;         // 128*68
    float* sP  = sV  + 128 * 68;         // 128*132
    float* sM  = sP  + 128 * 132;        // 128
    float* sL  = sM  + 128;              // 128

    const int tid = threadIdx.x;
    const int tx = tid & 15;
    const int ty = tid >> 4;
    const int r0 = ty * 8;                 // 8 q-rows
    const int c0 = tx * 8;                 // 8 S-cols
    const int half = tx >> 3;              // PV: which kv-col half
    const int v0 = (tx & 7) * 8;           // PV: 8 dk-cols
    const int qi = (int)gridDim.x - 1 - (int)blockIdx.x;   // long tiles first
    const int bh = blockIdx.y;

    // load Q tile 128x64
    const float* Qb = g_Q + ((long)bh * S_LEN + qi * 128) * DKH;
    for (int f = tid; f < 2048; f += 256) {
        const int r = f >> 4, d0 = (f & 15) << 2;
        *(float4*)&sQ[r * 68 + d0] = *(const float4*)(Qb + r * 64 + d0);
    }
    if (tid < 128) { sM[tid] = -1e30f; sL[tid] = 0.0f; }

    u64 O2[8][4] = {};    // rows r0+i, dks v0..v0+7 (partial over this half's kv cols)

    for (int j = 0; j <= qi; j++) {
        __syncthreads();   // prev PV done reading sV; covers sQ/sM init on j=0

        const float* Kb = g_K + ((long)bh * S_LEN + j * 128) * DKH;
        const float* Vb = g_Q + ((long)bh * S_LEN + j * 128) * DKH;  // V = Q

        for (int f = tid; f < 2048; f += 256) {     // K transposed
            const int c = f & 127, d0 = (f >> 7) << 2;
            float4 v = *(const float4*)(Kb + c * 64 + d0);
            sKT[(d0 + 0) * 132 + c] = v.x;
            sKT[(d0 + 1) * 132 + c] = v.y;
            sKT[(d0 + 2) * 132 + c] = v.z;
            sKT[(d0 + 3) * 132 + c] = v.w;
        }
        for (int f = tid; f < 2048; f += 256) {     // V row-major
            const int r = f >> 4, d0 = (f & 15) << 2;
            *(float4*)&sV[r * 68 + d0] = *(const float4*)(Vb + r * 64 + d0);
        }
        __syncthreads();

        // ---- S = Q K^T (8x8 per thread, FFMA2) ----
        u64 s2[8][4] = {};
#pragma unroll 4
        for (int d = 0; d < 64; d++) {
            ulonglong2 kA = *(ulonglong2*)&sKT[d * 132 + c0];
            ulonglong2 kB = *(ulonglong2*)&sKT[d * 132 + c0 + 4];
            u64 kb[4] = {kA.x, kA.y, kB.x, kB.y};
#pragma unroll
            for (int i = 0; i < 8; i++) {
                u64 a2 = bcast2(sQ[(r0 + i) * 68 + d]);
#pragma unroll
                for (int jj = 0; jj < 4; jj++)
                    s2[i][jj] = ffma2(a2, kb[jj], s2[i][jj]);
            }
        }

        // ---- online softmax, per row ----
#pragma unroll
        for (int i = 0; i < 8; i++) {
            float s[8];
#pragma unroll
            for (int jj = 0; jj < 4; jj++) {
                s[2 * jj]     = lo2(s2[i][jj]) * 0.125f;   // 1/sqrt(64)
                s[2 * jj + 1] = hi2(s2[i][jj]) * 0.125f;
            }
            if (j == qi) {
                const int r = r0 + i;
#pragma unroll
                for (int jj = 0; jj < 8; jj++)
                    if (c0 + jj > r) s[jj] = -1e30f;
            }
            float rm = s[0];
#pragma unroll
            for (int jj = 1; jj < 8; jj++) rm = fmaxf(rm, s[jj]);
            rm = fmaxf(rm, __shfl_xor_sync(0xffffffffu, rm, 1));
            rm = fmaxf(rm, __shfl_xor_sync(0xffffffffu, rm, 2));
            rm = fmaxf(rm, __shfl_xor_sync(0xffffffffu, rm, 4));
            rm = fmaxf(rm, __shfl_xor_sync(0xffffffffu, rm, 8));
            const float mo = sM[r0 + i];
            const float mn = fmaxf(mo, rm);
            const float alpha = __expf(mo - mn);
            float p[8], rs = 0.0f;
#pragma unroll
            for (int jj = 0; jj < 8; jj++) { p[jj] = __expf(s[jj] - mn); rs += p[jj]; }
            *(float4*)&sP[(r0 + i) * 132 + c0]     = make_float4(p[0], p[1], p[2], p[3]);
            *(float4*)&sP[(r0 + i) * 132 + c0 + 4] = make_float4(p[4], p[5], p[6], p[7]);
            rs += __shfl_xor_sync(0xffffffffu, rs, 1);
            rs += __shfl_xor_sync(0xffffffffu, rs, 2);
            rs += __shfl_xor_sync(0xffffffffu, rs, 4);
            rs += __shfl_xor_sync(0xffffffffu, rs, 8);
            __syncwarp();                 // all lanes read sM before owner rewrites
            if (tx == 0) { sM[r0 + i] = mn; sL[r0 + i] = sL[r0 + i] * alpha + rs; }
            const u64 al2 = bcast2(alpha);
#pragma unroll
            for (int jj = 0; jj < 4; jj++) O2[i][jj] = mul2(al2, O2[i][jj]);
        }
        __syncwarp();   // sP visible within warp (P rows are warp-local)

        // ---- O += P @ V over this half's 64 kv cols ----
        const int cb = half * 64;
#pragma unroll 4
        for (int c = 0; c < 64; c++) {
            const int cc = cb + c;
            ulonglong2 vA = *(ulonglong2*)&sV[cc * 68 + v0];
            ulonglong2 vB = *(ulonglong2*)&sV[cc * 68 + v0 + 4];
            u64 vb[4] = {vA.x, vA.y, vB.x, vB.y};
#pragma unroll
            for (int i = 0; i < 8; i++) {
                u64 p2 = bcast2(sP[(r0 + i) * 132 + cc]);
#pragma unroll
                for (int jj = 0; jj < 4; jj++)
                    O2[i][jj] = ffma2(p2, vb[jj], O2[i][jj]);
            }
        }
    }

    __syncwarp();   // sL final values visible within warp

    // epilogue: combine halves (shfl xor 8), divide by l, write [B,S,D]
    const int b = bh >> 4, h = bh & 15;
#pragma unroll
    for (int i = 0; i < 8; i++) {
        const float inv = 1.0f / sL[r0 + i];
        float o[8];
#pragma unroll
        for (int jj = 0; jj < 4; jj++) {
            u64 mine  = O2[i][jj];
            u64 other = __shfl_xor_sync(0xffffffffu, mine, 8);
            o[2 * jj]     = (lo2(mine) + lo2(other)) * inv;
            o[2 * jj + 1] = (hi2(mine) + hi2(other)) * inv;
        }
        if (half == 0) {
            const int srow = qi * 128 + r0 + i;
            float* dst = &g_att[((long)(b * S_LEN + srow)) * D_MODEL + h * DKH + v0];
            *(float4*)(dst)     = make_float4(o[0], o[1], o[2], o[3]);
            *(float4*)(dst + 4) = make_float4(o[4], o[5], o[6], o[7]);
        }
    }
}

// ---------------------------------------------------------------------------
extern "C" void kernel_launch(void* const* d_in, const int* in_sizes, int n_in,
                              void* d_out, int out_size)
{
    const float* x  = (const float*)d_in[0];
    const float* Wq = (const float*)d_in[1];
    const float* bq = (const float*)d_in[2];
    const float* Wk = (const float*)d_in[3];
    const float* bk = (const float*)d_in[4];
    const float* W0 = (const float*)d_in[5];
    const float* b0 = (const float*)d_in[6];
    float* out = (float*)d_out;

    const int attn_smem = AT_SMEM_FLOATS * (int)sizeof(float);  // 172,032 B
    cudaFuncSetAttribute(attn_kernel, cudaFuncAttributeMaxDynamicSharedMemorySize,
                         attn_smem);

    dim3 qk_grid(D_MODEL / 128, M_TOK / 128, 2);   // (8, 32, 2)
    qk_gemm<<<qk_grid, 256>>>(x, Wq, bq, Wk, bk);

    dim3 attn_grid(S_LEN / 128, BATCH * NHEAD);     // (16, 32)
    attn_kernel<<<attn_grid, 256, attn_smem>>>();

    dim3 out_grid(D_MODEL / 128, M_TOK / 128);      // (8, 32)
    out_gemm<<<out_grid, 256>>>(W0, b0, out);
}

// round 4
// speedup vs baseline: 1.4290x; 1.3320x over previous
#include <cuda_runtime.h>
#include <cuda_bf16.h>

#define S_LEN   2048
#define D_MODEL 1024
#define NHEAD   16
#define DKH     64
#define BATCH   2
#define M_TOK   (BATCH * S_LEN)   // 4096

typedef unsigned long long u64;
typedef unsigned int u32;

// ------------------------------- scratch -----------------------------------
__device__ float g_Q[BATCH * NHEAD * S_LEN * DKH];     // [B,H,S,DK] (Q == V)
__device__ float g_K[BATCH * NHEAD * S_LEN * DKH];     // [B,H,S,DK]
__device__ float g_att[M_TOK * D_MODEL];               // [B,S,D]
__device__ __nv_bfloat16 g_Ah[M_TOK * D_MODEL];        // A hi (x, then att)
__device__ __nv_bfloat16 g_Al[M_TOK * D_MODEL];        // A lo
__device__ __nv_bfloat16 g_WhT[3][D_MODEL * D_MODEL];  // W^T hi: q,k,o
__device__ __nv_bfloat16 g_WlT[3][D_MODEL * D_MODEL];  // W^T lo

// --------------------------- small PTX helpers -----------------------------
__device__ __forceinline__ u64 ffma2(u64 a, u64 b, u64 c) {
    u64 d; asm("fma.rn.f32x2 %0, %1, %2, %3;" : "=l"(d) : "l"(a), "l"(b), "l"(c)); return d;
}
__device__ __forceinline__ u64 mul2(u64 a, u64 b) {
    u64 d; asm("mul.rn.f32x2 %0, %1, %2;" : "=l"(d) : "l"(a), "l"(b)); return d;
}
__device__ __forceinline__ u64 bcast2(float x) {
    unsigned xi = __float_as_uint(x); u64 d;
    asm("mov.b64 %0, {%1, %2};" : "=l"(d) : "r"(xi), "r"(xi)); return d;
}
__device__ __forceinline__ float lo2(u64 v) { return __uint_as_float((unsigned)v); }
__device__ __forceinline__ float hi2(u64 v) { return __uint_as_float((unsigned)(v >> 32)); }

__device__ __forceinline__ u32 smem_u32(const void* p) {
    u32 a; asm("{ .reg .u64 t; cvta.to.shared.u64 t, %1; cvt.u32.u64 %0, t; }" : "=r"(a) : "l"(p));
    return a;
}

#define CP_ASYNC16(dst, src) \
    asm volatile("cp.async.cg.shared.global [%0], [%1], 16;" :: "r"(dst), "l"(src))
#define CP_COMMIT()  asm volatile("cp.async.commit_group;" ::: "memory")
#define CP_WAIT1()   asm volatile("cp.async.wait_group 1;" ::: "memory")

__device__ __forceinline__ void ldsm_x4(u32& r0, u32& r1, u32& r2, u32& r3, u32 addr) {
    asm volatile("ldmatrix.sync.aligned.m8n8.x4.shared.b16 {%0,%1,%2,%3}, [%4];"
                 : "=r"(r0), "=r"(r1), "=r"(r2), "=r"(r3) : "r"(addr));
}

__device__ __forceinline__ void mma16816(float* d, u32 a0, u32 a1, u32 a2, u32 a3,
                                         u32 b0, u32 b1) {
    asm volatile("mma.sync.aligned.m16n8k16.row.col.f32.bf16.bf16.f32 "
                 "{%0,%1,%2,%3}, {%4,%5,%6,%7}, {%8,%9}, {%0,%1,%2,%3};"
                 : "+f"(d[0]), "+f"(d[1]), "+f"(d[2]), "+f"(d[3])
                 : "r"(a0), "r"(a1), "r"(a2), "r"(a3), "r"(b0), "r"(b1));
}

// ------------------------- fp32 -> bf16 hi/lo split -------------------------
__device__ __forceinline__ u32 pack_bf2(__nv_bfloat16 a, __nv_bfloat16 b) {
    __nv_bfloat162 p(a, b);
    return *reinterpret_cast<u32*>(&p);
}

__global__ __launch_bounds__(256) void decomp_A(const float* __restrict__ src,
                                                __nv_bfloat16* __restrict__ hi,
                                                __nv_bfloat16* __restrict__ lo)
{
    const int i = (blockIdx.x * 256 + threadIdx.x) * 4;
    float4 v = *(const float4*)(src + i);
    __nv_bfloat16 h0 = __float2bfloat16_rn(v.x);
    __nv_bfloat16 h1 = __float2bfloat16_rn(v.y);
    __nv_bfloat16 h2 = __float2bfloat16_rn(v.z);
    __nv_bfloat16 h3 = __float2bfloat16_rn(v.w);
    __nv_bfloat16 l0 = __float2bfloat16_rn(v.x - __bfloat162float(h0));
    __nv_bfloat16 l1 = __float2bfloat16_rn(v.y - __bfloat162float(h1));
    __nv_bfloat16 l2 = __float2bfloat16_rn(v.z - __bfloat162float(h2));
    __nv_bfloat16 l3 = __float2bfloat16_rn(v.w - __bfloat162float(h3));
    *(uint2*)(hi + i) = make_uint2(pack_bf2(h0, h1), pack_bf2(h2, h3));
    *(uint2*)(lo + i) = make_uint2(pack_bf2(l0, l1), pack_bf2(l2, l3));
}

// W [K,N] fp32 row-major -> WhT/WlT [N,K] bf16 row-major (transpose + split)
__global__ __launch_bounds__(256) void decomp_WT(const float* __restrict__ W,
                                                 __nv_bfloat16* __restrict__ hiT,
                                                 __nv_bfloat16* __restrict__ loT)
{
    __shared__ float t[32][33];
    const int tx = threadIdx.x, ty = threadIdx.y;     // (32, 8)
    const int n0 = blockIdx.x * 32, k0 = blockIdx.y * 32;
#pragma unroll
    for (int i = 0; i < 4; i++)
        t[ty + 8 * i][tx] = W[(k0 + ty + 8 * i) * D_MODEL + n0 + tx];
    __syncthreads();
#pragma unroll
    for (int i = 0; i < 4; i++) {
        float v = t[tx][ty + 8 * i];
        __nv_bfloat16 h = __float2bfloat16_rn(v);
        __nv_bfloat16 l = __float2bfloat16_rn(v - __bfloat162float(h));
        const long o = (long)(n0 + ty + 8 * i) * D_MODEL + k0 + tx;
        hiT[o] = h;
        loT[o] = l;
    }
}

// ---------------------------------------------------------------------------
// mma.sync split-bf16 GEMM: C[4096,1024] = A @ W + bias   (3 passes over K)
// BM=BN=128, BK=32, 256 threads (8 warps, 2x4), warp tile 64x32.
// SMEM rows padded to 80 B (conflict-free ldmatrix). cp.async double buffer.
//   MODE 0: scatter into [B,H,S,DK] ; MODE 1: row-major [M,N]
// ---------------------------------------------------------------------------
#define ROWB 80          // bytes per smem row (64 data + 16 pad)
#define TILEB (128 * ROWB)

template <int MODE>
__device__ __forceinline__ void tc_gemm_body(const __nv_bfloat16* __restrict__ Ah,
                                             const __nv_bfloat16* __restrict__ Al,
                                             const __nv_bfloat16* __restrict__ BhT,
                                             const __nv_bfloat16* __restrict__ BlT,
                                             const float* __restrict__ bias,
                                             float* __restrict__ out)
{
    __shared__ __align__(16) char smA[2][TILEB];
    __shared__ __align__(16) char smB[2][TILEB];

    const int tid = threadIdx.x;
    const int wid = tid >> 5;
    const int lane = tid & 31;
    const int warp_m = wid >> 2;          // 0..1
    const int warp_n = wid & 3;           // 0..3
    const int m0 = blockIdx.y * 128;
    const int n0 = blockIdx.x * 128;

    // ldmatrix lane addressing (within current buffer)
    const int a_row = (lane & 15);
    const int a_kh  = (lane >> 4);                 // 0/1 -> k-chunk
    const u32 aoff = (u32)((warp_m * 64 + a_row) * ROWB + a_kh * 16);
    const int b_row = (lane & 7) + ((lane >> 4) << 3);   // lanes16-31 -> +8 rows
    const int b_kh  = (lane >> 3) & 1;
    const u32 boff = (u32)((warp_n * 32 + b_row) * ROWB + b_kh * 16);

    const u32 smA0 = smem_u32(smA[0]);
    const u32 smB0 = smem_u32(smB[0]);

    float acc[4][4][4] = {};   // [mt][nt][reg]

    // async fill of chunk c into buffer p
    auto issue = [&](int c, int p) {
        const int pass = c >> 5;
        const int kc = c & 31;
        const __nv_bfloat16* As = (pass == 2) ? Al : Ah;
        const __nv_bfloat16* Bs = (pass == 1) ? BlT : BhT;
        const u32 dA = smA0 + p * TILEB;
        const u32 dB = smB0 + p * TILEB;
#pragma unroll
        for (int i = 0; i < 2; i++) {
            const int f = tid + i * 256;           // 0..511
            const int row = f >> 2, ch = f & 3;
            const long koff = kc * 32 + ch * 8;
            CP_ASYNC16(dA + row * ROWB + ch * 16, As + ((long)(m0 + row) << 10) + koff);
            CP_ASYNC16(dB + row * ROWB + ch * 16, Bs + ((long)(n0 + row) << 10) + koff);
        }
    };

    issue(0, 0); CP_COMMIT();
    issue(1, 1); CP_COMMIT();

    for (int c = 0; c < 96; c++) {
        const int p = c & 1;
        CP_WAIT1();
        __syncthreads();

        const u32 bA = smA0 + p * TILEB + aoff;
        const u32 bB = smB0 + p * TILEB + boff;
#pragma unroll
        for (int ks = 0; ks < 2; ks++) {
            u32 af[4][4];
#pragma unroll
            for (int mt = 0; mt < 4; mt++)
                ldsm_x4(af[mt][0], af[mt][1], af[mt][2], af[mt][3],
                        bA + mt * (16 * ROWB) + ks * 32);
            u32 bf[4][2];
#pragma unroll
            for (int nt2 = 0; nt2 < 2; nt2++) {
                u32 r0, r1, r2, r3;
                ldsm_x4(r0, r1, r2, r3, bB + nt2 * (16 * ROWB) + ks * 32);
                bf[nt2 * 2 + 0][0] = r0; bf[nt2 * 2 + 0][1] = r1;
                bf[nt2 * 2 + 1][0] = r2; bf[nt2 * 2 + 1][1] = r3;
            }
#pragma unroll
            for (int mt = 0; mt < 4; mt++)
#pragma unroll
                for (int nt = 0; nt < 4; nt++)
                    mma16816(acc[mt][nt], af[mt][0], af[mt][1], af[mt][2], af[mt][3],
                             bf[nt][0], bf[nt][1]);
        }
        __syncthreads();
        if (c + 2 < 96) issue(c + 2, p);
        CP_COMMIT();
    }

    // epilogue: bias + store (two float2 per mma tile per lane)
#pragma unroll
    for (int mt = 0; mt < 4; mt++) {
#pragma unroll
        for (int nt = 0; nt < 4; nt++) {
            const int m = m0 + warp_m * 64 + mt * 16 + (lane >> 2);
            const int n = n0 + warp_n * 32 + nt * 8 + (lane & 3) * 2;
            const float bx = bias[n], by = bias[n + 1];
#pragma unroll
            for (int half = 0; half < 2; half++) {
                const int mm = m + half * 8;
                float2 v;
                v.x = acc[mt][nt][half * 2 + 0] + bx;
                v.y = acc[mt][nt][half * 2 + 1] + by;
                if (MODE == 1) {
                    *(float2*)&out[(long)mm * D_MODEL + n] = v;
                } else {
                    const int b = mm >> 11, s = mm & 2047;
                    const int h = n >> 6, dk = n & 63;
                    *(float2*)&out[(((long)(b * NHEAD + h) * S_LEN + s) << 6) + dk] = v;
                }
            }
        }
    }
}

__global__ __launch_bounds__(256) void qk_gemm_tc(const float* __restrict__ bq,
                                                  const float* __restrict__ bk)
{
    if (blockIdx.z == 0) tc_gemm_body<0>(g_Ah, g_Al, g_WhT[0], g_WlT[0], bq, g_Q);
    else                 tc_gemm_body<0>(g_Ah, g_Al, g_WhT[1], g_WlT[1], bk, g_K);
}

__global__ __launch_bounds__(256) void out_gemm_tc(const float* __restrict__ b0,
                                                   float* __restrict__ out)
{
    tc_gemm_body<1>(g_Ah, g_Al, g_WhT[2], g_WlT[2], b0, out);
}

// ---------------------------------------------------------------------------
// Flash attention (causal), V = Q. Round-2 FFMA2 version (unchanged).
// ---------------------------------------------------------------------------
#define AT_SMEM_FLOATS (128*68 + 64*132 + 128*68 + 128*132 + 256)

__global__ __launch_bounds__(256, 1) void attn_kernel()
{
    extern __shared__ float smf[];
    float* sQ  = smf;
    float* sKT = sQ  + 128 * 68;
    float* sV  = sKT + 64 * 132;
    float* sP  = sV  + 128 * 68;
    float* sM  = sP  + 128 * 132;
    float* sL  = sM  + 128;

    const int tid = threadIdx.x;
    const int tx = tid & 15;
    const int ty = tid >> 4;
    const int r0 = ty * 8;
    const int c0 = tx * 8;
    const int half = tx >> 3;
    const int v0 = (tx & 7) * 8;
    const int qi = (int)gridDim.x - 1 - (int)blockIdx.x;
    const int bh = blockIdx.y;

    const float* Qb = g_Q + ((long)bh * S_LEN + qi * 128) * DKH;
    for (int f = tid; f < 2048; f += 256) {
        const int r = f >> 4, d0 = (f & 15) << 2;
        *(float4*)&sQ[r * 68 + d0] = *(const float4*)(Qb + r * 64 + d0);
    }
    if (tid < 128) { sM[tid] = -1e30f; sL[tid] = 0.0f; }

    u64 O2[8][4] = {};

    for (int j = 0; j <= qi; j++) {
        __syncthreads();

        const float* Kb = g_K + ((long)bh * S_LEN + j * 128) * DKH;
        const float* Vb = g_Q + ((long)bh * S_LEN + j * 128) * DKH;

        for (int f = tid; f < 2048; f += 256) {
            const int c = f & 127, d0 = (f >> 7) << 2;
            float4 v = *(const float4*)(Kb + c * 64 + d0);
            sKT[(d0 + 0) * 132 + c] = v.x;
            sKT[(d0 + 1) * 132 + c] = v.y;
            sKT[(d0 + 2) * 132 + c] = v.z;
            sKT[(d0 + 3) * 132 + c] = v.w;
        }
        for (int f = tid; f < 2048; f += 256) {
            const int r = f >> 4, d0 = (f & 15) << 2;
            *(float4*)&sV[r * 68 + d0] = *(const float4*)(Vb + r * 64 + d0);
        }
        __syncthreads();

        u64 s2[8][4] = {};
#pragma unroll 4
        for (int d = 0; d < 64; d++) {
            ulonglong2 kA = *(ulonglong2*)&sKT[d * 132 + c0];
            ulonglong2 kB = *(ulonglong2*)&sKT[d * 132 + c0 + 4];
            u64 kb[4] = {kA.x, kA.y, kB.x, kB.y};
#pragma unroll
            for (int i = 0; i < 8; i++) {
                u64 a2 = bcast2(sQ[(r0 + i) * 68 + d]);
#pragma unroll
                for (int jj = 0; jj < 4; jj++)
                    s2[i][jj] = ffma2(a2, kb[jj], s2[i][jj]);
            }
        }

#pragma unroll
        for (int i = 0; i < 8; i++) {
            float s[8];
#pragma unroll
            for (int jj = 0; jj < 4; jj++) {
                s[2 * jj]     = lo2(s2[i][jj]) * 0.125f;
                s[2 * jj + 1] = hi2(s2[i][jj]) * 0.125f;
            }
            if (j == qi) {
                const int r = r0 + i;
#pragma unroll
                for (int jj = 0; jj < 8; jj++)
                    if (c0 + jj > r) s[jj] = -1e30f;
            }
            float rm = s[0];
#pragma unroll
            for (int jj = 1; jj < 8; jj++) rm = fmaxf(rm, s[jj]);
            rm = fmaxf(rm, __shfl_xor_sync(0xffffffffu, rm, 1));
            rm = fmaxf(rm, __shfl_xor_sync(0xffffffffu, rm, 2));
            rm = fmaxf(rm, __shfl_xor_sync(0xffffffffu, rm, 4));
            rm = fmaxf(rm, __shfl_xor_sync(0xffffffffu, rm, 8));
            const float mo = sM[r0 + i];
            const float mn = fmaxf(mo, rm);
            const float alpha = __expf(mo - mn);
            float p[8], rs = 0.0f;
#pragma unroll
            for (int jj = 0; jj < 8; jj++) { p[jj] = __expf(s[jj] - mn); rs += p[jj]; }
            *(float4*)&sP[(r0 + i) * 132 + c0]     = make_float4(p[0], p[1], p[2], p[3]);
            *(float4*)&sP[(r0 + i) * 132 + c0 + 4] = make_float4(p[4], p[5], p[6], p[7]);
            rs += __shfl_xor_sync(0xffffffffu, rs, 1);
            rs += __shfl_xor_sync(0xffffffffu, rs, 2);
            rs += __shfl_xor_sync(0xffffffffu, rs, 4);
            rs += __shfl_xor_sync(0xffffffffu, rs, 8);
            __syncwarp();
            if (tx == 0) { sM[r0 + i] = mn; sL[r0 + i] = sL[r0 + i] * alpha + rs; }
            const u64 al2 = bcast2(alpha);
#pragma unroll
            for (int jj = 0; jj < 4; jj++) O2[i][jj] = mul2(al2, O2[i][jj]);
        }
        __syncwarp();

        const int cb = half * 64;
#pragma unroll 4
        for (int c = 0; c < 64; c++) {
            const int cc = cb + c;
            ulonglong2 vA = *(ulonglong2*)&sV[cc * 68 + v0];
            ulonglong2 vB = *(ulonglong2*)&sV[cc * 68 + v0 + 4];
            u64 vb[4] = {vA.x, vA.y, vB.x, vB.y};
#pragma unroll
            for (int i = 0; i < 8; i++) {
                u64 p2 = bcast2(sP[(r0 + i) * 132 + cc]);
#pragma unroll
                for (int jj = 0; jj < 4; jj++)
                    O2[i][jj] = ffma2(p2, vb[jj], O2[i][jj]);
            }
        }
    }

    __syncwarp();

    const int b = bh >> 4, h = bh & 15;
#pragma unroll
    for (int i = 0; i < 8; i++) {
        const float inv = 1.0f / sL[r0 + i];
        float o[8];
#pragma unroll
        for (int jj = 0; jj < 4; jj++) {
            u64 mine  = O2[i][jj];
            u64 other = __shfl_xor_sync(0xffffffffu, mine, 8);
            o[2 * jj]     = (lo2(mine) + lo2(other)) * inv;
            o[2 * jj + 1] = (hi2(mine) + hi2(other)) * inv;
        }
        if (half == 0) {
            const int srow = qi * 128 + r0 + i;
            float* dst = &g_att[((long)(b * S_LEN + srow)) * D_MODEL + h * DKH + v0];
            *(float4*)(dst)     = make_float4(o[0], o[1], o[2], o[3]);
            *(float4*)(dst + 4) = make_float4(o[4], o[5], o[6], o[7]);
        }
    }
}

// ---------------------------------------------------------------------------
extern "C" void kernel_launch(void* const* d_in, const int* in_sizes, int n_in,
                              void* d_out, int out_size)
{
    const float* x  = (const float*)d_in[0];
    const float* Wq = (const float*)d_in[1];
    const float* bq = (const float*)d_in[2];
    const float* Wk = (const float*)d_in[3];
    const float* bk = (const float*)d_in[4];
    const float* W0 = (const float*)d_in[5];
    const float* b0 = (const float*)d_in[6];
    float* out = (float*)d_out;

    __nv_bfloat16 *dAh, *dAl, *dWhT, *dWlT;
    float* dAtt;
    cudaGetSymbolAddress((void**)&dAh,  g_Ah);
    cudaGetSymbolAddress((void**)&dAl,  g_Al);
    cudaGetSymbolAddress((void**)&dWhT, g_WhT);
    cudaGetSymbolAddress((void**)&dWlT, g_WlT);
    cudaGetSymbolAddress((void**)&dAtt, g_att);

    const int attn_smem = AT_SMEM_FLOATS * (int)sizeof(float);
    cudaFuncSetAttribute(attn_kernel, cudaFuncAttributeMaxDynamicSharedMemorySize, attn_smem);

    // 1) decompose x and all weights
    decomp_A<<<M_TOK * D_MODEL / 1024, 256>>>(x, dAh, dAl);
    dim3 wt_grid(32, 32), wt_blk(32, 8);
    decomp_WT<<<wt_grid, wt_blk>>>(Wq, dWhT + 0 * D_MODEL * D_MODEL, dWlT + 0 * D_MODEL * D_MODEL);
    decomp_WT<<<wt_grid, wt_blk>>>(Wk, dWhT + 1 * D_MODEL * D_MODEL, dWlT + 1 * D_MODEL * D_MODEL);
    decomp_WT<<<wt_grid, wt_blk>>>(W0, dWhT + 2 * D_MODEL * D_MODEL, dWlT + 2 * D_MODEL * D_MODEL);

    // 2) Q & K projections on tensor cores (HMMA)
    dim3 qk_grid(D_MODEL / 128, M_TOK / 128, 2);   // (8, 32, 2)
    qk_gemm_tc<<<qk_grid, 256>>>(bq, bk);

    // 3) attention
    dim3 attn_grid(S_LEN / 128, BATCH * NHEAD);
    attn_kernel<<<attn_grid, 256, attn_smem>>>();

    // 4) decompose attention output, output projection on tensor cores
    decomp_A<<<M_TOK * D_MODEL / 1024, 256>>>(dAtt, dAh, dAl);
    dim3 o_grid(D_MODEL / 128, M_TOK / 128);
    out_gemm_tc<<<o_grid, 256>>>(b0, out);
}

// round 5
// speedup vs baseline: 2.6000x; 1.8195x over previous
#include <cuda_runtime.h>
#include <cuda_bf16.h>

#define S_LEN   2048
#define D_MODEL 1024
#define NHEAD   16
#define DKH     64
#define BATCH   2
#define M_TOK   (BATCH * S_LEN)   // 4096

typedef unsigned long long u64;
typedef unsigned int u32;

// ------------------------------- scratch -----------------------------------
__device__ __nv_bfloat16 g_Qh[BATCH * NHEAD * S_LEN * DKH];  // [B,H,S,DK] hi
__device__ __nv_bfloat16 g_Ql[BATCH * NHEAD * S_LEN * DKH];  // lo
__device__ __nv_bfloat16 g_Kh[BATCH * NHEAD * S_LEN * DKH];
__device__ __nv_bfloat16 g_Kl[BATCH * NHEAD * S_LEN * DKH];
__device__ __nv_bfloat16 g_Ah[M_TOK * D_MODEL];              // A hi (x, then att)
__device__ __nv_bfloat16 g_Al[M_TOK * D_MODEL];              // A lo
__device__ __nv_bfloat16 g_WhT[3][D_MODEL * D_MODEL];        // W^T hi: q,k,o
__device__ __nv_bfloat16 g_WlT[3][D_MODEL * D_MODEL];        // W^T lo

// --------------------------- small helpers ---------------------------------
__device__ __forceinline__ u32 smem_u32(const void* p) {
    u32 a; asm("{ .reg .u64 t; cvta.to.shared.u64 t, %1; cvt.u32.u64 %0, t; }" : "=r"(a) : "l"(p));
    return a;
}

#define CP_ASYNC16(dst, src) \
    asm volatile("cp.async.cg.shared.global [%0], [%1], 16;" :: "r"(dst), "l"(src))
#define CP_COMMIT()  asm volatile("cp.async.commit_group;" ::: "memory")
#define CP_WAIT1()   asm volatile("cp.async.wait_group 1;" ::: "memory")
#define CP_WAIT0()   asm volatile("cp.async.wait_group 0;" ::: "memory")

__device__ __forceinline__ void ldsm_x4(u32& r0, u32& r1, u32& r2, u32& r3, u32 addr) {
    asm volatile("ldmatrix.sync.aligned.m8n8.x4.shared.b16 {%0,%1,%2,%3}, [%4];"
                 : "=r"(r0), "=r"(r1), "=r"(r2), "=r"(r3) : "r"(addr));
}
__device__ __forceinline__ void ldsm_x4t(u32& r0, u32& r1, u32& r2, u32& r3, u32 addr) {
    asm volatile("ldmatrix.sync.aligned.m8n8.x4.trans.shared.b16 {%0,%1,%2,%3}, [%4];"
                 : "=r"(r0), "=r"(r1), "=r"(r2), "=r"(r3) : "r"(addr));
}

__device__ __forceinline__ void mma16816(float* d, u32 a0, u32 a1, u32 a2, u32 a3,
                                         u32 b0, u32 b1) {
    asm volatile("mma.sync.aligned.m16n8k16.row.col.f32.bf16.bf16.f32 "
                 "{%0,%1,%2,%3}, {%4,%5,%6,%7}, {%8,%9}, {%0,%1,%2,%3};"
                 : "+f"(d[0]), "+f"(d[1]), "+f"(d[2]), "+f"(d[3])
                 : "r"(a0), "r"(a1), "r"(a2), "r"(a3), "r"(b0), "r"(b1));
}

// pack two fp32 -> bf16x2 (x in low half, y in high half)
__device__ __forceinline__ u32 cvt2bf(float x, float y) {
    __nv_bfloat162 t = __floats2bfloat162_rn(x, y);
    return *reinterpret_cast<u32*>(&t);
}
// residual pack: (x,y) minus the bf16 values packed in h
__device__ __forceinline__ u32 resid2(u32 h, float x, float y) {
    float hx = __uint_as_float(h << 16);
    float hy = __uint_as_float(h & 0xffff0000u);
    return cvt2bf(x - hx, y - hy);
}

// ------------------------- fp32 -> bf16 hi/lo split -------------------------
__device__ __forceinline__ u32 pack_bf2(__nv_bfloat16 a, __nv_bfloat16 b) {
    __nv_bfloat162 p(a, b);
    return *reinterpret_cast<u32*>(&p);
}

__global__ __launch_bounds__(256) void decomp_A(const float* __restrict__ src,
                                                __nv_bfloat16* __restrict__ hi,
                                                __nv_bfloat16* __restrict__ lo)
{
    const int i = (blockIdx.x * 256 + threadIdx.x) * 4;
    float4 v = *(const float4*)(src + i);
    __nv_bfloat16 h0 = __float2bfloat16_rn(v.x);
    __nv_bfloat16 h1 = __float2bfloat16_rn(v.y);
    __nv_bfloat16 h2 = __float2bfloat16_rn(v.z);
    __nv_bfloat16 h3 = __float2bfloat16_rn(v.w);
    __nv_bfloat16 l0 = __float2bfloat16_rn(v.x - __bfloat162float(h0));
    __nv_bfloat16 l1 = __float2bfloat16_rn(v.y - __bfloat162float(h1));
    __nv_bfloat16 l2 = __float2bfloat16_rn(v.z - __bfloat162float(h2));
    __nv_bfloat16 l3 = __float2bfloat16_rn(v.w - __bfloat162float(h3));
    *(uint2*)(hi + i) = make_uint2(pack_bf2(h0, h1), pack_bf2(h2, h3));
    *(uint2*)(lo + i) = make_uint2(pack_bf2(l0, l1), pack_bf2(l2, l3));
}

// W [K,N] fp32 row-major -> WhT/WlT [N,K] bf16 row-major (transpose + split)
__global__ __launch_bounds__(256) void decomp_WT(const float* __restrict__ W,
                                                 __nv_bfloat16* __restrict__ hiT,
                                                 __nv_bfloat16* __restrict__ loT)
{
    __shared__ float t[32][33];
    const int tx = threadIdx.x, ty = threadIdx.y;     // (32, 8)
    const int n0 = blockIdx.x * 32, k0 = blockIdx.y * 32;
#pragma unroll
    for (int i = 0; i < 4; i++)
        t[ty + 8 * i][tx] = W[(k0 + ty + 8 * i) * D_MODEL + n0 + tx];
    __syncthreads();
#pragma unroll
    for (int i = 0; i < 4; i++) {
        float v = t[tx][ty + 8 * i];
        __nv_bfloat16 h = __float2bfloat16_rn(v);
        __nv_bfloat16 l = __float2bfloat16_rn(v - __bfloat162float(h));
        const long o = (long)(n0 + ty + 8 * i) * D_MODEL + k0 + tx;
        hiT[o] = h;
        loT[o] = l;
    }
}

// ---------------------------------------------------------------------------
// mma.sync split-bf16 GEMM: C[4096,1024] = A @ W + bias   (3 passes over K)
// BM=BN=128, BK=32, 256 threads (8 warps, 2x4), warp tile 64x32.
//   MODE 0: write bf16 hi/lo into head layout [B,H,S,DK]
//   MODE 1: write fp32 row-major [M,N]
// ---------------------------------------------------------------------------
#define ROWB 80          // bytes per smem row (64 data + 16 pad)
#define TILEG (128 * ROWB)

template <int MODE>
__device__ __forceinline__ void tc_gemm_body(const __nv_bfloat16* __restrict__ Ah,
                                             const __nv_bfloat16* __restrict__ Al,
                                             const __nv_bfloat16* __restrict__ BhT,
                                             const __nv_bfloat16* __restrict__ BlT,
                                             const float* __restrict__ bias,
                                             float* __restrict__ out,
                                             __nv_bfloat16* __restrict__ outh,
                                             __nv_bfloat16* __restrict__ outl)
{
    __shared__ __align__(16) char smA[2][TILEG];
    __shared__ __align__(16) char smB[2][TILEG];

    const int tid = threadIdx.x;
    const int wid = tid >> 5;
    const int lane = tid & 31;
    const int warp_m = wid >> 2;
    const int warp_n = wid & 3;
    const int m0 = blockIdx.y * 128;
    const int n0 = blockIdx.x * 128;

    const int a_row = (lane & 15);
    const int a_kh  = (lane >> 4);
    const u32 aoff = (u32)((warp_m * 64 + a_row) * ROWB + a_kh * 16);
    const int b_row = (lane & 7) + ((lane >> 4) << 3);
    const int b_kh  = (lane >> 3) & 1;
    const u32 boff = (u32)((warp_n * 32 + b_row) * ROWB + b_kh * 16);

    const u32 smA0 = smem_u32(smA[0]);
    const u32 smB0 = smem_u32(smB[0]);

    float acc[4][4][4] = {};

    auto issue = [&](int c, int p) {
        const int pass = c >> 5;
        const int kc = c & 31;
        const __nv_bfloat16* As = (pass == 2) ? Al : Ah;
        const __nv_bfloat16* Bs = (pass == 1) ? BlT : BhT;
        const u32 dA = smA0 + p * TILEG;
        const u32 dB = smB0 + p * TILEG;
#pragma unroll
        for (int i = 0; i < 2; i++) {
            const int f = tid + i * 256;
            const int row = f >> 2, ch = f & 3;
            const long koff = kc * 32 + ch * 8;
            CP_ASYNC16(dA + row * ROWB + ch * 16, As + ((long)(m0 + row) << 10) + koff);
            CP_ASYNC16(dB + row * ROWB + ch * 16, Bs + ((long)(n0 + row) << 10) + koff);
        }
    };

    issue(0, 0); CP_COMMIT();
    issue(1, 1); CP_COMMIT();

    for (int c = 0; c < 96; c++) {
        const int p = c & 1;
        CP_WAIT1();
        __syncthreads();

        const u32 bA = smA0 + p * TILEG + aoff;
        const u32 bB = smB0 + p * TILEG + boff;
#pragma unroll
        for (int ks = 0; ks < 2; ks++) {
            u32 af[4][4];
#pragma unroll
            for (int mt = 0; mt < 4; mt++)
                ldsm_x4(af[mt][0], af[mt][1], af[mt][2], af[mt][3],
                        bA + mt * (16 * ROWB) + ks * 32);
            u32 bf[4][2];
#pragma unroll
            for (int nt2 = 0; nt2 < 2; nt2++) {
                u32 r0, r1, r2, r3;
                ldsm_x4(r0, r1, r2, r3, bB + nt2 * (16 * ROWB) + ks * 32);
                bf[nt2 * 2 + 0][0] = r0; bf[nt2 * 2 + 0][1] = r1;
                bf[nt2 * 2 + 1][0] = r2; bf[nt2 * 2 + 1][1] = r3;
            }
#pragma unroll
            for (int mt = 0; mt < 4; mt++)
#pragma unroll
                for (int nt = 0; nt < 4; nt++)
                    mma16816(acc[mt][nt], af[mt][0], af[mt][1], af[mt][2], af[mt][3],
                             bf[nt][0], bf[nt][1]);
        }
        __syncthreads();
        if (c + 2 < 96) issue(c + 2, p);
        CP_COMMIT();
    }

    // epilogue
#pragma unroll
    for (int mt = 0; mt < 4; mt++) {
#pragma unroll
        for (int nt = 0; nt < 4; nt++) {
            const int m = m0 + warp_m * 64 + mt * 16 + (lane >> 2);
            const int n = n0 + warp_n * 32 + nt * 8 + (lane & 3) * 2;
            const float bx = bias[n], by = bias[n + 1];
#pragma unroll
            for (int half = 0; half < 2; half++) {
                const int mm = m + half * 8;
                const float vx = acc[mt][nt][half * 2 + 0] + bx;
                const float vy = acc[mt][nt][half * 2 + 1] + by;
                if (MODE == 1) {
                    *(float2*)&out[(long)mm * D_MODEL + n] = make_float2(vx, vy);
                } else {
                    const int b = mm >> 11, s = mm & 2047;
                    const int hd = n >> 6, dk = n & 63;
                    const long o = (((long)(b * NHEAD + hd) * S_LEN + s) << 6) + dk;
                    const u32 hh = cvt2bf(vx, vy);
                    const u32 ll = resid2(hh, vx, vy);
                    *(u32*)&outh[o] = hh;
                    *(u32*)&outl[o] = ll;
                }
            }
        }
    }
}

__global__ __launch_bounds__(256) void qk_gemm_tc(const float* __restrict__ bq,
                                                  const float* __restrict__ bk)
{
    if (blockIdx.z == 0)
        tc_gemm_body<0>(g_Ah, g_Al, g_WhT[0], g_WlT[0], bq, nullptr, g_Qh, g_Ql);
    else
        tc_gemm_body<0>(g_Ah, g_Al, g_WhT[1], g_WlT[1], bk, nullptr, g_Kh, g_Kl);
}

__global__ __launch_bounds__(256) void out_gemm_tc(const float* __restrict__ b0,
                                                   float* __restrict__ out)
{
    tc_gemm_body<1>(g_Ah, g_Al, g_WhT[2], g_WlT[2], b0, out, nullptr, nullptr);
}

// ---------------------------------------------------------------------------
// Flash attention on mma.sync, causal, V = Q (reference quirk).
// 256 threads (8 warps x 16 q-rows), BQ=BKV=128, DK=64, split-bf16 3-pass.
// smem: Qh,Ql + 2 x (Kh,Kl,Vh,Vl), 144-byte row pitch, cp.async double buffer.
// Output: bf16 hi/lo straight into g_Ah/g_Al [B,S,D].
// ---------------------------------------------------------------------------
#define PITCH   144
#define TILE_B  (128 * PITCH)          // 18432
#define OFF_KV0 (2 * TILE_B)
#define KV_SZ   (4 * TILE_B)
#define AT_SMEM (OFF_KV0 + 2 * KV_SZ)  // 184320

__global__ __launch_bounds__(256, 1) void attn_tc()
{
    extern __shared__ char smc[];
    const u32 sb = smem_u32(smc);
    const int tid  = threadIdx.x;
    const int lane = tid & 31;
    const int w    = tid >> 5;
    const int qi = (int)gridDim.x - 1 - (int)blockIdx.x;   // long tiles first
    const int bh = blockIdx.y;

    const int lrow = lane & 15;
    const int lch  = lane >> 4;
    const int rlo  = w * 16 + (lane >> 2);      // local q row (low)
    const int rhi  = rlo + 8;

    // ---- issue Q tile + KV tile 0 ----
    {
        const long qb = ((long)bh * S_LEN + (long)qi * 128) * DKH;
#pragma unroll
        for (int i = 0; i < 8; i++) {
            const int t = i >> 2;
            const int idx = (i & 3) * 256 + tid;
            const int r = idx >> 3, c = idx & 7;
            const __nv_bfloat16* src = (t == 0 ? g_Qh : g_Ql) + qb + r * 64 + c * 8;
            CP_ASYNC16(sb + t * TILE_B + r * PITCH + c * 16, src);
        }
        const long kb = ((long)bh * S_LEN) * DKH;   // j = 0
#pragma unroll
        for (int i = 0; i < 16; i++) {
            const int t = i >> 2;
            const int idx = (i & 3) * 256 + tid;
            const int r = idx >> 3, c = idx & 7;
            const __nv_bfloat16* src =
                (t == 0 ? g_Kh : t == 1 ? g_Kl : t == 2 ? g_Qh : g_Ql) + kb + r * 64 + c * 8;
            CP_ASYNC16(sb + OFF_KV0 + t * TILE_B + r * PITCH + c * 16, src);
        }
        CP_COMMIT();
    }

    u32 aQh[4][4], aQl[4][4];
    float o_[8][4] = {};
    float mst0 = -1e30f, mst1 = -1e30f;
    float lst0 = 0.0f, lst1 = 0.0f;

    for (int j = 0; j <= qi; j++) {
        CP_WAIT0();
        __syncthreads();
        const u32 buf = sb + OFF_KV0 + (u32)(j & 1) * KV_SZ;

        if (j == 0) {
            // load Q fragments once (Q smem persists)
#pragma unroll
            for (int s = 0; s < 4; s++) {
                const u32 a = (u32)((w * 16 + lrow) * PITCH + s * 32 + lch * 16);
                ldsm_x4(aQh[s][0], aQh[s][1], aQh[s][2], aQh[s][3], sb + a);
                ldsm_x4(aQl[s][0], aQl[s][1], aQl[s][2], aQl[s][3], sb + TILE_B + a);
            }
        }
        if (j < qi) {
            const long kb = ((long)bh * S_LEN + (long)(j + 1) * 128) * DKH;
            const u32 nbuf = sb + OFF_KV0 + (u32)((j + 1) & 1) * KV_SZ;
#pragma unroll
            for (int i = 0; i < 16; i++) {
                const int t = i >> 2;
                const int idx = (i & 3) * 256 + tid;
                const int r = idx >> 3, c = idx & 7;
                const __nv_bfloat16* src =
                    (t == 0 ? g_Kh : t == 1 ? g_Kl : t == 2 ? g_Qh : g_Ql) + kb + r * 64 + c * 8;
                CP_ASYNC16(nbuf + t * TILE_B + r * PITCH + c * 16, src);
            }
            CP_COMMIT();
        }

        // ---- S = Q K^T (3 passes fused per n-chunk) ----
        float s_[16][4] = {};
#pragma unroll
        for (int nc = 0; nc < 8; nc++) {
            u32 bh_[4][4], bl_[4][4];
#pragma unroll
            for (int s = 0; s < 4; s++) {
                const u32 a = buf + (u32)((nc * 16 + lrow) * PITCH + s * 32 + lch * 16);
                ldsm_x4(bh_[s][0], bh_[s][1], bh_[s][2], bh_[s][3], a);
                ldsm_x4(bl_[s][0], bl_[s][1], bl_[s][2], bl_[s][3], a + TILE_B);
            }
#pragma unroll
            for (int s = 0; s < 4; s++) {
                mma16816(s_[2 * nc],     aQh[s][0], aQh[s][1], aQh[s][2], aQh[s][3], bh_[s][0], bh_[s][2]);
                mma16816(s_[2 * nc + 1], aQh[s][0], aQh[s][1], aQh[s][2], aQh[s][3], bh_[s][1], bh_[s][3]);
                mma16816(s_[2 * nc],     aQh[s][0], aQh[s][1], aQh[s][2], aQh[s][3], bl_[s][0], bl_[s][2]);
                mma16816(s_[2 * nc + 1], aQh[s][0], aQh[s][1], aQh[s][2], aQh[s][3], bl_[s][1], bl_[s][3]);
                mma16816(s_[2 * nc],     aQl[s][0], aQl[s][1], aQl[s][2], aQl[s][3], bh_[s][0], bh_[s][2]);
                mma16816(s_[2 * nc + 1], aQl[s][0], aQl[s][1], aQl[s][2], aQl[s][3], bh_[s][1], bh_[s][3]);
            }
        }

        // ---- online softmax (rows are warp-private; 4-lane shfl reduce) ----
        float rmx0 = -1e30f, rmx1 = -1e30f;
#pragma unroll
        for (int nt = 0; nt < 16; nt++) {
#pragma unroll
            for (int q = 0; q < 4; q++) s_[nt][q] *= 0.125f;    // 1/sqrt(64)
            if (j == qi) {
                const int c0 = nt * 8 + (lane & 3) * 2;
                if (c0 > rlo)     s_[nt][0] = -1e30f;
                if (c0 + 1 > rlo) s_[nt][1] = -1e30f;
                if (c0 > rhi)     s_[nt][2] = -1e30f;
                if (c0 + 1 > rhi) s_[nt][3] = -1e30f;
            }
            rmx0 = fmaxf(rmx0, fmaxf(s_[nt][0], s_[nt][1]));
            rmx1 = fmaxf(rmx1, fmaxf(s_[nt][2], s_[nt][3]));
        }
        rmx0 = fmaxf(rmx0, __shfl_xor_sync(0xffffffffu, rmx0, 1));
        rmx0 = fmaxf(rmx0, __shfl_xor_sync(0xffffffffu, rmx0, 2));
        rmx1 = fmaxf(rmx1, __shfl_xor_sync(0xffffffffu, rmx1, 1));
        rmx1 = fmaxf(rmx1, __shfl_xor_sync(0xffffffffu, rmx1, 2));
        const float mn0 = fmaxf(mst0, rmx0);
        const float mn1 = fmaxf(mst1, rmx1);
        const float al0 = __expf(mst0 - mn0);
        const float al1 = __expf(mst1 - mn1);
        float sum0 = 0.0f, sum1 = 0.0f;
#pragma unroll
        for (int nt = 0; nt < 16; nt++) {
            s_[nt][0] = __expf(s_[nt][0] - mn0);
            s_[nt][1] = __expf(s_[nt][1] - mn0);
            s_[nt][2] = __expf(s_[nt][2] - mn1);
            s_[nt][3] = __expf(s_[nt][3] - mn1);
            sum0 += s_[nt][0] + s_[nt][1];
            sum1 += s_[nt][2] + s_[nt][3];
        }
        sum0 += __shfl_xor_sync(0xffffffffu, sum0, 1);
        sum0 += __shfl_xor_sync(0xffffffffu, sum0, 2);
        sum1 += __shfl_xor_sync(0xffffffffu, sum1, 1);
        sum1 += __shfl_xor_sync(0xffffffffu, sum1, 2);
        lst0 = lst0 * al0 + sum0;
        lst1 = lst1 * al1 + sum1;
        mst0 = mn0;
        mst1 = mn1;
#pragma unroll
        for (int nt = 0; nt < 8; nt++) {
            o_[nt][0] *= al0; o_[nt][1] *= al0;
            o_[nt][2] *= al1; o_[nt][3] *= al1;
        }

        // ---- O += P V (3 passes, on-the-fly P hi/lo packing) ----
        const u32 vh_b = buf + 2 * TILE_B;
#pragma unroll
        for (int s = 0; s < 8; s++) {
            u32 ah[4], al_[4];
            ah[0] = cvt2bf(s_[2 * s][0], s_[2 * s][1]);
            ah[1] = cvt2bf(s_[2 * s][2], s_[2 * s][3]);
            ah[2] = cvt2bf(s_[2 * s + 1][0], s_[2 * s + 1][1]);
            ah[3] = cvt2bf(s_[2 * s + 1][2], s_[2 * s + 1][3]);
            al_[0] = resid2(ah[0], s_[2 * s][0], s_[2 * s][1]);
            al_[1] = resid2(ah[1], s_[2 * s][2], s_[2 * s][3]);
            al_[2] = resid2(ah[2], s_[2 * s + 1][0], s_[2 * s + 1][1]);
            al_[3] = resid2(ah[3], s_[2 * s + 1][2], s_[2 * s + 1][3]);

            u32 vh_[8][2], vl_[8][2];
#pragma unroll
            for (int tp = 0; tp < 4; tp++) {
                const u32 a = vh_b + (u32)((s * 16 + lrow) * PITCH + (tp * 2 + lch) * 16);
                u32 r0, r1, r2, r3;
                ldsm_x4t(r0, r1, r2, r3, a);
                vh_[2 * tp][0] = r0; vh_[2 * tp][1] = r1;
                vh_[2 * tp + 1][0] = r2; vh_[2 * tp + 1][1] = r3;
                ldsm_x4t(r0, r1, r2, r3, a + TILE_B);
                vl_[2 * tp][0] = r0; vl_[2 * tp][1] = r1;
                vl_[2 * tp + 1][0] = r2; vl_[2 * tp + 1][1] = r3;
            }
#pragma unroll
            for (int nt = 0; nt < 8; nt++) {
                mma16816(o_[nt], ah[0], ah[1], ah[2], ah[3], vh_[nt][0], vh_[nt][1]);
                mma16816(o_[nt], ah[0], ah[1], ah[2], ah[3], vl_[nt][0], vl_[nt][1]);
                mma16816(o_[nt], al_[0], al_[1], al_[2], al_[3], vh_[nt][0], vh_[nt][1]);
            }
        }
    }

    // ---- epilogue: normalize, split hi/lo, write g_Ah/g_Al [B,S,D] ----
    const int bat = bh >> 4, head = bh & 15;
    const float i0 = 1.0f / lst0;
    const float i1 = 1.0f / lst1;
    const int row0 = qi * 128 + rlo;
#pragma unroll
    for (int nt = 0; nt < 8; nt++) {
        const int d = head * 64 + nt * 8 + (lane & 3) * 2;
        {
            const float x = o_[nt][0] * i0, y = o_[nt][1] * i0;
            const u32 hh = cvt2bf(x, y), ll = resid2(hh, x, y);
            const long a = ((long)(bat * S_LEN + row0) << 10) + d;
            *(u32*)&g_Ah[a] = hh;
            *(u32*)&g_Al[a] = ll;
        }
        {
            const float x = o_[nt][2] * i1, y = o_[nt][3] * i1;
            const u32 hh = cvt2bf(x, y), ll = resid2(hh, x, y);
            const long a = ((long)(bat * S_LEN + row0 + 8) << 10) + d;
            *(u32*)&g_Ah[a] = hh;
            *(u32*)&g_Al[a] = ll;
        }
    }
}

// ---------------------------------------------------------------------------
extern "C" void kernel_launch(void* const* d_in, const int* in_sizes, int n_in,
                              void* d_out, int out_size)
{
    const float* x  = (const float*)d_in[0];
    const float* Wq = (const float*)d_in[1];
    const float* bq = (const float*)d_in[2];
    const float* Wk = (const float*)d_in[3];
    const float* bk = (const float*)d_in[4];
    const float* W0 = (const float*)d_in[5];
    const float* b0 = (const float*)d_in[6];
    float* out = (float*)d_out;

    __nv_bfloat16 *dAh, *dAl, *dWhT, *dWlT;
    cudaGetSymbolAddress((void**)&dAh,  g_Ah);
    cudaGetSymbolAddress((void**)&dAl,  g_Al);
    cudaGetSymbolAddress((void**)&dWhT, g_WhT);
    cudaGetSymbolAddress((void**)&dWlT, g_WlT);

    cudaFuncSetAttribute(attn_tc, cudaFuncAttributeMaxDynamicSharedMemorySize, AT_SMEM);

    // 1) decompose x and all weights
    decomp_A<<<M_TOK * D_MODEL / 1024, 256>>>(x, dAh, dAl);
    dim3 wt_grid(32, 32), wt_blk(32, 8);
    decomp_WT<<<wt_grid, wt_blk>>>(Wq, dWhT + 0 * D_MODEL * D_MODEL, dWlT + 0 * D_MODEL * D_MODEL);
    decomp_WT<<<wt_grid, wt_blk>>>(Wk, dWhT + 1 * D_MODEL * D_MODEL, dWlT + 1 * D_MODEL * D_MODEL);
    decomp_WT<<<wt_grid, wt_blk>>>(W0, dWhT + 2 * D_MODEL * D_MODEL, dWlT + 2 * D_MODEL * D_MODEL);

    // 2) Q & K projections -> bf16 hi/lo head layout
    dim3 qk_grid(D_MODEL / 128, M_TOK / 128, 2);   // (8, 32, 2)
    qk_gemm_tc<<<qk_grid, 256>>>(bq, bk);

    // 3) attention (tensor cores) -> g_Ah/g_Al
    dim3 attn_grid(S_LEN / 128, BATCH * NHEAD);     // (16, 32)
    attn_tc<<<attn_grid, 256, AT_SMEM>>>();

    // 4) output projection
    dim3 o_grid(D_MODEL / 128, M_TOK / 128);
    out_gemm_tc<<<o_grid, 256>>>(b0, out);
}

// round 6
// speedup vs baseline: 2.8326x; 1.0895x over previous
#include <cuda_runtime.h>
#include <cuda_bf16.h>

#define S_LEN   2048
#define D_MODEL 1024
#define NHEAD   16
#define DKH     64
#define BATCH   2
#define M_TOK   (BATCH * S_LEN)   // 4096

typedef unsigned long long u64;
typedef unsigned int u32;

// ------------------------------- scratch -----------------------------------
__device__ __nv_bfloat16 g_Qh[BATCH * NHEAD * S_LEN * DKH];  // [B,H,S,DK] hi
__device__ __nv_bfloat16 g_Ql[BATCH * NHEAD * S_LEN * DKH];  // lo
__device__ __nv_bfloat16 g_Kh[BATCH * NHEAD * S_LEN * DKH];
__device__ __nv_bfloat16 g_Kl[BATCH * NHEAD * S_LEN * DKH];
__device__ __nv_bfloat16 g_Ah[M_TOK * D_MODEL];              // A hi (x, then att)
__device__ __nv_bfloat16 g_Al[M_TOK * D_MODEL];              // A lo
__device__ __nv_bfloat16 g_WhT[3][D_MODEL * D_MODEL];        // W^T hi: q,k,o
__device__ __nv_bfloat16 g_WlT[3][D_MODEL * D_MODEL];        // W^T lo

// --------------------------- small helpers ---------------------------------
__device__ __forceinline__ u32 smem_u32(const void* p) {
    u32 a; asm("{ .reg .u64 t; cvta.to.shared.u64 t, %1; cvt.u32.u64 %0, t; }" : "=r"(a) : "l"(p));
    return a;
}

#define CP_ASYNC16(dst, src) \
    asm volatile("cp.async.cg.shared.global [%0], [%1], 16;" :: "r"(dst), "l"(src))
#define CP_COMMIT()  asm volatile("cp.async.commit_group;" ::: "memory")
#define CP_WAIT1()   asm volatile("cp.async.wait_group 1;" ::: "memory")
#define CP_WAIT0()   asm volatile("cp.async.wait_group 0;" ::: "memory")

__device__ __forceinline__ void ldsm_x4(u32& r0, u32& r1, u32& r2, u32& r3, u32 addr) {
    asm volatile("ldmatrix.sync.aligned.m8n8.x4.shared.b16 {%0,%1,%2,%3}, [%4];"
                 : "=r"(r0), "=r"(r1), "=r"(r2), "=r"(r3) : "r"(addr));
}
__device__ __forceinline__ void ldsm_x4t(u32& r0, u32& r1, u32& r2, u32& r3, u32 addr) {
    asm volatile("ldmatrix.sync.aligned.m8n8.x4.trans.shared.b16 {%0,%1,%2,%3}, [%4];"
                 : "=r"(r0), "=r"(r1), "=r"(r2), "=r"(r3) : "r"(addr));
}

__device__ __forceinline__ void mma16816(float* d, u32 a0, u32 a1, u32 a2, u32 a3,
                                         u32 b0, u32 b1) {
    asm volatile("mma.sync.aligned.m16n8k16.row.col.f32.bf16.bf16.f32 "
                 "{%0,%1,%2,%3}, {%4,%5,%6,%7}, {%8,%9}, {%0,%1,%2,%3};"
                 : "+f"(d[0]), "+f"(d[1]), "+f"(d[2]), "+f"(d[3])
                 : "r"(a0), "r"(a1), "r"(a2), "r"(a3), "r"(b0), "r"(b1));
}

__device__ __forceinline__ u32 cvt2bf(float x, float y) {
    __nv_bfloat162 t = __floats2bfloat162_rn(x, y);
    return *reinterpret_cast<u32*>(&t);
}
__device__ __forceinline__ u32 resid2(u32 h, float x, float y) {
    float hx = __uint_as_float(h << 16);
    float hy = __uint_as_float(h & 0xffff0000u);
    return cvt2bf(x - hx, y - hy);
}
__device__ __forceinline__ u32 pack_bf2(__nv_bfloat16 a, __nv_bfloat16 b) {
    __nv_bfloat162 p(a, b);
    return *reinterpret_cast<u32*>(&p);
}

// ------------------------- fp32 -> bf16 hi/lo split -------------------------
__global__ __launch_bounds__(256) void decomp_A(const float* __restrict__ src,
                                                __nv_bfloat16* __restrict__ hi,
                                                __nv_bfloat16* __restrict__ lo)
{
    const int i = (blockIdx.x * 256 + threadIdx.x) * 4;
    float4 v = *(const float4*)(src + i);
    __nv_bfloat16 h0 = __float2bfloat16_rn(v.x);
    __nv_bfloat16 h1 = __float2bfloat16_rn(v.y);
    __nv_bfloat16 h2 = __float2bfloat16_rn(v.z);
    __nv_bfloat16 h3 = __float2bfloat16_rn(v.w);
    __nv_bfloat16 l0 = __float2bfloat16_rn(v.x - __bfloat162float(h0));
    __nv_bfloat16 l1 = __float2bfloat16_rn(v.y - __bfloat162float(h1));
    __nv_bfloat16 l2 = __float2bfloat16_rn(v.z - __bfloat162float(h2));
    __nv_bfloat16 l3 = __float2bfloat16_rn(v.w - __bfloat162float(h3));
    *(uint2*)(hi + i) = make_uint2(pack_bf2(h0, h1), pack_bf2(h2, h3));
    *(uint2*)(lo + i) = make_uint2(pack_bf2(l0, l1), pack_bf2(l2, l3));
}

// all three W [K,N] fp32 -> W^T hi/lo bf16, one launch (z = which matrix)
__global__ __launch_bounds__(256) void decomp_WT3(const float* __restrict__ Wq,
                                                  const float* __restrict__ Wk,
                                                  const float* __restrict__ W0)
{
    const int z = blockIdx.z;
    const float* W = (z == 0) ? Wq : (z == 1) ? Wk : W0;
    __nv_bfloat16* hiT = g_WhT[z];
    __nv_bfloat16* loT = g_WlT[z];

    __shared__ float t[32][33];
    const int tx = threadIdx.x & 31, ty = threadIdx.x >> 5;   // (32, 8)
    const int n0 = blockIdx.x * 32, k0 = blockIdx.y * 32;
#pragma unroll
    for (int i = 0; i < 4; i++)
        t[ty + 8 * i][tx] = W[(k0 + ty + 8 * i) * D_MODEL + n0 + tx];
    __syncthreads();
#pragma unroll
    for (int i = 0; i < 4; i++) {
        float v = t[tx][ty + 8 * i];
        __nv_bfloat16 h = __float2bfloat16_rn(v);
        __nv_bfloat16 l = __float2bfloat16_rn(v - __bfloat162float(h));
        const long o = (long)(n0 + ty + 8 * i) * D_MODEL + k0 + tx;
        hiT[o] = h;
        loT[o] = l;
    }
}

// ---------------------------------------------------------------------------
// Fused 3-pass split-bf16 GEMM: C[4096,1024] = A @ W + bias
// Per K-chunk (BK=32) load Ah,Al,Bh,Bl once, issue AhBh + AhBl + AlBh.
// BM=BN=128, 256 threads (8 warps 2x4), warp tile 64x32. 2-stage cp.async.
//   MODE 0: write bf16 hi/lo into head layout [B,H,S,DK]
//   MODE 1: write fp32 row-major [M,N]
// ---------------------------------------------------------------------------
#define ROWB 80                        // 64 data bytes + 16 pad
#define TILEG (128 * ROWB)             // 10240
#define STAGE (4 * TILEG)              // Ah,Al,Bh,Bl = 40960
#define GSMEM (2 * STAGE)              // 81920

template <int MODE>
__device__ __forceinline__ void tc_gemm_body(const __nv_bfloat16* __restrict__ Ah,
                                             const __nv_bfloat16* __restrict__ Al,
                                             const __nv_bfloat16* __restrict__ BhT,
                                             const __nv_bfloat16* __restrict__ BlT,
                                             const float* __restrict__ bias,
                                             float* __restrict__ out,
                                             __nv_bfloat16* __restrict__ outh,
                                             __nv_bfloat16* __restrict__ outl)
{
    extern __shared__ __align__(16) char smg[];
    const u32 sb = smem_u32(smg);

    const int tid = threadIdx.x;
    const int wid = tid >> 5;
    const int lane = tid & 31;
    const int warp_m = wid >> 2;
    const int warp_n = wid & 3;
    const int m0 = blockIdx.y * 128;
    const int n0 = blockIdx.x * 128;

    const int a_row = (lane & 15);
    const int a_kh  = (lane >> 4);
    const u32 aoff = (u32)((warp_m * 64 + a_row) * ROWB + a_kh * 16);
    const int b_row = (lane & 7) + ((lane >> 4) << 3);
    const int b_kh  = (lane >> 3) & 1;
    const u32 boff = (u32)((warp_n * 32 + b_row) * ROWB + b_kh * 16);

    float acc[4][4][4] = {};

    const __nv_bfloat16* srcs[4] = {
        Ah + ((long)m0 << 10), Al + ((long)m0 << 10),
        BhT + ((long)n0 << 10), BlT + ((long)n0 << 10)
    };

    auto issue = [&](int kc, int p) {
        const u32 dst = sb + (u32)p * STAGE;
#pragma unroll
        for (int t = 0; t < 4; t++) {
            const __nv_bfloat16* s = srcs[t];
#pragma unroll
            for (int i = 0; i < 2; i++) {
                const int f = i * 256 + tid;      // 0..511
                const int row = f >> 2, ch = f & 3;
                CP_ASYNC16(dst + t * TILEG + row * ROWB + ch * 16,
                           s + ((long)row << 10) + kc * 32 + ch * 8);
            }
        }
    };

    issue(0, 0); CP_COMMIT();
    issue(1, 1); CP_COMMIT();

    for (int c = 0; c < 32; c++) {
        const int p = c & 1;
        CP_WAIT1();
        __syncthreads();

        const u32 base = sb + (u32)p * STAGE;
#pragma unroll
        for (int ks = 0; ks < 2; ks++) {
            // A fragments (hi + lo)
            u32 ah[4][4], al[4][4];
#pragma unroll
            for (int mt = 0; mt < 4; mt++) {
                const u32 a = base + aoff + mt * (16 * ROWB) + ks * 32;
                ldsm_x4(ah[mt][0], ah[mt][1], ah[mt][2], ah[mt][3], a);
                ldsm_x4(al[mt][0], al[mt][1], al[mt][2], al[mt][3], a + TILEG);
            }
            // B hi fragments
            u32 bh[4][2];
#pragma unroll
            for (int nt2 = 0; nt2 < 2; nt2++) {
                u32 r0, r1, r2, r3;
                ldsm_x4(r0, r1, r2, r3, base + 2 * TILEG + boff + nt2 * (16 * ROWB) + ks * 32);
                bh[nt2 * 2 + 0][0] = r0; bh[nt2 * 2 + 0][1] = r1;
                bh[nt2 * 2 + 1][0] = r2; bh[nt2 * 2 + 1][1] = r3;
            }
            // Ah*Bh + Al*Bh
#pragma unroll
            for (int mt = 0; mt < 4; mt++)
#pragma unroll
                for (int nt = 0; nt < 4; nt++) {
                    mma16816(acc[mt][nt], ah[mt][0], ah[mt][1], ah[mt][2], ah[mt][3],
                             bh[nt][0], bh[nt][1]);
                    mma16816(acc[mt][nt], al[mt][0], al[mt][1], al[mt][2], al[mt][3],
                             bh[nt][0], bh[nt][1]);
                }
            // B lo fragments (reuse regs)
#pragma unroll
            for (int nt2 = 0; nt2 < 2; nt2++) {
                u32 r0, r1, r2, r3;
                ldsm_x4(r0, r1, r2, r3, base + 3 * TILEG + boff + nt2 * (16 * ROWB) + ks * 32);
                bh[nt2 * 2 + 0][0] = r0; bh[nt2 * 2 + 0][1] = r1;
                bh[nt2 * 2 + 1][0] = r2; bh[nt2 * 2 + 1][1] = r3;
            }
            // Ah*Bl
#pragma unroll
            for (int mt = 0; mt < 4; mt++)
#pragma unroll
                for (int nt = 0; nt < 4; nt++)
                    mma16816(acc[mt][nt], ah[mt][0], ah[mt][1], ah[mt][2], ah[mt][3],
                             bh[nt][0], bh[nt][1]);
        }
        __syncthreads();
        if (c + 2 < 32) issue(c + 2, p);
        CP_COMMIT();
    }

    // epilogue
#pragma unroll
    for (int mt = 0; mt < 4; mt++) {
#pragma unroll
        for (int nt = 0; nt < 4; nt++) {
            const int m = m0 + warp_m * 64 + mt * 16 + (lane >> 2);
            const int n = n0 + warp_n * 32 + nt * 8 + (lane & 3) * 2;
            const float bx = bias[n], by = bias[n + 1];
#pragma unroll
            for (int half = 0; half < 2; half++) {
                const int mm = m + half * 8;
                const float vx = acc[mt][nt][half * 2 + 0] + bx;
                const float vy = acc[mt][nt][half * 2 + 1] + by;
                if (MODE == 1) {
                    *(float2*)&out[(long)mm * D_MODEL + n] = make_float2(vx, vy);
                } else {
                    const int b = mm >> 11, s = mm & 2047;
                    const int hd = n >> 6, dk = n & 63;
                    const long o = (((long)(b * NHEAD + hd) * S_LEN + s) << 6) + dk;
                    const u32 hh = cvt2bf(vx, vy);
                    const u32 ll = resid2(hh, vx, vy);
                    *(u32*)&outh[o] = hh;
                    *(u32*)&outl[o] = ll;
                }
            }
        }
    }
}

__global__ __launch_bounds__(256) void qk_gemm_tc(const float* __restrict__ bq,
                                                  const float* __restrict__ bk)
{
    if (blockIdx.z == 0)
        tc_gemm_body<0>(g_Ah, g_Al, g_WhT[0], g_WlT[0], bq, nullptr, g_Qh, g_Ql);
    else
        tc_gemm_body<0>(g_Ah, g_Al, g_WhT[1], g_WlT[1], bk, nullptr, g_Kh, g_Kl);
}

__global__ __launch_bounds__(256) void out_gemm_tc(const float* __restrict__ b0,
                                                   float* __restrict__ out)
{
    tc_gemm_body<1>(g_Ah, g_Al, g_WhT[2], g_WlT[2], b0, out, nullptr, nullptr);
}

// ---------------------------------------------------------------------------
// Flash attention on mma.sync, causal, V = Q. (unchanged from round 5)
// ---------------------------------------------------------------------------
#define PITCH   144
#define TILE_B  (128 * PITCH)
#define OFF_KV0 (2 * TILE_B)
#define KV_SZ   (4 * TILE_B)
#define AT_SMEM (OFF_KV0 + 2 * KV_SZ)

__global__ __launch_bounds__(256, 1) void attn_tc()
{
    extern __shared__ char smc[];
    const u32 sb = smem_u32(smc);
    const int tid  = threadIdx.x;
    const int lane = tid & 31;
    const int w    = tid >> 5;
    const int qi = (int)gridDim.x - 1 - (int)blockIdx.x;
    const int bh = blockIdx.y;

    const int lrow = lane & 15;
    const int lch  = lane >> 4;
    const int rlo  = w * 16 + (lane >> 2);
    const int rhi  = rlo + 8;

    {
        const long qb = ((long)bh * S_LEN + (long)qi * 128) * DKH;
#pragma unroll
        for (int i = 0; i < 8; i++) {
            const int t = i >> 2;
            const int idx = (i & 3) * 256 + tid;
            const int r = idx >> 3, c = idx & 7;
            const __nv_bfloat16* src = (t == 0 ? g_Qh : g_Ql) + qb + r * 64 + c * 8;
            CP_ASYNC16(sb + t * TILE_B + r * PITCH + c * 16, src);
        }
        const long kb = ((long)bh * S_LEN) * DKH;
#pragma unroll
        for (int i = 0; i < 16; i++) {
            const int t = i >> 2;
            const int idx = (i & 3) * 256 + tid;
            const int r = idx >> 3, c = idx & 7;
            const __nv_bfloat16* src =
                (t == 0 ? g_Kh : t == 1 ? g_Kl : t == 2 ? g_Qh : g_Ql) + kb + r * 64 + c * 8;
            CP_ASYNC16(sb + OFF_KV0 + t * TILE_B + r * PITCH + c * 16, src);
        }
        CP_COMMIT();
    }

    u32 aQh[4][4], aQl[4][4];
    float o_[8][4] = {};
    float mst0 = -1e30f, mst1 = -1e30f;
    float lst0 = 0.0f, lst1 = 0.0f;

    for (int j = 0; j <= qi; j++) {
        CP_WAIT0();
        __syncthreads();
        const u32 buf = sb + OFF_KV0 + (u32)(j & 1) * KV_SZ;

        if (j == 0) {
#pragma unroll
            for (int s = 0; s < 4; s++) {
                const u32 a = (u32)((w * 16 + lrow) * PITCH + s * 32 + lch * 16);
                ldsm_x4(aQh[s][0], aQh[s][1], aQh[s][2], aQh[s][3], sb + a);
                ldsm_x4(aQl[s][0], aQl[s][1], aQl[s][2], aQl[s][3], sb + TILE_B + a);
            }
        }
        if (j < qi) {
            const long kb = ((long)bh * S_LEN + (long)(j + 1) * 128) * DKH;
            const u32 nbuf = sb + OFF_KV0 + (u32)((j + 1) & 1) * KV_SZ;
#pragma unroll
            for (int i = 0; i < 16; i++) {
                const int t = i >> 2;
                const int idx = (i & 3) * 256 + tid;
                const int r = idx >> 3, c = idx & 7;
                const __nv_bfloat16* src =
                    (t == 0 ? g_Kh : t == 1 ? g_Kl : t == 2 ? g_Qh : g_Ql) + kb + r * 64 + c * 8;
                CP_ASYNC16(nbuf + t * TILE_B + r * PITCH + c * 16, src);
            }
            CP_COMMIT();
        }

        float s_[16][4] = {};
#pragma unroll
        for (int nc = 0; nc < 8; nc++) {
            u32 bh_[4][4], bl_[4][4];
#pragma unroll
            for (int s = 0; s < 4; s++) {
                const u32 a = buf + (u32)((nc * 16 + lrow) * PITCH + s * 32 + lch * 16);
                ldsm_x4(bh_[s][0], bh_[s][1], bh_[s][2], bh_[s][3], a);
                ldsm_x4(bl_[s][0], bl_[s][1], bl_[s][2], bl_[s][3], a + TILE_B);
            }
#pragma unroll
            for (int s = 0; s < 4; s++) {
                mma16816(s_[2 * nc],     aQh[s][0], aQh[s][1], aQh[s][2], aQh[s][3], bh_[s][0], bh_[s][2]);
                mma16816(s_[2 * nc + 1], aQh[s][0], aQh[s][1], aQh[s][2], aQh[s][3], bh_[s][1], bh_[s][3]);
                mma16816(s_[2 * nc],     aQh[s][0], aQh[s][1], aQh[s][2], aQh[s][3], bl_[s][0], bl_[s][2]);
                mma16816(s_[2 * nc + 1], aQh[s][0], aQh[s][1], aQh[s][2], aQh[s][3], bl_[s][1], bl_[s][3]);
                mma16816(s_[2 * nc],     aQl[s][0], aQl[s][1], aQl[s][2], aQl[s][3], bh_[s][0], bh_[s][2]);
                mma16816(s_[2 * nc + 1], aQl[s][0], aQl[s][1], aQl[s][2], aQl[s][3], bh_[s][1], bh_[s][3]);
            }
        }

        float rmx0 = -1e30f, rmx1 = -1e30f;
#pragma unroll
        for (int nt = 0; nt < 16; nt++) {
#pragma unroll
            for (int q = 0; q < 4; q++) s_[nt][q] *= 0.125f;
            if (j == qi) {
                const int c0 = nt * 8 + (lane & 3) * 2;
                if (c0 > rlo)     s_[nt][0] = -1e30f;
                if (c0 + 1 > rlo) s_[nt][1] = -1e30f;
                if (c0 > rhi)     s_[nt][2] = -1e30f;
                if (c0 + 1 > rhi) s_[nt][3] = -1e30f;
            }
            rmx0 = fmaxf(rmx0, fmaxf(s_[nt][0], s_[nt][1]));
            rmx1 = fmaxf(rmx1, fmaxf(s_[nt][2], s_[nt][3]));
        }
        rmx0 = fmaxf(rmx0, __shfl_xor_sync(0xffffffffu, rmx0, 1));
        rmx0 = fmaxf(rmx0, __shfl_xor_sync(0xffffffffu, rmx0, 2));
        rmx1 = fmaxf(rmx1, __shfl_xor_sync(0xffffffffu, rmx1, 1));
        rmx1 = fmaxf(rmx1, __shfl_xor_sync(0xffffffffu, rmx1, 2));
        const float mn0 = fmaxf(mst0, rmx0);
        const float mn1 = fmaxf(mst1, rmx1);
        const float al0 = __expf(mst0 - mn0);
        const float al1 = __expf(mst1 - mn1);
        float sum0 = 0.0f, sum1 = 0.0f;
#pragma unroll
        for (int nt = 0; nt < 16; nt++) {
            s_[nt][0] = __expf(s_[nt][0] - mn0);
            s_[nt][1] = __expf(s_[nt][1] - mn0);
            s_[nt][2] = __expf(s_[nt][2] - mn1);
            s_[nt][3] = __expf(s_[nt][3] - mn1);
            sum0 += s_[nt][0] + s_[nt][1];
            sum1 += s_[nt][2] + s_[nt][3];
        }
        sum0 += __shfl_xor_sync(0xffffffffu, sum0, 1);
        sum0 += __shfl_xor_sync(0xffffffffu, sum0, 2);
        sum1 += __shfl_xor_sync(0xffffffffu, sum1, 1);
        sum1 += __shfl_xor_sync(0xffffffffu, sum1, 2);
        lst0 = lst0 * al0 + sum0;
        lst1 = lst1 * al1 + sum1;
        mst0 = mn0;
        mst1 = mn1;
#pragma unroll
        for (int nt = 0; nt < 8; nt++) {
            o_[nt][0] *= al0; o_[nt][1] *= al0;
            o_[nt][2] *= al1; o_[nt][3] *= al1;
        }

        const u32 vh_b = buf + 2 * TILE_B;
#pragma unroll
        for (int s = 0; s < 8; s++) {
            u32 ah[4], al_[4];
            ah[0] = cvt2bf(s_[2 * s][0], s_[2 * s][1]);
            ah[1] = cvt2bf(s_[2 * s][2], s_[2 * s][3]);
            ah[2] = cvt2bf(s_[2 * s + 1][0], s_[2 * s + 1][1]);
            ah[3] = cvt2bf(s_[2 * s + 1][2], s_[2 * s + 1][3]);
            al_[0] = resid2(ah[0], s_[2 * s][0], s_[2 * s][1]);
            al_[1] = resid2(ah[1], s_[2 * s][2], s_[2 * s][3]);
            al_[2] = resid2(ah[2], s_[2 * s + 1][0], s_[2 * s + 1][1]);
            al_[3] = resid2(ah[3], s_[2 * s + 1][2], s_[2 * s + 1][3]);

            u32 vh_[8][2], vl_[8][2];
#pragma unroll
            for (int tp = 0; tp < 4; tp++) {
                const u32 a = vh_b + (u32)((s * 16 + lrow) * PITCH + (tp * 2 + lch) * 16);
                u32 r0, r1, r2, r3;
                ldsm_x4t(r0, r1, r2, r3, a);
                vh_[2 * tp][0] = r0; vh_[2 * tp][1] = r1;
                vh_[2 * tp + 1][0] = r2; vh_[2 * tp + 1][1] = r3;
                ldsm_x4t(r0, r1, r2, r3, a + TILE_B);
                vl_[2 * tp][0] = r0; vl_[2 * tp][1] = r1;
                vl_[2 * tp + 1][0] = r2; vl_[2 * tp + 1][1] = r3;
            }
#pragma unroll
            for (int nt = 0; nt < 8; nt++) {
                mma16816(o_[nt], ah[0], ah[1], ah[2], ah[3], vh_[nt][0], vh_[nt][1]);
                mma16816(o_[nt], ah[0], ah[1], ah[2], ah[3], vl_[nt][0], vl_[nt][1]);
                mma16816(o_[nt], al_[0], al_[1], al_[2], al_[3], vh_[nt][0], vh_[nt][1]);
            }
        }
    }

    const int bat = bh >> 4, head = bh & 15;
    const float i0 = 1.0f / lst0;
    const float i1 = 1.0f / lst1;
    const int row0 = qi * 128 + rlo;
#pragma unroll
    for (int nt = 0; nt < 8; nt++) {
        const int d = head * 64 + nt * 8 + (lane & 3) * 2;
        {
            const float x = o_[nt][0] * i0, y = o_[nt][1] * i0;
            const u32 hh = cvt2bf(x, y), ll = resid2(hh, x, y);
            const long a = ((long)(bat * S_LEN + row0) << 10) + d;
            *(u32*)&g_Ah[a] = hh;
            *(u32*)&g_Al[a] = ll;
        }
        {
            const float x = o_[nt][2] * i1, y = o_[nt][3] * i1;
            const u32 hh = cvt2bf(x, y), ll = resid2(hh, x, y);
            const long a = ((long)(bat * S_LEN + row0 + 8) << 10) + d;
            *(u32*)&g_Ah[a] = hh;
            *(u32*)&g_Al[a] = ll;
        }
    }
}

// ---------------------------------------------------------------------------
extern "C" void kernel_launch(void* const* d_in, const int* in_sizes, int n_in,
                              void* d_out, int out_size)
{
    const float* x  = (const float*)d_in[0];
    const float* Wq = (const float*)d_in[1];
    const float* bq = (const float*)d_in[2];
    const float* Wk = (const float*)d_in[3];
    const float* bk = (const float*)d_in[4];
    const float* W0 = (const float*)d_in[5];
    const float* b0 = (const float*)d_in[6];
    float* out = (float*)d_out;

    __nv_bfloat16 *dAh, *dAl;
    cudaGetSymbolAddress((void**)&dAh, g_Ah);
    cudaGetSymbolAddress((void**)&dAl, g_Al);

    cudaFuncSetAttribute(attn_tc, cudaFuncAttributeMaxDynamicSharedMemorySize, AT_SMEM);
    cudaFuncSetAttribute(qk_gemm_tc, cudaFuncAttributeMaxDynamicSharedMemorySize, GSMEM);
    cudaFuncSetAttribute(out_gemm_tc, cudaFuncAttributeMaxDynamicSharedMemorySize, GSMEM);

    // 1) decompose x and all weights
    decomp_A<<<M_TOK * D_MODEL / 1024, 256>>>(x, dAh, dAl);
    dim3 wt_grid(32, 32, 3);
    decomp_WT3<<<wt_grid, 256>>>(Wq, Wk, W0);

    // 2) Q & K projections -> bf16 hi/lo head layout
    dim3 qk_grid(D_MODEL / 128, M_TOK / 128, 2);   // (8, 32, 2)
    qk_gemm_tc<<<qk_grid, 256, GSMEM>>>(bq, bk);

    // 3) attention (tensor cores) -> g_Ah/g_Al
    dim3 attn_grid(S_LEN / 128, BATCH * NHEAD);     // (16, 32)
    attn_tc<<<attn_grid, 256, AT_SMEM>>>();

    // 4) output projection
    dim3 o_grid(D_MODEL / 128, M_TOK / 128);        // (8, 32)
    out_gemm_tc<<<o_grid, 256, GSMEM>>>(b0, out);
}

// round 7
// speedup vs baseline: 2.8543x; 1.0077x over previous
#include <cuda_runtime.h>
#include <cuda_bf16.h>

#define S_LEN   2048
#define D_MODEL 1024
#define NHEAD   16
#define DKH     64
#define BATCH   2
#define M_TOK   (BATCH * S_LEN)   // 4096

typedef unsigned long long u64;
typedef unsigned int u32;

// ------------------------------- scratch -----------------------------------
__device__ __nv_bfloat16 g_Qh[BATCH * NHEAD * S_LEN * DKH];  // [B,H,S,DK] hi
__device__ __nv_bfloat16 g_Ql[BATCH * NHEAD * S_LEN * DKH];  // lo
__device__ __nv_bfloat16 g_Kh[BATCH * NHEAD * S_LEN * DKH];
__device__ __nv_bfloat16 g_Kl[BATCH * NHEAD * S_LEN * DKH];
__device__ __nv_bfloat16 g_Ah[M_TOK * D_MODEL];              // A hi (x, then att)
__device__ __nv_bfloat16 g_Al[M_TOK * D_MODEL];              // A lo
__device__ __nv_bfloat16 g_WhT[3][D_MODEL * D_MODEL];        // W^T hi: q,k,o
__device__ __nv_bfloat16 g_WlT[3][D_MODEL * D_MODEL];        // W^T lo

// --------------------------- small helpers ---------------------------------
__device__ __forceinline__ u32 smem_u32(const void* p) {
    u32 a; asm("{ .reg .u64 t; cvta.to.shared.u64 t, %1; cvt.u32.u64 %0, t; }" : "=r"(a) : "l"(p));
    return a;
}

#define CP_ASYNC16(dst, src) \
    asm volatile("cp.async.cg.shared.global [%0], [%1], 16;" :: "r"(dst), "l"(src))
#define CP_COMMIT()  asm volatile("cp.async.commit_group;" ::: "memory")
#define CP_WAIT1()   asm volatile("cp.async.wait_group 1;" ::: "memory")
#define CP_WAIT0()   asm volatile("cp.async.wait_group 0;" ::: "memory")

__device__ __forceinline__ void ldsm_x4(u32& r0, u32& r1, u32& r2, u32& r3, u32 addr) {
    asm volatile("ldmatrix.sync.aligned.m8n8.x4.shared.b16 {%0,%1,%2,%3}, [%4];"
                 : "=r"(r0), "=r"(r1), "=r"(r2), "=r"(r3) : "r"(addr));
}
__device__ __forceinline__ void ldsm_x4t(u32& r0, u32& r1, u32& r2, u32& r3, u32 addr) {
    asm volatile("ldmatrix.sync.aligned.m8n8.x4.trans.shared.b16 {%0,%1,%2,%3}, [%4];"
                 : "=r"(r0), "=r"(r1), "=r"(r2), "=r"(r3) : "r"(addr));
}

__device__ __forceinline__ void mma16816(float* d, u32 a0, u32 a1, u32 a2, u32 a3,
                                         u32 b0, u32 b1) {
    asm volatile("mma.sync.aligned.m16n8k16.row.col.f32.bf16.bf16.f32 "
                 "{%0,%1,%2,%3}, {%4,%5,%6,%7}, {%8,%9}, {%0,%1,%2,%3};"
                 : "+f"(d[0]), "+f"(d[1]), "+f"(d[2]), "+f"(d[3])
                 : "r"(a0), "r"(a1), "r"(a2), "r"(a3), "r"(b0), "r"(b1));
}

__device__ __forceinline__ u32 cvt2bf(float x, float y) {
    __nv_bfloat162 t = __floats2bfloat162_rn(x, y);
    return *reinterpret_cast<u32*>(&t);
}
__device__ __forceinline__ u32 resid2(u32 h, float x, float y) {
    float hx = __uint_as_float(h << 16);
    float hy = __uint_as_float(h & 0xffff0000u);
    return cvt2bf(x - hx, y - hy);
}
__device__ __forceinline__ u32 pack_bf2(__nv_bfloat16 a, __nv_bfloat16 b) {
    __nv_bfloat162 p(a, b);
    return *reinterpret_cast<u32*>(&p);
}

// ------------------------- fp32 -> bf16 hi/lo split -------------------------
__global__ __launch_bounds__(256) void decomp_A(const float* __restrict__ src,
                                                __nv_bfloat16* __restrict__ hi,
                                                __nv_bfloat16* __restrict__ lo)
{
    const int i = (blockIdx.x * 256 + threadIdx.x) * 4;
    float4 v = *(const float4*)(src + i);
    __nv_bfloat16 h0 = __float2bfloat16_rn(v.x);
    __nv_bfloat16 h1 = __float2bfloat16_rn(v.y);
    __nv_bfloat16 h2 = __float2bfloat16_rn(v.z);
    __nv_bfloat16 h3 = __float2bfloat16_rn(v.w);
    __nv_bfloat16 l0 = __float2bfloat16_rn(v.x - __bfloat162float(h0));
    __nv_bfloat16 l1 = __float2bfloat16_rn(v.y - __bfloat162float(h1));
    __nv_bfloat16 l2 = __float2bfloat16_rn(v.z - __bfloat162float(h2));
    __nv_bfloat16 l3 = __float2bfloat16_rn(v.w - __bfloat162float(h3));
    *(uint2*)(hi + i) = make_uint2(pack_bf2(h0, h1), pack_bf2(h2, h3));
    *(uint2*)(lo + i) = make_uint2(pack_bf2(l0, l1), pack_bf2(l2, l3));
}

// all three W [K,N] fp32 -> W^T hi/lo bf16, one launch (z = which matrix)
__global__ __launch_bounds__(256) void decomp_WT3(const float* __restrict__ Wq,
                                                  const float* __restrict__ Wk,
                                                  const float* __restrict__ W0)
{
    const int z = blockIdx.z;
    const float* W = (z == 0) ? Wq : (z == 1) ? Wk : W0;
    __nv_bfloat16* hiT = g_WhT[z];
    __nv_bfloat16* loT = g_WlT[z];

    __shared__ float t[32][33];
    const int tx = threadIdx.x & 31, ty = threadIdx.x >> 5;   // (32, 8)
    const int n0 = blockIdx.x * 32, k0 = blockIdx.y * 32;
#pragma unroll
    for (int i = 0; i < 4; i++)
        t[ty + 8 * i][tx] = W[(k0 + ty + 8 * i) * D_MODEL + n0 + tx];
    __syncthreads();
#pragma unroll
    for (int i = 0; i < 4; i++) {
        float v = t[tx][ty + 8 * i];
        __nv_bfloat16 h = __float2bfloat16_rn(v);
        __nv_bfloat16 l = __float2bfloat16_rn(v - __bfloat162float(h));
        const long o = (long)(n0 + ty + 8 * i) * D_MODEL + k0 + tx;
        hiT[o] = h;
        loT[o] = l;
    }
}

// ---------------------------------------------------------------------------
// Fused 3-pass split-bf16 GEMM: C[4096,1024] = A @ W + bias
// BM=128, BN=64, BK=32, 256 threads (8 warps 2x4), warp tile 64x16.
// 2-stage cp.async, 2 CTAs/SM (launch_bounds (256,2)).
//   MODE 0: write bf16 hi/lo into head layout [B,H,S,DK]
//   MODE 1: write fp32 row-major [M,N]
// ---------------------------------------------------------------------------
#define ROWB  80                       // 64 data bytes + 16 pad
#define ATILE (128 * ROWB)             // 10240
#define BTILE (64 * ROWB)              // 5120
#define STAGE (2 * ATILE + 2 * BTILE)  // 30720 : [Ah][Al][Bh][Bl]
#define GSMEM (2 * STAGE)              // 61440

template <int MODE>
__device__ __forceinline__ void tc_gemm_body(const __nv_bfloat16* __restrict__ Ah,
                                             const __nv_bfloat16* __restrict__ Al,
                                             const __nv_bfloat16* __restrict__ BhT,
                                             const __nv_bfloat16* __restrict__ BlT,
                                             const float* __restrict__ bias,
                                             float* __restrict__ out,
                                             __nv_bfloat16* __restrict__ outh,
                                             __nv_bfloat16* __restrict__ outl)
{
    extern __shared__ __align__(16) char smg[];
    const u32 sb = smem_u32(smg);

    const int tid = threadIdx.x;
    const int wid = tid >> 5;
    const int lane = tid & 31;
    const int warp_m = wid >> 2;          // 0..1  (64 rows each)
    const int warp_n = wid & 3;           // 0..3  (16 cols each)
    const int m0 = blockIdx.y * 128;
    const int n0 = blockIdx.x * 64;

    const int a_row = (lane & 15);
    const int a_kh  = (lane >> 4);
    const u32 aoff = (u32)((warp_m * 64 + a_row) * ROWB + a_kh * 16);
    const int b_row = (lane & 7) + ((lane >> 4) << 3);
    const int b_kh  = (lane >> 3) & 1;
    const u32 boff = (u32)((warp_n * 16 + b_row) * ROWB + b_kh * 16);

    float acc[4][2][4] = {};

    const __nv_bfloat16* aS[2] = { Ah + ((long)m0 << 10), Al + ((long)m0 << 10) };
    const __nv_bfloat16* bS[2] = { BhT + ((long)n0 << 10), BlT + ((long)n0 << 10) };

    auto issue = [&](int kc, int p) {
        const u32 dst = sb + (u32)p * STAGE;
        const int row_a = tid >> 2, ch = tid & 3;          // 0..63 rows? no: tid>>2 = 0..63
        // A tiles: 128 rows x 4 chunks = 512 xfers per tile -> 2 per thread
#pragma unroll
        for (int t = 0; t < 2; t++) {
#pragma unroll
            for (int i = 0; i < 2; i++) {
                const int f = i * 256 + tid;               // 0..511
                const int r = f >> 2, cc = f & 3;
                CP_ASYNC16(dst + t * ATILE + r * ROWB + cc * 16,
                           aS[t] + ((long)r << 10) + kc * 32 + cc * 8);
            }
        }
        // B tiles: 64 rows x 4 chunks = 256 xfers per tile -> 1 per thread
#pragma unroll
        for (int t = 0; t < 2; t++) {
            CP_ASYNC16(dst + 2 * ATILE + t * BTILE + row_a * ROWB + ch * 16,
                       bS[t] + ((long)row_a << 10) + kc * 32 + ch * 8);
        }
    };

    issue(0, 0); CP_COMMIT();
    issue(1, 1); CP_COMMIT();

    for (int c = 0; c < 32; c++) {
        const int p = c & 1;
        CP_WAIT1();
        __syncthreads();

        const u32 base = sb + (u32)p * STAGE;
#pragma unroll
        for (int ks = 0; ks < 2; ks++) {
            u32 ah[4][4], al[4][4];
#pragma unroll
            for (int mt = 0; mt < 4; mt++) {
                const u32 a = base + aoff + mt * (16 * ROWB) + ks * 32;
                ldsm_x4(ah[mt][0], ah[mt][1], ah[mt][2], ah[mt][3], a);
                ldsm_x4(al[mt][0], al[mt][1], al[mt][2], al[mt][3], a + ATILE);
            }
            u32 bfr[2][2];
            {
                u32 r0, r1, r2, r3;
                ldsm_x4(r0, r1, r2, r3, base + 2 * ATILE + boff + ks * 32);
                bfr[0][0] = r0; bfr[0][1] = r1; bfr[1][0] = r2; bfr[1][1] = r3;
            }
#pragma unroll
            for (int mt = 0; mt < 4; mt++)
#pragma unroll
                for (int nt = 0; nt < 2; nt++) {
                    mma16816(acc[mt][nt], ah[mt][0], ah[mt][1], ah[mt][2], ah[mt][3],
                             bfr[nt][0], bfr[nt][1]);
                    mma16816(acc[mt][nt], al[mt][0], al[mt][1], al[mt][2], al[mt][3],
                             bfr[nt][0], bfr[nt][1]);
                }
            {
                u32 r0, r1, r2, r3;
                ldsm_x4(r0, r1, r2, r3, base + 2 * ATILE + BTILE + boff + ks * 32);
                bfr[0][0] = r0; bfr[0][1] = r1; bfr[1][0] = r2; bfr[1][1] = r3;
            }
#pragma unroll
            for (int mt = 0; mt < 4; mt++)
#pragma unroll
                for (int nt = 0; nt < 2; nt++)
                    mma16816(acc[mt][nt], ah[mt][0], ah[mt][1], ah[mt][2], ah[mt][3],
                             bfr[nt][0], bfr[nt][1]);
        }
        __syncthreads();
        if (c + 2 < 32) issue(c + 2, p);
        CP_COMMIT();
    }

    // epilogue
#pragma unroll
    for (int mt = 0; mt < 4; mt++) {
#pragma unroll
        for (int nt = 0; nt < 2; nt++) {
            const int m = m0 + warp_m * 64 + mt * 16 + (lane >> 2);
            const int n = n0 + warp_n * 16 + nt * 8 + (lane & 3) * 2;
            const float bx = bias[n], by = bias[n + 1];
#pragma unroll
            for (int half = 0; half < 2; half++) {
                const int mm = m + half * 8;
                const float vx = acc[mt][nt][half * 2 + 0] + bx;
                const float vy = acc[mt][nt][half * 2 + 1] + by;
                if (MODE == 1) {
                    *(float2*)&out[(long)mm * D_MODEL + n] = make_float2(vx, vy);
                } else {
                    const int b = mm >> 11, s = mm & 2047;
                    const int hd = n >> 6, dk = n & 63;
                    const long o = (((long)(b * NHEAD + hd) * S_LEN + s) << 6) + dk;
                    const u32 hh = cvt2bf(vx, vy);
                    const u32 ll = resid2(hh, vx, vy);
                    *(u32*)&outh[o] = hh;
                    *(u32*)&outl[o] = ll;
                }
            }
        }
    }
}

__global__ __launch_bounds__(256, 2) void qk_gemm_tc(const float* __restrict__ bq,
                                                     const float* __restrict__ bk)
{
    if (blockIdx.z == 0)
        tc_gemm_body<0>(g_Ah, g_Al, g_WhT[0], g_WlT[0], bq, nullptr, g_Qh, g_Ql);
    else
        tc_gemm_body<0>(g_Ah, g_Al, g_WhT[1], g_WlT[1], bk, nullptr, g_Kh, g_Kl);
}

__global__ __launch_bounds__(256, 2) void out_gemm_tc(const float* __restrict__ b0,
                                                      float* __restrict__ out)
{
    tc_gemm_body<1>(g_Ah, g_Al, g_WhT[2], g_WlT[2], b0, out, nullptr, nullptr);
}

// ---------------------------------------------------------------------------
// Flash attention on mma.sync, causal, V = Q. (unchanged from round 6)
// ---------------------------------------------------------------------------
#define PITCH   144
#define TILE_B  (128 * PITCH)
#define OFF_KV0 (2 * TILE_B)
#define KV_SZ   (4 * TILE_B)
#define AT_SMEM (OFF_KV0 + 2 * KV_SZ)

__global__ __launch_bounds__(256, 1) void attn_tc()
{
    extern __shared__ char smc[];
    const u32 sb = smem_u32(smc);
    const int tid  = threadIdx.x;
    const int lane = tid & 31;
    const int w    = tid >> 5;
    const int qi = (int)gridDim.x - 1 - (int)blockIdx.x;
    const int bh = blockIdx.y;

    const int lrow = lane & 15;
    const int lch  = lane >> 4;
    const int rlo  = w * 16 + (lane >> 2);
    const int rhi  = rlo + 8;

    {
        const long qb = ((long)bh * S_LEN + (long)qi * 128) * DKH;
#pragma unroll
        for (int i = 0; i < 8; i++) {
            const int t = i >> 2;
            const int idx = (i & 3) * 256 + tid;
            const int r = idx >> 3, c = idx & 7;
            const __nv_bfloat16* src = (t == 0 ? g_Qh : g_Ql) + qb + r * 64 + c * 8;
            CP_ASYNC16(sb + t * TILE_B + r * PITCH + c * 16, src);
        }
        const long kb = ((long)bh * S_LEN) * DKH;
#pragma unroll
        for (int i = 0; i < 16; i++) {
            const int t = i >> 2;
            const int idx = (i & 3) * 256 + tid;
            const int r = idx >> 3, c = idx & 7;
            const __nv_bfloat16* src =
                (t == 0 ? g_Kh : t == 1 ? g_Kl : t == 2 ? g_Qh : g_Ql) + kb + r * 64 + c * 8;
            CP_ASYNC16(sb + OFF_KV0 + t * TILE_B + r * PITCH + c * 16, src);
        }
        CP_COMMIT();
    }

    u32 aQh[4][4], aQl[4][4];
    float o_[8][4] = {};
    float mst0 = -1e30f, mst1 = -1e30f;
    float lst0 = 0.0f, lst1 = 0.0f;

    for (int j = 0; j <= qi; j++) {
        CP_WAIT0();
        __syncthreads();
        const u32 buf = sb + OFF_KV0 + (u32)(j & 1) * KV_SZ;

        if (j == 0) {
#pragma unroll
            for (int s = 0; s < 4; s++) {
                const u32 a = (u32)((w * 16 + lrow) * PITCH + s * 32 + lch * 16);
                ldsm_x4(aQh[s][0], aQh[s][1], aQh[s][2], aQh[s][3], sb + a);
                ldsm_x4(aQl[s][0], aQl[s][1], aQl[s][2], aQl[s][3], sb + TILE_B + a);
            }
        }
        if (j < qi) {
            const long kb = ((long)bh * S_LEN + (long)(j + 1) * 128) * DKH;
            const u32 nbuf = sb + OFF_KV0 + (u32)((j + 1) & 1) * KV_SZ;
#pragma unroll
            for (int i = 0; i < 16; i++) {
                const int t = i >> 2;
                const int idx = (i & 3) * 256 + tid;
                const int r = idx >> 3, c = idx & 7;
                const __nv_bfloat16* src =
                    (t == 0 ? g_Kh : t == 1 ? g_Kl : t == 2 ? g_Qh : g_Ql) + kb + r * 64 + c * 8;
                CP_ASYNC16(nbuf + t * TILE_B + r * PITCH + c * 16, src);
            }
            CP_COMMIT();
        }

        float s_[16][4] = {};
#pragma unroll
        for (int nc = 0; nc < 8; nc++) {
            u32 bh_[4][4], bl_[4][4];
#pragma unroll
            for (int s = 0; s < 4; s++) {
                const u32 a = buf + (u32)((nc * 16 + lrow) * PITCH + s * 32 + lch * 16);
                ldsm_x4(bh_[s][0], bh_[s][1], bh_[s][2], bh_[s][3], a);
                ldsm_x4(bl_[s][0], bl_[s][1], bl_[s][2], bl_[s][3], a + TILE_B);
            }
#pragma unroll
            for (int s = 0; s < 4; s++) {
                mma16816(s_[2 * nc],     aQh[s][0], aQh[s][1], aQh[s][2], aQh[s][3], bh_[s][0], bh_[s][2]);
                mma16816(s_[2 * nc + 1], aQh[s][0], aQh[s][1], aQh[s][2], aQh[s][3], bh_[s][1], bh_[s][3]);
                mma16816(s_[2 * nc],     aQh[s][0], aQh[s][1], aQh[s][2], aQh[s][3], bl_[s][0], bl_[s][2]);
                mma16816(s_[2 * nc + 1], aQh[s][0], aQh[s][1], aQh[s][2], aQh[s][3], bl_[s][1], bl_[s][3]);
                mma16816(s_[2 * nc],     aQl[s][0], aQl[s][1], aQl[s][2], aQl[s][3], bh_[s][0], bh_[s][2]);
                mma16816(s_[2 * nc + 1], aQl[s][0], aQl[s][1], aQl[s][2], aQl[s][3], bh_[s][1], bh_[s][3]);
            }
        }

        float rmx0 = -1e30f, rmx1 = -1e30f;
#pragma unroll
        for (int nt = 0; nt < 16; nt++) {
#pragma unroll
            for (int q = 0; q < 4; q++) s_[nt][q] *= 0.125f;
            if (j == qi) {
                const int c0 = nt * 8 + (lane & 3) * 2;
                if (c0 > rlo)     s_[nt][0] = -1e30f;
                if (c0 + 1 > rlo) s_[nt][1] = -1e30f;
                if (c0 > rhi)     s_[nt][2] = -1e30f;
                if (c0 + 1 > rhi) s_[nt][3] = -1e30f;
            }
            rmx0 = fmaxf(rmx0, fmaxf(s_[nt][0], s_[nt][1]));
            rmx1 = fmaxf(rmx1, fmaxf(s_[nt][2], s_[nt][3]));
        }
        rmx0 = fmaxf(rmx0, __shfl_xor_sync(0xffffffffu, rmx0, 1));
        rmx0 = fmaxf(rmx0, __shfl_xor_sync(0xffffffffu, rmx0, 2));
        rmx1 = fmaxf(rmx1, __shfl_xor_sync(0xffffffffu, rmx1, 1));
        rmx1 = fmaxf(rmx1, __shfl_xor_sync(0xffffffffu, rmx1, 2));
        const float mn0 = fmaxf(mst0, rmx0);
        const float mn1 = fmaxf(mst1, rmx1);
        const float al0 = __expf(mst0 - mn0);
        const float al1 = __expf(mst1 - mn1);
        float sum0 = 0.0f, sum1 = 0.0f;
#pragma unroll
        for (int nt = 0; nt < 16; nt++) {
            s_[nt][0] = __expf(s_[nt][0] - mn0);
            s_[nt][1] = __expf(s_[nt][1] - mn0);
            s_[nt][2] = __expf(s_[nt][2] - mn1);
            s_[nt][3] = __expf(s_[nt][3] - mn1);
            sum0 += s_[nt][0] + s_[nt][1];
            sum1 += s_[nt][2] + s_[nt][3];
        }
        sum0 += __shfl_xor_sync(0xffffffffu, sum0, 1);
        sum0 += __shfl_xor_sync(0xffffffffu, sum0, 2);
        sum1 += __shfl_xor_sync(0xffffffffu, sum1, 1);
        sum1 += __shfl_xor_sync(0xffffffffu, sum1, 2);
        lst0 = lst0 * al0 + sum0;
        lst1 = lst1 * al1 + sum1;
        mst0 = mn0;
        mst1 = mn1;
#pragma unroll
        for (int nt = 0; nt < 8; nt++) {
            o_[nt][0] *= al0; o_[nt][1] *= al0;
            o_[nt][2] *= al1; o_[nt][3] *= al1;
        }

        const u32 vh_b = buf + 2 * TILE_B;
#pragma unroll
        for (int s = 0; s < 8; s++) {
            u32 ah[4], al_[4];
            ah[0] = cvt2bf(s_[2 * s][0], s_[2 * s][1]);
            ah[1] = cvt2bf(s_[2 * s][2], s_[2 * s][3]);
            ah[2] = cvt2bf(s_[2 * s + 1][0], s_[2 * s + 1][1]);
            ah[3] = cvt2bf(s_[2 * s + 1][2], s_[2 * s + 1][3]);
            al_[0] = resid2(ah[0], s_[2 * s][0], s_[2 * s][1]);
            al_[1] = resid2(ah[1], s_[2 * s][2], s_[2 * s][3]);
            al_[2] = resid2(ah[2], s_[2 * s + 1][0], s_[2 * s + 1][1]);
            al_[3] = resid2(ah[3], s_[2 * s + 1][2], s_[2 * s + 1][3]);

            u32 vh_[8][2], vl_[8][2];
#pragma unroll
            for (int tp = 0; tp < 4; tp++) {
                const u32 a = vh_b + (u32)((s * 16 + lrow) * PITCH + (tp * 2 + lch) * 16);
                u32 r0, r1, r2, r3;
                ldsm_x4t(r0, r1, r2, r3, a);
                vh_[2 * tp][0] = r0; vh_[2 * tp][1] = r1;
                vh_[2 * tp + 1][0] = r2; vh_[2 * tp + 1][1] = r3;
                ldsm_x4t(r0, r1, r2, r3, a + TILE_B);
                vl_[2 * tp][0] = r0; vl_[2 * tp][1] = r1;
                vl_[2 * tp + 1][0] = r2; vl_[2 * tp + 1][1] = r3;
            }
#pragma unroll
            for (int nt = 0; nt < 8; nt++) {
                mma16816(o_[nt], ah[0], ah[1], ah[2], ah[3], vh_[nt][0], vh_[nt][1]);
                mma16816(o_[nt], ah[0], ah[1], ah[2], ah[3], vl_[nt][0], vl_[nt][1]);
                mma16816(o_[nt], al_[0], al_[1], al_[2], al_[3], vh_[nt][0], vh_[nt][1]);
            }
        }
    }

    const int bat = bh >> 4, head = bh & 15;
    const float i0 = 1.0f / lst0;
    const float i1 = 1.0f / lst1;
    const int row0 = qi * 128 + rlo;
#pragma unroll
    for (int nt = 0; nt < 8; nt++) {
        const int d = head * 64 + nt * 8 + (lane & 3) * 2;
        {
            const float x = o_[nt][0] * i0, y = o_[nt][1] * i0;
            const u32 hh = cvt2bf(x, y), ll = resid2(hh, x, y);
            const long a = ((long)(bat * S_LEN + row0) << 10) + d;
            *(u32*)&g_Ah[a] = hh;
            *(u32*)&g_Al[a] = ll;
        }
        {
            const float x = o_[nt][2] * i1, y = o_[nt][3] * i1;
            const u32 hh = cvt2bf(x, y), ll = resid2(hh, x, y);
            const long a = ((long)(bat * S_LEN + row0 + 8) << 10) + d;
            *(u32*)&g_Ah[a] = hh;
            *(u32*)&g_Al[a] = ll;
        }
    }
}

// ---------------------------------------------------------------------------
extern "C" void kernel_launch(void* const* d_in, const int* in_sizes, int n_in,
                              void* d_out, int out_size)
{
    const float* x  = (const float*)d_in[0];
    const float* Wq = (const float*)d_in[1];
    const float* bq = (const float*)d_in[2];
    const float* Wk = (const float*)d_in[3];
    const float* bk = (const float*)d_in[4];
    const float* W0 = (const float*)d_in[5];
    const float* b0 = (const float*)d_in[6];
    float* out = (float*)d_out;

    __nv_bfloat16 *dAh, *dAl;
    cudaGetSymbolAddress((void**)&dAh, g_Ah);
    cudaGetSymbolAddress((void**)&dAl, g_Al);

    cudaFuncSetAttribute(attn_tc, cudaFuncAttributeMaxDynamicSharedMemorySize, AT_SMEM);
    cudaFuncSetAttribute(qk_gemm_tc, cudaFuncAttributeMaxDynamicSharedMemorySize, GSMEM);
    cudaFuncSetAttribute(out_gemm_tc, cudaFuncAttributeMaxDynamicSharedMemorySize, GSMEM);

    // 1) decompose x and all weights
    decomp_A<<<M_TOK * D_MODEL / 1024, 256>>>(x, dAh, dAl);
    dim3 wt_grid(32, 32, 3);
    decomp_WT3<<<wt_grid, 256>>>(Wq, Wk, W0);

    // 2) Q & K projections -> bf16 hi/lo head layout
    dim3 qk_grid(D_MODEL / 64, M_TOK / 128, 2);    // (16, 32, 2)
    qk_gemm_tc<<<qk_grid, 256, GSMEM>>>(bq, bk);

    // 3) attention (tensor cores) -> g_Ah/g_Al
    dim3 attn_grid(S_LEN / 128, BATCH * NHEAD);     // (16, 32)
    attn_tc<<<attn_grid, 256, AT_SMEM>>>();

    // 4) output projection
    dim3 o_grid(D_MODEL / 64, M_TOK / 128);         // (16, 32)
    out_gemm_tc<<<o_grid, 256, GSMEM>>>(b0, out);
}

// round 8
// speedup vs baseline: 2.8810x; 1.0093x over previous
#include <cuda_runtime.h>
#include <cuda_bf16.h>

#define S_LEN   2048
#define D_MODEL 1024
#define NHEAD   16
#define DKH     64
#define BATCH   2
#define M_TOK   (BATCH * S_LEN)   // 4096

typedef unsigned long long u64;
typedef unsigned int u32;

// ------------------------------- scratch -----------------------------------
__device__ __nv_bfloat16 g_Qh[BATCH * NHEAD * S_LEN * DKH];  // [B,H,S,DK] hi
__device__ __nv_bfloat16 g_Ql[BATCH * NHEAD * S_LEN * DKH];  // lo
__device__ __nv_bfloat16 g_Kh[BATCH * NHEAD * S_LEN * DKH];
__device__ __nv_bfloat16 g_Kl[BATCH * NHEAD * S_LEN * DKH];
__device__ __nv_bfloat16 g_Ah[M_TOK * D_MODEL];              // A hi (x, then att)
__device__ __nv_bfloat16 g_Al[M_TOK * D_MODEL];              // A lo
__device__ __nv_bfloat16 g_WhT[3][D_MODEL * D_MODEL];        // W^T hi: q,k,o
__device__ __nv_bfloat16 g_WlT[3][D_MODEL * D_MODEL];        // W^T lo

// --------------------------- small helpers ---------------------------------
__device__ __forceinline__ u32 smem_u32(const void* p) {
    u32 a; asm("{ .reg .u64 t; cvta.to.shared.u64 t, %1; cvt.u32.u64 %0, t; }" : "=r"(a) : "l"(p));
    return a;
}

#define CP_ASYNC16(dst, src) \
    asm volatile("cp.async.cg.shared.global [%0], [%1], 16;" :: "r"(dst), "l"(src))
#define CP_COMMIT()  asm volatile("cp.async.commit_group;" ::: "memory")
#define CP_WAIT2()   asm volatile("cp.async.wait_group 2;" ::: "memory")
#define CP_WAIT0()   asm volatile("cp.async.wait_group 0;" ::: "memory")

__device__ __forceinline__ void ldsm_x4(u32& r0, u32& r1, u32& r2, u32& r3, u32 addr) {
    asm volatile("ldmatrix.sync.aligned.m8n8.x4.shared.b16 {%0,%1,%2,%3}, [%4];"
                 : "=r"(r0), "=r"(r1), "=r"(r2), "=r"(r3) : "r"(addr));
}
__device__ __forceinline__ void ldsm_x4t(u32& r0, u32& r1, u32& r2, u32& r3, u32 addr) {
    asm volatile("ldmatrix.sync.aligned.m8n8.x4.trans.shared.b16 {%0,%1,%2,%3}, [%4];"
                 : "=r"(r0), "=r"(r1), "=r"(r2), "=r"(r3) : "r"(addr));
}

__device__ __forceinline__ void mma16816(float* d, u32 a0, u32 a1, u32 a2, u32 a3,
                                         u32 b0, u32 b1) {
    asm volatile("mma.sync.aligned.m16n8k16.row.col.f32.bf16.bf16.f32 "
                 "{%0,%1,%2,%3}, {%4,%5,%6,%7}, {%8,%9}, {%0,%1,%2,%3};"
                 : "+f"(d[0]), "+f"(d[1]), "+f"(d[2]), "+f"(d[3])
                 : "r"(a0), "r"(a1), "r"(a2), "r"(a3), "r"(b0), "r"(b1));
}

__device__ __forceinline__ float ex2(float x) {
    float y; asm("ex2.approx.f32 %0, %1;" : "=f"(y) : "f"(x)); return y;
}

__device__ __forceinline__ u32 cvt2bf(float x, float y) {
    __nv_bfloat162 t = __floats2bfloat162_rn(x, y);
    return *reinterpret_cast<u32*>(&t);
}
__device__ __forceinline__ u32 resid2(u32 h, float x, float y) {
    float hx = __uint_as_float(h << 16);
    float hy = __uint_as_float(h & 0xffff0000u);
    return cvt2bf(x - hx, y - hy);
}
__device__ __forceinline__ u32 pack_bf2(__nv_bfloat16 a, __nv_bfloat16 b) {
    __nv_bfloat162 p(a, b);
    return *reinterpret_cast<u32*>(&p);
}

// ------------------------- fp32 -> bf16 hi/lo split -------------------------
__global__ __launch_bounds__(256) void decomp_A(const float* __restrict__ src,
                                                __nv_bfloat16* __restrict__ hi,
                                                __nv_bfloat16* __restrict__ lo)
{
    const int i = (blockIdx.x * 256 + threadIdx.x) * 4;
    float4 v = *(const float4*)(src + i);
    __nv_bfloat16 h0 = __float2bfloat16_rn(v.x);
    __nv_bfloat16 h1 = __float2bfloat16_rn(v.y);
    __nv_bfloat16 h2 = __float2bfloat16_rn(v.z);
    __nv_bfloat16 h3 = __float2bfloat16_rn(v.w);
    __nv_bfloat16 l0 = __float2bfloat16_rn(v.x - __bfloat162float(h0));
    __nv_bfloat16 l1 = __float2bfloat16_rn(v.y - __bfloat162float(h1));
    __nv_bfloat16 l2 = __float2bfloat16_rn(v.z - __bfloat162float(h2));
    __nv_bfloat16 l3 = __float2bfloat16_rn(v.w - __bfloat162float(h3));
    *(uint2*)(hi + i) = make_uint2(pack_bf2(h0, h1), pack_bf2(h2, h3));
    *(uint2*)(lo + i) = make_uint2(pack_bf2(l0, l1), pack_bf2(l2, l3));
}

// all three W [K,N] fp32 -> W^T hi/lo bf16, one launch (z = which matrix)
__global__ __launch_bounds__(256) void decomp_WT3(const float* __restrict__ Wq,
                                                  const float* __restrict__ Wk,
                                                  const float* __restrict__ W0)
{
    const int z = blockIdx.z;
    const float* W = (z == 0) ? Wq : (z == 1) ? Wk : W0;
    __nv_bfloat16* hiT = g_WhT[z];
    __nv_bfloat16* loT = g_WlT[z];

    __shared__ float t[32][33];
    const int tx = threadIdx.x & 31, ty = threadIdx.x >> 5;   // (32, 8)
    const int n0 = blockIdx.x * 32, k0 = blockIdx.y * 32;
#pragma unroll
    for (int i = 0; i < 4; i++)
        t[ty + 8 * i][tx] = W[(k0 + ty + 8 * i) * D_MODEL + n0 + tx];
    __syncthreads();
#pragma unroll
    for (int i = 0; i < 4; i++) {
        float v = t[tx][ty + 8 * i];
        __nv_bfloat16 h = __float2bfloat16_rn(v);
        __nv_bfloat16 l = __float2bfloat16_rn(v - __bfloat162float(h));
        const long o = (long)(n0 + ty + 8 * i) * D_MODEL + k0 + tx;
        hiT[o] = h;
        loT[o] = l;
    }
}

// ---------------------------------------------------------------------------
// Fused 3-pass split-bf16 GEMM: C[4096,1024] = A @ W + bias
// BM=128, BN=64, BK=32, 256 threads (8 warps 2x4), warp tile 64x16.
// 3-stage cp.async (prefetch distance 2 chunks), 2 CTAs/SM.
// Inner loop ordered sweep-major: 8 independent accumulator chains between
// same-chain revisits.
// ---------------------------------------------------------------------------
#define ROWB  80                       // 64 data bytes + 16 pad
#define ATILE (128 * ROWB)             // 10240
#define BTILE (64 * ROWB)              // 5120
#define STAGE (2 * ATILE + 2 * BTILE)  // 30720 : [Ah][Al][Bh][Bl]
#define GSMEM (3 * STAGE)              // 92160

template <int MODE>
__device__ __forceinline__ void tc_gemm_body(const __nv_bfloat16* __restrict__ Ah,
                                             const __nv_bfloat16* __restrict__ Al,
                                             const __nv_bfloat16* __restrict__ BhT,
                                             const __nv_bfloat16* __restrict__ BlT,
                                             const float* __restrict__ bias,
                                             float* __restrict__ out,
                                             __nv_bfloat16* __restrict__ outh,
                                             __nv_bfloat16* __restrict__ outl)
{
    extern __shared__ __align__(16) char smg[];
    const u32 sb = smem_u32(smg);

    const int tid = threadIdx.x;
    const int wid = tid >> 5;
    const int lane = tid & 31;
    const int warp_m = wid >> 2;          // 0..1  (64 rows each)
    const int warp_n = wid & 3;           // 0..3  (16 cols each)
    const int m0 = blockIdx.y * 128;
    const int n0 = blockIdx.x * 64;

    const int a_row = (lane & 15);
    const int a_kh  = (lane >> 4);
    const u32 aoff = (u32)((warp_m * 64 + a_row) * ROWB + a_kh * 16);
    const int b_row = (lane & 7) + ((lane >> 4) << 3);
    const int b_kh  = (lane >> 3) & 1;
    const u32 boff = (u32)((warp_n * 16 + b_row) * ROWB + b_kh * 16);

    float acc[4][2][4] = {};

    const __nv_bfloat16* aS[2] = { Ah + ((long)m0 << 10), Al + ((long)m0 << 10) };
    const __nv_bfloat16* bS[2] = { BhT + ((long)n0 << 10), BlT + ((long)n0 << 10) };

    auto issue = [&](int kc, int p) {
        const u32 dst = sb + (u32)p * STAGE;
        const int row_a = tid >> 2, ch = tid & 3;
#pragma unroll
        for (int t = 0; t < 2; t++) {
#pragma unroll
            for (int i = 0; i < 2; i++) {
                const int f = i * 256 + tid;               // 0..511
                const int r = f >> 2, cc = f & 3;
                CP_ASYNC16(dst + t * ATILE + r * ROWB + cc * 16,
                           aS[t] + ((long)r << 10) + kc * 32 + cc * 8);
            }
        }
#pragma unroll
        for (int t = 0; t < 2; t++) {
            CP_ASYNC16(dst + 2 * ATILE + t * BTILE + row_a * ROWB + ch * 16,
                       bS[t] + ((long)row_a << 10) + kc * 32 + ch * 8);
        }
    };

    issue(0, 0); CP_COMMIT();
    issue(1, 1); CP_COMMIT();
    issue(2, 2); CP_COMMIT();

    for (int c = 0; c < 32; c++) {
        const int p = c - (c / 3) * 3;          // c % 3
        CP_WAIT2();
        __syncthreads();

        const u32 base = sb + (u32)p * STAGE;
#pragma unroll
        for (int ks = 0; ks < 2; ks++) {
            u32 ah[4][4], al[4][4];
#pragma unroll
            for (int mt = 0; mt < 4; mt++) {
                const u32 a = base + aoff + mt * (16 * ROWB) + ks * 32;
                ldsm_x4(ah[mt][0], ah[mt][1], ah[mt][2], ah[mt][3], a);
                ldsm_x4(al[mt][0], al[mt][1], al[mt][2], al[mt][3], a + ATILE);
            }
            u32 bh0, bh1, bh2, bh3, bl0, bl1, bl2, bl3;
            ldsm_x4(bh0, bh1, bh2, bh3, base + 2 * ATILE + boff + ks * 32);
            ldsm_x4(bl0, bl1, bl2, bl3, base + 2 * ATILE + BTILE + boff + ks * 32);

            // sweep 1: Ah * Bh  (8 independent chains)
#pragma unroll
            for (int mt = 0; mt < 4; mt++) {
                mma16816(acc[mt][0], ah[mt][0], ah[mt][1], ah[mt][2], ah[mt][3], bh0, bh1);
                mma16816(acc[mt][1], ah[mt][0], ah[mt][1], ah[mt][2], ah[mt][3], bh2, bh3);
            }
            // sweep 2: Al * Bh
#pragma unroll
            for (int mt = 0; mt < 4; mt++) {
                mma16816(acc[mt][0], al[mt][0], al[mt][1], al[mt][2], al[mt][3], bh0, bh1);
                mma16816(acc[mt][1], al[mt][0], al[mt][1], al[mt][2], al[mt][3], bh2, bh3);
            }
            // sweep 3: Ah * Bl
#pragma unroll
            for (int mt = 0; mt < 4; mt++) {
                mma16816(acc[mt][0], ah[mt][0], ah[mt][1], ah[mt][2], ah[mt][3], bl0, bl1);
                mma16816(acc[mt][1], ah[mt][0], ah[mt][1], ah[mt][2], ah[mt][3], bl2, bl3);
            }
        }
        __syncthreads();
        if (c + 3 < 32) issue(c + 3, p);
        CP_COMMIT();
    }

    // epilogue
#pragma unroll
    for (int mt = 0; mt < 4; mt++) {
#pragma unroll
        for (int nt = 0; nt < 2; nt++) {
            const int m = m0 + warp_m * 64 + mt * 16 + (lane >> 2);
            const int n = n0 + warp_n * 16 + nt * 8 + (lane & 3) * 2;
            const float bx = bias[n], by = bias[n + 1];
#pragma unroll
            for (int half = 0; half < 2; half++) {
                const int mm = m + half * 8;
                const float vx = acc[mt][nt][half * 2 + 0] + bx;
                const float vy = acc[mt][nt][half * 2 + 1] + by;
                if (MODE == 1) {
                    *(float2*)&out[(long)mm * D_MODEL + n] = make_float2(vx, vy);
                } else {
                    const int b = mm >> 11, s = mm & 2047;
                    const int hd = n >> 6, dk = n & 63;
                    const long o = (((long)(b * NHEAD + hd) * S_LEN + s) << 6) + dk;
                    const u32 hh = cvt2bf(vx, vy);
                    const u32 ll = resid2(hh, vx, vy);
                    *(u32*)&outh[o] = hh;
                    *(u32*)&outl[o] = ll;
                }
            }
        }
    }
}

__global__ __launch_bounds__(256, 2) void qk_gemm_tc(const float* __restrict__ bq,
                                                     const float* __restrict__ bk)
{
    if (blockIdx.z == 0)
        tc_gemm_body<0>(g_Ah, g_Al, g_WhT[0], g_WlT[0], bq, nullptr, g_Qh, g_Ql);
    else
        tc_gemm_body<0>(g_Ah, g_Al, g_WhT[1], g_WlT[1], bk, nullptr, g_Kh, g_Kl);
}

__global__ __launch_bounds__(256, 2) void out_gemm_tc(const float* __restrict__ b0,
                                                      float* __restrict__ out)
{
    tc_gemm_body<1>(g_Ah, g_Al, g_WhT[2], g_WlT[2], b0, out, nullptr, nullptr);
}

// ---------------------------------------------------------------------------
// Flash attention on mma.sync, causal, V = Q.
// S-phase: pass-major sweeps, 16 independent chains, depth-2 ldsm prefetch.
// PV-phase: pass-major, 8 independent chains.
// Softmax in log2 domain (ex2.approx).
// ---------------------------------------------------------------------------
#define PITCH   144
#define TILE_B  (128 * PITCH)
#define OFF_KV0 (2 * TILE_B)
#define KV_SZ   (4 * TILE_B)
#define AT_SMEM (OFF_KV0 + 2 * KV_SZ)

#define SCALE_LOG2 0.18033688011112043f   // (1/8) * log2(e)

__global__ __launch_bounds__(256, 1) void attn_tc()
{
    extern __shared__ char smc[];
    const u32 sb = smem_u32(smc);
    const int tid  = threadIdx.x;
    const int lane = tid & 31;
    const int w    = tid >> 5;
    const int qi = (int)gridDim.x - 1 - (int)blockIdx.x;
    const int bh = blockIdx.y;

    const int lrow = lane & 15;
    const int lch  = lane >> 4;
    const int rlo  = w * 16 + (lane >> 2);
    const int rhi  = rlo + 8;

    {
        const long qb = ((long)bh * S_LEN + (long)qi * 128) * DKH;
#pragma unroll
        for (int i = 0; i < 8; i++) {
            const int t = i >> 2;
            const int idx = (i & 3) * 256 + tid;
            const int r = idx >> 3, c = idx & 7;
            const __nv_bfloat16* src = (t == 0 ? g_Qh : g_Ql) + qb + r * 64 + c * 8;
            CP_ASYNC16(sb + t * TILE_B + r * PITCH + c * 16, src);
        }
        const long kb = ((long)bh * S_LEN) * DKH;
#pragma unroll
        for (int i = 0; i < 16; i++) {
            const int t = i >> 2;
            const int idx = (i & 3) * 256 + tid;
            const int r = idx >> 3, c = idx & 7;
            const __nv_bfloat16* src =
                (t == 0 ? g_Kh : t == 1 ? g_Kl : t == 2 ? g_Qh : g_Ql) + kb + r * 64 + c * 8;
            CP_ASYNC16(sb + OFF_KV0 + t * TILE_B + r * PITCH + c * 16, src);
        }
        CP_COMMIT();
    }

    u32 aQh[4][4], aQl[4][4];
    float o_[8][4] = {};
    float mst0 = -1e30f, mst1 = -1e30f;
    float lst0 = 0.0f, lst1 = 0.0f;

    for (int j = 0; j <= qi; j++) {
        CP_WAIT0();
        __syncthreads();
        const u32 buf = sb + OFF_KV0 + (u32)(j & 1) * KV_SZ;

        if (j == 0) {
#pragma unroll
            for (int s = 0; s < 4; s++) {
                const u32 a = (u32)((w * 16 + lrow) * PITCH + s * 32 + lch * 16);
                ldsm_x4(aQh[s][0], aQh[s][1], aQh[s][2], aQh[s][3], sb + a);
                ldsm_x4(aQl[s][0], aQl[s][1], aQl[s][2], aQl[s][3], sb + TILE_B + a);
            }
        }
        if (j < qi) {
            const long kb = ((long)bh * S_LEN + (long)(j + 1) * 128) * DKH;
            const u32 nbuf = sb + OFF_KV0 + (u32)((j + 1) & 1) * KV_SZ;
#pragma unroll
            for (int i = 0; i < 16; i++) {
                const int t = i >> 2;
                const int idx = (i & 3) * 256 + tid;
                const int r = idx >> 3, c = idx & 7;
                const __nv_bfloat16* src =
                    (t == 0 ? g_Kh : t == 1 ? g_Kl : t == 2 ? g_Qh : g_Ql) + kb + r * 64 + c * 8;
                CP_ASYNC16(nbuf + t * TILE_B + r * PITCH + c * 16, src);
            }
            CP_COMMIT();
        }

        // ---- S = Q K^T : per k-step, 3 pass-major sweeps over 16 chains ----
        float s_[16][4] = {};
        const u32 bbase = buf + (u32)(lrow * PITCH + lch * 16);

        auto s_sweep = [&](const u32* A0, u32 tb) {
            u32 bb[3][4];
            ldsm_x4(bb[0][0], bb[0][1], bb[0][2], bb[0][3], tb);
            ldsm_x4(bb[1][0], bb[1][1], bb[1][2], bb[1][3], tb + 16 * PITCH);
#pragma unroll
            for (int nc = 0; nc < 8; nc++) {
                const int cur = nc % 3;
                if (nc < 6) {
                    const int nxt = (nc + 2) % 3;
                    ldsm_x4(bb[nxt][0], bb[nxt][1], bb[nxt][2], bb[nxt][3],
                            tb + (nc + 2) * (16 * PITCH));
                }
                mma16816(s_[2 * nc],     A0[0], A0[1], A0[2], A0[3], bb[cur][0], bb[cur][2]);
                mma16816(s_[2 * nc + 1], A0[0], A0[1], A0[2], A0[3], bb[cur][1], bb[cur][3]);
            }
        };

#pragma unroll
        for (int ks = 0; ks < 4; ks++) {
            const u32 tb = bbase + ks * 32;
            s_sweep(&aQh[ks][0], tb);            // Qh * Kh
            s_sweep(&aQl[ks][0], tb);            // Ql * Kh
            s_sweep(&aQh[ks][0], tb + TILE_B);   // Qh * Kl
        }

        // ---- online softmax (log2 domain) ----
        float rmx0 = -1e30f, rmx1 = -1e30f;
#pragma unroll
        for (int nt = 0; nt < 16; nt++) {
#pragma unroll
            for (int q = 0; q < 4; q++) s_[nt][q] *= SCALE_LOG2;
            if (j == qi) {
                const int c0 = nt * 8 + (lane & 3) * 2;
                if (c0 > rlo)     s_[nt][0] = -1e30f;
                if (c0 + 1 > rlo) s_[nt][1] = -1e30f;
                if (c0 > rhi)     s_[nt][2] = -1e30f;
                if (c0 + 1 > rhi) s_[nt][3] = -1e30f;
            }
            rmx0 = fmaxf(rmx0, fmaxf(s_[nt][0], s_[nt][1]));
            rmx1 = fmaxf(rmx1, fmaxf(s_[nt][2], s_[nt][3]));
        }
        rmx0 = fmaxf(rmx0, __shfl_xor_sync(0xffffffffu, rmx0, 1));
        rmx0 = fmaxf(rmx0, __shfl_xor_sync(0xffffffffu, rmx0, 2));
        rmx1 = fmaxf(rmx1, __shfl_xor_sync(0xffffffffu, rmx1, 1));
        rmx1 = fmaxf(rmx1, __shfl_xor_sync(0xffffffffu, rmx1, 2));
        const float mn0 = fmaxf(mst0, rmx0);
        const float mn1 = fmaxf(mst1, rmx1);
        const float al0 = ex2(mst0 - mn0);
        const float al1 = ex2(mst1 - mn1);
        float sum0 = 0.0f, sum1 = 0.0f;
#pragma unroll
        for (int nt = 0; nt < 16; nt++) {
            s_[nt][0] = ex2(s_[nt][0] - mn0);
            s_[nt][1] = ex2(s_[nt][1] - mn0);
            s_[nt][2] = ex2(s_[nt][2] - mn1);
            s_[nt][3] = ex2(s_[nt][3] - mn1);
            sum0 += s_[nt][0] + s_[nt][1];
            sum1 += s_[nt][2] + s_[nt][3];
        }
        sum0 += __shfl_xor_sync(0xffffffffu, sum0, 1);
        sum0 += __shfl_xor_sync(0xffffffffu, sum0, 2);
        sum1 += __shfl_xor_sync(0xffffffffu, sum1, 1);
        sum1 += __shfl_xor_sync(0xffffffffu, sum1, 2);
        lst0 = lst0 * al0 + sum0;
        lst1 = lst1 * al1 + sum1;
        mst0 = mn0;
        mst1 = mn1;
#pragma unroll
        for (int nt = 0; nt < 8; nt++) {
            o_[nt][0] *= al0; o_[nt][1] *= al0;
            o_[nt][2] *= al1; o_[nt][3] *= al1;
        }

        // ---- O += P V : pass-major, 8 independent chains ----
        const u32 vh_b = buf + 2 * TILE_B;
#pragma unroll
        for (int s = 0; s < 8; s++) {
            u32 ah[4], al_[4];
            ah[0] = cvt2bf(s_[2 * s][0], s_[2 * s][1]);
            ah[1] = cvt2bf(s_[2 * s][2], s_[2 * s][3]);
            ah[2] = cvt2bf(s_[2 * s + 1][0], s_[2 * s + 1][1]);
            ah[3] = cvt2bf(s_[2 * s + 1][2], s_[2 * s + 1][3]);
            al_[0] = resid2(ah[0], s_[2 * s][0], s_[2 * s][1]);
            al_[1] = resid2(ah[1], s_[2 * s][2], s_[2 * s][3]);
            al_[2] = resid2(ah[2], s_[2 * s + 1][0], s_[2 * s + 1][1]);
            al_[3] = resid2(ah[3], s_[2 * s + 1][2], s_[2 * s + 1][3]);

            u32 vh_[8][2], vl_[8][2];
#pragma unroll
            for (int tp = 0; tp < 4; tp++) {
                const u32 a = vh_b + (u32)((s * 16 + lrow) * PITCH + (tp * 2 + lch) * 16);
                u32 r0, r1, r2, r3;
                ldsm_x4t(r0, r1, r2, r3, a);
                vh_[2 * tp][0] = r0; vh_[2 * tp][1] = r1;
                vh_[2 * tp + 1][0] = r2; vh_[2 * tp + 1][1] = r3;
                ldsm_x4t(r0, r1, r2, r3, a + TILE_B);
                vl_[2 * tp][0] = r0; vl_[2 * tp][1] = r1;
                vl_[2 * tp + 1][0] = r2; vl_[2 * tp + 1][1] = r3;
            }
            // sweep 1: Ph * Vh
#pragma unroll
            for (int nt = 0; nt < 8; nt++)
                mma16816(o_[nt], ah[0], ah[1], ah[2], ah[3], vh_[nt][0], vh_[nt][1]);
            // sweep 2: Ph * Vl
#pragma unroll
            for (int nt = 0; nt < 8; nt++)
                mma16816(o_[nt], ah[0], ah[1], ah[2], ah[3], vl_[nt][0], vl_[nt][1]);
            // sweep 3: Pl * Vh
#pragma unroll
            for (int nt = 0; nt < 8; nt++)
                mma16816(o_[nt], al_[0], al_[1], al_[2], al_[3], vh_[nt][0], vh_[nt][1]);
        }
    }

    const int bat = bh >> 4, head = bh & 15;
    const float i0 = 1.0f / lst0;
    const float i1 = 1.0f / lst1;
    const int row0 = qi * 128 + rlo;
#pragma unroll
    for (int nt = 0; nt < 8; nt++) {
        const int d = head * 64 + nt * 8 + (lane & 3) * 2;
        {
            const float x = o_[nt][0] * i0, y = o_[nt][1] * i0;
            const u32 hh = cvt2bf(x, y), ll = resid2(hh, x, y);
            const long a = ((long)(bat * S_LEN + row0) << 10) + d;
            *(u32*)&g_Ah[a] = hh;
            *(u32*)&g_Al[a] = ll;
        }
        {
            const float x = o_[nt][2] * i1, y = o_[nt][3] * i1;
            const u32 hh = cvt2bf(x, y), ll = resid2(hh, x, y);
            const long a = ((long)(bat * S_LEN + row0 + 8) << 10) + d;
            *(u32*)&g_Ah[a] = hh;
            *(u32*)&g_Al[a] = ll;
        }
    }
}

// ---------------------------------------------------------------------------
extern "C" void kernel_launch(void* const* d_in, const int* in_sizes, int n_in,
                              void* d_out, int out_size)
{
    const float* x  = (const float*)d_in[0];
    const float* Wq = (const float*)d_in[1];
    const float* bq = (const float*)d_in[2];
    const float* Wk = (const float*)d_in[3];
    const float* bk = (const float*)d_in[4];
    const float* W0 = (const float*)d_in[5];
    const float* b0 = (const float*)d_in[6];
    float* out = (float*)d_out;

    __nv_bfloat16 *dAh, *dAl;
    cudaGetSymbolAddress((void**)&dAh, g_Ah);
    cudaGetSymbolAddress((void**)&dAl, g_Al);

    cudaFuncSetAttribute(attn_tc, cudaFuncAttributeMaxDynamicSharedMemorySize, AT_SMEM);
    cudaFuncSetAttribute(qk_gemm_tc, cudaFuncAttributeMaxDynamicSharedMemorySize, GSMEM);
    cudaFuncSetAttribute(out_gemm_tc, cudaFuncAttributeMaxDynamicSharedMemorySize, GSMEM);

    // 1) decompose x and all weights
    decomp_A<<<M_TOK * D_MODEL / 1024, 256>>>(x, dAh, dAl);
    dim3 wt_grid(32, 32, 3);
    decomp_WT3<<<wt_grid, 256>>>(Wq, Wk, W0);

    // 2) Q & K projections -> bf16 hi/lo head layout
    dim3 qk_grid(D_MODEL / 64, M_TOK / 128, 2);    // (16, 32, 2)
    qk_gemm_tc<<<qk_grid, 256, GSMEM>>>(bq, bk);

    // 3) attention (tensor cores) -> g_Ah/g_Al
    dim3 attn_grid(S_LEN / 128, BATCH * NHEAD);     // (16, 32)
    attn_tc<<<attn_grid, 256, AT_SMEM>>>();

    // 4) output projection
    dim3 o_grid(D_MODEL / 64, M_TOK / 128);         // (16, 32)
    out_gemm_tc<<<o_grid, 256, GSMEM>>>(b0, out);
}

// round 9
// speedup vs baseline: 2.9454x; 1.0224x over previous
#include <cuda_runtime.h>
#include <cuda_bf16.h>

#define S_LEN   2048
#define D_MODEL 1024
#define NHEAD   16
#define DKH     64
#define BATCH   2
#define M_TOK   (BATCH * S_LEN)   // 4096

typedef unsigned long long u64;
typedef unsigned int u32;

// ------------------------------- scratch -----------------------------------
__device__ __nv_bfloat16 g_Qh[BATCH * NHEAD * S_LEN * DKH];  // [B,H,S,DK] hi
__device__ __nv_bfloat16 g_Ql[BATCH * NHEAD * S_LEN * DKH];  // lo
__device__ __nv_bfloat16 g_Kh[BATCH * NHEAD * S_LEN * DKH];
__device__ __nv_bfloat16 g_Kl[BATCH * NHEAD * S_LEN * DKH];
__device__ __nv_bfloat16 g_Ah[M_TOK * D_MODEL];              // A hi (x, then att)
__device__ __nv_bfloat16 g_Al[M_TOK * D_MODEL];              // A lo
__device__ __nv_bfloat16 g_WhT[3][D_MODEL * D_MODEL];        // W^T hi: q,k,o
__device__ __nv_bfloat16 g_WlT[3][D_MODEL * D_MODEL];        // W^T lo

// --------------------------- small helpers ---------------------------------
__device__ __forceinline__ u32 smem_u32(const void* p) {
    u32 a; asm("{ .reg .u64 t; cvta.to.shared.u64 t, %1; cvt.u32.u64 %0, t; }" : "=r"(a) : "l"(p));
    return a;
}

#define CP_ASYNC16(dst, src) \
    asm volatile("cp.async.cg.shared.global [%0], [%1], 16;" :: "r"(dst), "l"(src))
#define CP_COMMIT()  asm volatile("cp.async.commit_group;" ::: "memory")
#define CP_WAIT2()   asm volatile("cp.async.wait_group 2;" ::: "memory")
#define CP_WAIT0()   asm volatile("cp.async.wait_group 0;" ::: "memory")

__device__ __forceinline__ void ldsm_x4(u32& r0, u32& r1, u32& r2, u32& r3, u32 addr) {
    asm volatile("ldmatrix.sync.aligned.m8n8.x4.shared.b16 {%0,%1,%2,%3}, [%4];"
                 : "=r"(r0), "=r"(r1), "=r"(r2), "=r"(r3) : "r"(addr));
}
__device__ __forceinline__ void ldsm_x4t(u32& r0, u32& r1, u32& r2, u32& r3, u32 addr) {
    asm volatile("ldmatrix.sync.aligned.m8n8.x4.trans.shared.b16 {%0,%1,%2,%3}, [%4];"
                 : "=r"(r0), "=r"(r1), "=r"(r2), "=r"(r3) : "r"(addr));
}

__device__ __forceinline__ void mma16816(float* d, u32 a0, u32 a1, u32 a2, u32 a3,
                                         u32 b0, u32 b1) {
    asm volatile("mma.sync.aligned.m16n8k16.row.col.f32.bf16.bf16.f32 "
                 "{%0,%1,%2,%3}, {%4,%5,%6,%7}, {%8,%9}, {%0,%1,%2,%3};"
                 : "+f"(d[0]), "+f"(d[1]), "+f"(d[2]), "+f"(d[3])
                 : "r"(a0), "r"(a1), "r"(a2), "r"(a3), "r"(b0), "r"(b1));
}

__device__ __forceinline__ float ex2(float x) {
    float y; asm("ex2.approx.f32 %0, %1;" : "=f"(y) : "f"(x)); return y;
}

__device__ __forceinline__ u32 cvt2bf(float x, float y) {
    __nv_bfloat162 t = __floats2bfloat162_rn(x, y);
    return *reinterpret_cast<u32*>(&t);
}
__device__ __forceinline__ u32 resid2(u32 h, float x, float y) {
    float hx = __uint_as_float(h << 16);
    float hy = __uint_as_float(h & 0xffff0000u);
    return cvt2bf(x - hx, y - hy);
}
__device__ __forceinline__ u32 pack_bf2(__nv_bfloat16 a, __nv_bfloat16 b) {
    __nv_bfloat162 p(a, b);
    return *reinterpret_cast<u32*>(&p);
}

// ------------------------- fp32 -> bf16 hi/lo split -------------------------
__global__ __launch_bounds__(256) void decomp_A(const float* __restrict__ src,
                                                __nv_bfloat16* __restrict__ hi,
                                                __nv_bfloat16* __restrict__ lo)
{
    const int i = (blockIdx.x * 256 + threadIdx.x) * 4;
    float4 v = *(const float4*)(src + i);
    __nv_bfloat16 h0 = __float2bfloat16_rn(v.x);
    __nv_bfloat16 h1 = __float2bfloat16_rn(v.y);
    __nv_bfloat16 h2 = __float2bfloat16_rn(v.z);
    __nv_bfloat16 h3 = __float2bfloat16_rn(v.w);
    __nv_bfloat16 l0 = __float2bfloat16_rn(v.x - __bfloat162float(h0));
    __nv_bfloat16 l1 = __float2bfloat16_rn(v.y - __bfloat162float(h1));
    __nv_bfloat16 l2 = __float2bfloat16_rn(v.z - __bfloat162float(h2));
    __nv_bfloat16 l3 = __float2bfloat16_rn(v.w - __bfloat162float(h3));
    *(uint2*)(hi + i) = make_uint2(pack_bf2(h0, h1), pack_bf2(h2, h3));
    *(uint2*)(lo + i) = make_uint2(pack_bf2(l0, l1), pack_bf2(l2, l3));
}

// all three W [K,N] fp32 -> W^T hi/lo bf16, one launch (z = which matrix)
__global__ __launch_bounds__(256) void decomp_WT3(const float* __restrict__ Wq,
                                                  const float* __restrict__ Wk,
                                                  const float* __restrict__ W0)
{
    const int z = blockIdx.z;
    const float* W = (z == 0) ? Wq : (z == 1) ? Wk : W0;
    __nv_bfloat16* hiT = g_WhT[z];
    __nv_bfloat16* loT = g_WlT[z];

    __shared__ float t[32][33];
    const int tx = threadIdx.x & 31, ty = threadIdx.x >> 5;   // (32, 8)
    const int n0 = blockIdx.x * 32, k0 = blockIdx.y * 32;
#pragma unroll
    for (int i = 0; i < 4; i++)
        t[ty + 8 * i][tx] = W[(k0 + ty + 8 * i) * D_MODEL + n0 + tx];
    __syncthreads();
#pragma unroll
    for (int i = 0; i < 4; i++) {
        float v = t[tx][ty + 8 * i];
        __nv_bfloat16 h = __float2bfloat16_rn(v);
        __nv_bfloat16 l = __float2bfloat16_rn(v - __bfloat162float(h));
        const long o = (long)(n0 + ty + 8 * i) * D_MODEL + k0 + tx;
        hiT[o] = h;
        loT[o] = l;
    }
}

// ---------------------------------------------------------------------------
// Fused 3-pass split-bf16 GEMM: C[4096,1024] = A @ W + bias
// BM=128, BN=64, BK=32, 256 threads (8 warps, 4x2 layout), warp tile 32x32.
// 3-stage cp.async, 2 CTAs/SM. A-tile ldsm redundancy 2x (was 4x).
// ---------------------------------------------------------------------------
#define ROWB  80                       // 64 data bytes + 16 pad
#define ATILE (128 * ROWB)             // 10240
#define BTILE (64 * ROWB)              // 5120
#define STAGE (2 * ATILE + 2 * BTILE)  // 30720 : [Ah][Al][Bh][Bl]
#define GSMEM (3 * STAGE)              // 92160

template <int MODE>
__device__ __forceinline__ void tc_gemm_body(const __nv_bfloat16* __restrict__ Ah,
                                             const __nv_bfloat16* __restrict__ Al,
                                             const __nv_bfloat16* __restrict__ BhT,
                                             const __nv_bfloat16* __restrict__ BlT,
                                             const float* __restrict__ bias,
                                             float* __restrict__ out,
                                             __nv_bfloat16* __restrict__ outh,
                                             __nv_bfloat16* __restrict__ outl)
{
    extern __shared__ __align__(16) char smg[];
    const u32 sb = smem_u32(smg);

    const int tid = threadIdx.x;
    const int wid = tid >> 5;
    const int lane = tid & 31;
    const int warp_m = wid & 3;           // 0..3  (32 rows each)
    const int warp_n = wid >> 2;          // 0..1  (32 cols each)
    const int m0 = blockIdx.y * 128;
    const int n0 = blockIdx.x * 64;

    const int a_row = (lane & 15);
    const int a_kh  = (lane >> 4);
    const u32 aoff = (u32)((warp_m * 32 + a_row) * ROWB + a_kh * 16);
    const int b_row = (lane & 7) + ((lane >> 4) << 3);
    const int b_kh  = (lane >> 3) & 1;
    const u32 boff = (u32)((warp_n * 32 + b_row) * ROWB + b_kh * 16);

    float acc[2][4][4] = {};

    const __nv_bfloat16* aS[2] = { Ah + ((long)m0 << 10), Al + ((long)m0 << 10) };
    const __nv_bfloat16* bS[2] = { BhT + ((long)n0 << 10), BlT + ((long)n0 << 10) };

    auto issue = [&](int kc, int p) {
        const u32 dst = sb + (u32)p * STAGE;
        const int row_a = tid >> 2, ch = tid & 3;
#pragma unroll
        for (int t = 0; t < 2; t++) {
#pragma unroll
            for (int i = 0; i < 2; i++) {
                const int f = i * 256 + tid;               // 0..511
                const int r = f >> 2, cc = f & 3;
                CP_ASYNC16(dst + t * ATILE + r * ROWB + cc * 16,
                           aS[t] + ((long)r << 10) + kc * 32 + cc * 8);
            }
        }
#pragma unroll
        for (int t = 0; t < 2; t++) {
            CP_ASYNC16(dst + 2 * ATILE + t * BTILE + row_a * ROWB + ch * 16,
                       bS[t] + ((long)row_a << 10) + kc * 32 + ch * 8);
        }
    };

    issue(0, 0); CP_COMMIT();
    issue(1, 1); CP_COMMIT();
    issue(2, 2); CP_COMMIT();

    for (int c = 0; c < 32; c++) {
        const int p = c - (c / 3) * 3;          // c % 3
        CP_WAIT2();
        __syncthreads();

        const u32 base = sb + (u32)p * STAGE;
#pragma unroll
        for (int ks = 0; ks < 2; ks++) {
            u32 ah[2][4], al[2][4];
#pragma unroll
            for (int mt = 0; mt < 2; mt++) {
                const u32 a = base + aoff + mt * (16 * ROWB) + ks * 32;
                ldsm_x4(ah[mt][0], ah[mt][1], ah[mt][2], ah[mt][3], a);
                ldsm_x4(al[mt][0], al[mt][1], al[mt][2], al[mt][3], a + ATILE);
            }
            u32 bh[4][2], bl[4][2];
#pragma unroll
            for (int nt2 = 0; nt2 < 2; nt2++) {
                u32 r0, r1, r2, r3;
                ldsm_x4(r0, r1, r2, r3,
                        base + 2 * ATILE + boff + nt2 * (16 * ROWB) + ks * 32);
                bh[nt2 * 2 + 0][0] = r0; bh[nt2 * 2 + 0][1] = r1;
                bh[nt2 * 2 + 1][0] = r2; bh[nt2 * 2 + 1][1] = r3;
                ldsm_x4(r0, r1, r2, r3,
                        base + 2 * ATILE + BTILE + boff + nt2 * (16 * ROWB) + ks * 32);
                bl[nt2 * 2 + 0][0] = r0; bl[nt2 * 2 + 0][1] = r1;
                bl[nt2 * 2 + 1][0] = r2; bl[nt2 * 2 + 1][1] = r3;
            }
            // sweep 1: Ah * Bh  (8 independent chains)
#pragma unroll
            for (int mt = 0; mt < 2; mt++)
#pragma unroll
                for (int nt = 0; nt < 4; nt++)
                    mma16816(acc[mt][nt], ah[mt][0], ah[mt][1], ah[mt][2], ah[mt][3],
                             bh[nt][0], bh[nt][1]);
            // sweep 2: Al * Bh
#pragma unroll
            for (int mt = 0; mt < 2; mt++)
#pragma unroll
                for (int nt = 0; nt < 4; nt++)
                    mma16816(acc[mt][nt], al[mt][0], al[mt][1], al[mt][2], al[mt][3],
                             bh[nt][0], bh[nt][1]);
            // sweep 3: Ah * Bl
#pragma unroll
            for (int mt = 0; mt < 2; mt++)
#pragma unroll
                for (int nt = 0; nt < 4; nt++)
                    mma16816(acc[mt][nt], ah[mt][0], ah[mt][1], ah[mt][2], ah[mt][3],
                             bl[nt][0], bl[nt][1]);
        }
        __syncthreads();
        if (c + 3 < 32) issue(c + 3, p);
        CP_COMMIT();
    }

    // epilogue
#pragma unroll
    for (int mt = 0; mt < 2; mt++) {
#pragma unroll
        for (int nt = 0; nt < 4; nt++) {
            const int m = m0 + warp_m * 32 + mt * 16 + (lane >> 2);
            const int n = n0 + warp_n * 32 + nt * 8 + (lane & 3) * 2;
            const float bx = bias[n], by = bias[n + 1];
#pragma unroll
            for (int half = 0; half < 2; half++) {
                const int mm = m + half * 8;
                const float vx = acc[mt][nt][half * 2 + 0] + bx;
                const float vy = acc[mt][nt][half * 2 + 1] + by;
                if (MODE == 1) {
                    *(float2*)&out[(long)mm * D_MODEL + n] = make_float2(vx, vy);
                } else {
                    const int b = mm >> 11, s = mm & 2047;
                    const int hd = n >> 6, dk = n & 63;
                    const long o = (((long)(b * NHEAD + hd) * S_LEN + s) << 6) + dk;
                    const u32 hh = cvt2bf(vx, vy);
                    const u32 ll = resid2(hh, vx, vy);
                    *(u32*)&outh[o] = hh;
                    *(u32*)&outl[o] = ll;
                }
            }
        }
    }
}

__global__ __launch_bounds__(256, 2) void qk_gemm_tc(const float* __restrict__ bq,
                                                     const float* __restrict__ bk)
{
    if (blockIdx.z == 0)
        tc_gemm_body<0>(g_Ah, g_Al, g_WhT[0], g_WlT[0], bq, nullptr, g_Qh, g_Ql);
    else
        tc_gemm_body<0>(g_Ah, g_Al, g_WhT[1], g_WlT[1], bk, nullptr, g_Kh, g_Kl);
}

__global__ __launch_bounds__(256, 2) void out_gemm_tc(const float* __restrict__ b0,
                                                      float* __restrict__ out)
{
    tc_gemm_body<1>(g_Ah, g_Al, g_WhT[2], g_WlT[2], b0, out, nullptr, nullptr);
}

// ---------------------------------------------------------------------------
// Flash attention on mma.sync, causal, V = Q.
// S-phase FUSED: per (ks,nc) load Kh+Kl fragments once, issue all 3 passes.
// PV-phase: V frags loaded once per s-iter, 3 register sweeps (unchanged).
// ---------------------------------------------------------------------------
#define PITCH   144
#define TILE_B  (128 * PITCH)
#define OFF_KV0 (2 * TILE_B)
#define KV_SZ   (4 * TILE_B)
#define AT_SMEM (OFF_KV0 + 2 * KV_SZ)

#define SCALE_LOG2 0.18033688011112043f   // (1/8) * log2(e)

__global__ __launch_bounds__(256, 1) void attn_tc()
{
    extern __shared__ char smc[];
    const u32 sb = smem_u32(smc);
    const int tid  = threadIdx.x;
    const int lane = tid & 31;
    const int w    = tid >> 5;
    const int qi = (int)gridDim.x - 1 - (int)blockIdx.x;
    const int bh = blockIdx.y;

    const int lrow = lane & 15;
    const int lch  = lane >> 4;
    const int rlo  = w * 16 + (lane >> 2);
    const int rhi  = rlo + 8;

    {
        const long qb = ((long)bh * S_LEN + (long)qi * 128) * DKH;
#pragma unroll
        for (int i = 0; i < 8; i++) {
            const int t = i >> 2;
            const int idx = (i & 3) * 256 + tid;
            const int r = idx >> 3, c = idx & 7;
            const __nv_bfloat16* src = (t == 0 ? g_Qh : g_Ql) + qb + r * 64 + c * 8;
            CP_ASYNC16(sb + t * TILE_B + r * PITCH + c * 16, src);
        }
        const long kb = ((long)bh * S_LEN) * DKH;
#pragma unroll
        for (int i = 0; i < 16; i++) {
            const int t = i >> 2;
            const int idx = (i & 3) * 256 + tid;
            const int r = idx >> 3, c = idx & 7;
            const __nv_bfloat16* src =
                (t == 0 ? g_Kh : t == 1 ? g_Kl : t == 2 ? g_Qh : g_Ql) + kb + r * 64 + c * 8;
            CP_ASYNC16(sb + OFF_KV0 + t * TILE_B + r * PITCH + c * 16, src);
        }
        CP_COMMIT();
    }

    u32 aQh[4][4], aQl[4][4];
    float o_[8][4] = {};
    float mst0 = -1e30f, mst1 = -1e30f;
    float lst0 = 0.0f, lst1 = 0.0f;

    for (int j = 0; j <= qi; j++) {
        CP_WAIT0();
        __syncthreads();
        const u32 buf = sb + OFF_KV0 + (u32)(j & 1) * KV_SZ;

        if (j == 0) {
#pragma unroll
            for (int s = 0; s < 4; s++) {
                const u32 a = (u32)((w * 16 + lrow) * PITCH + s * 32 + lch * 16);
                ldsm_x4(aQh[s][0], aQh[s][1], aQh[s][2], aQh[s][3], sb + a);
                ldsm_x4(aQl[s][0], aQl[s][1], aQl[s][2], aQl[s][3], sb + TILE_B + a);
            }
        }
        if (j < qi) {
            const long kb = ((long)bh * S_LEN + (long)(j + 1) * 128) * DKH;
            const u32 nbuf = sb + OFF_KV0 + (u32)((j + 1) & 1) * KV_SZ;
#pragma unroll
            for (int i = 0; i < 16; i++) {
                const int t = i >> 2;
                const int idx = (i & 3) * 256 + tid;
                const int r = idx >> 3, c = idx & 7;
                const __nv_bfloat16* src =
                    (t == 0 ? g_Kh : t == 1 ? g_Kl : t == 2 ? g_Qh : g_Ql) + kb + r * 64 + c * 8;
                CP_ASYNC16(nbuf + t * TILE_B + r * PITCH + c * 16, src);
            }
            CP_COMMIT();
        }

        // ---- S = Q K^T : fused 3-pass, Kh/Kl fragments loaded ONCE ----
        float s_[16][4] = {};
        const u32 bbase = buf + (u32)(lrow * PITCH + lch * 16);

#pragma unroll
        for (int ks = 0; ks < 4; ks++) {
            const u32 tb = bbase + ks * 32;
#pragma unroll
            for (int nc = 0; nc < 8; nc++) {
                u32 h0, h1, h2, h3, l0, l1, l2, l3;
                ldsm_x4(h0, h1, h2, h3, tb + nc * (16 * PITCH));
                ldsm_x4(l0, l1, l2, l3, tb + nc * (16 * PITCH) + TILE_B);
                mma16816(s_[2 * nc],     aQh[ks][0], aQh[ks][1], aQh[ks][2], aQh[ks][3], h0, h2);
                mma16816(s_[2 * nc + 1], aQh[ks][0], aQh[ks][1], aQh[ks][2], aQh[ks][3], h1, h3);
                mma16816(s_[2 * nc],     aQl[ks][0], aQl[ks][1], aQl[ks][2], aQl[ks][3], h0, h2);
                mma16816(s_[2 * nc + 1], aQl[ks][0], aQl[ks][1], aQl[ks][2], aQl[ks][3], h1, h3);
                mma16816(s_[2 * nc],     aQh[ks][0], aQh[ks][1], aQh[ks][2], aQh[ks][3], l0, l2);
                mma16816(s_[2 * nc + 1], aQh[ks][0], aQh[ks][1], aQh[ks][2], aQh[ks][3], l1, l3);
            }
        }

        // ---- online softmax (log2 domain) ----
        float rmx0 = -1e30f, rmx1 = -1e30f;
#pragma unroll
        for (int nt = 0; nt < 16; nt++) {
#pragma unroll
            for (int q = 0; q < 4; q++) s_[nt][q] *= SCALE_LOG2;
            if (j == qi) {
                const int c0 = nt * 8 + (lane & 3) * 2;
                if (c0 > rlo)     s_[nt][0] = -1e30f;
                if (c0 + 1 > rlo) s_[nt][1] = -1e30f;
                if (c0 > rhi)     s_[nt][2] = -1e30f;
                if (c0 + 1 > rhi) s_[nt][3] = -1e30f;
            }
            rmx0 = fmaxf(rmx0, fmaxf(s_[nt][0], s_[nt][1]));
            rmx1 = fmaxf(rmx1, fmaxf(s_[nt][2], s_[nt][3]));
        }
        rmx0 = fmaxf(rmx0, __shfl_xor_sync(0xffffffffu, rmx0, 1));
        rmx0 = fmaxf(rmx0, __shfl_xor_sync(0xffffffffu, rmx0, 2));
        rmx1 = fmaxf(rmx1, __shfl_xor_sync(0xffffffffu, rmx1, 1));
        rmx1 = fmaxf(rmx1, __shfl_xor_sync(0xffffffffu, rmx1, 2));
        const float mn0 = fmaxf(mst0, rmx0);
        const float mn1 = fmaxf(mst1, rmx1);
        const float al0 = ex2(mst0 - mn0);
        const float al1 = ex2(mst1 - mn1);
        float sum0 = 0.0f, sum1 = 0.0f;
#pragma unroll
        for (int nt = 0; nt < 16; nt++) {
            s_[nt][0] = ex2(s_[nt][0] - mn0);
            s_[nt][1] = ex2(s_[nt][1] - mn0);
            s_[nt][2] = ex2(s_[nt][2] - mn1);
            s_[nt][3] = ex2(s_[nt][3] - mn1);
            sum0 += s_[nt][0] + s_[nt][1];
            sum1 += s_[nt][2] + s_[nt][3];
        }
        sum0 += __shfl_xor_sync(0xffffffffu, sum0, 1);
        sum0 += __shfl_xor_sync(0xffffffffu, sum0, 2);
        sum1 += __shfl_xor_sync(0xffffffffu, sum1, 1);
        sum1 += __shfl_xor_sync(0xffffffffu, sum1, 2);
        lst0 = lst0 * al0 + sum0;
        lst1 = lst1 * al1 + sum1;
        mst0 = mn0;
        mst1 = mn1;
#pragma unroll
        for (int nt = 0; nt < 8; nt++) {
            o_[nt][0] *= al0; o_[nt][1] *= al0;
            o_[nt][2] *= al1; o_[nt][3] *= al1;
        }

        // ---- O += P V : V frags loaded once, 3 register sweeps ----
        const u32 vh_b = buf + 2 * TILE_B;
#pragma unroll
        for (int s = 0; s < 8; s++) {
            u32 ah[4], al_[4];
            ah[0] = cvt2bf(s_[2 * s][0], s_[2 * s][1]);
            ah[1] = cvt2bf(s_[2 * s][2], s_[2 * s][3]);
            ah[2] = cvt2bf(s_[2 * s + 1][0], s_[2 * s + 1][1]);
            ah[3] = cvt2bf(s_[2 * s + 1][2], s_[2 * s + 1][3]);
            al_[0] = resid2(ah[0], s_[2 * s][0], s_[2 * s][1]);
            al_[1] = resid2(ah[1], s_[2 * s][2], s_[2 * s][3]);
            al_[2] = resid2(ah[2], s_[2 * s + 1][0], s_[2 * s + 1][1]);
            al_[3] = resid2(ah[3], s_[2 * s + 1][2], s_[2 * s + 1][3]);

            u32 vh_[8][2], vl_[8][2];
#pragma unroll
            for (int tp = 0; tp < 4; tp++) {
                const u32 a = vh_b + (u32)((s * 16 + lrow) * PITCH + (tp * 2 + lch) * 16);
                u32 r0, r1, r2, r3;
                ldsm_x4t(r0, r1, r2, r3, a);
                vh_[2 * tp][0] = r0; vh_[2 * tp][1] = r1;
                vh_[2 * tp + 1][0] = r2; vh_[2 * tp + 1][1] = r3;
                ldsm_x4t(r0, r1, r2, r3, a + TILE_B);
                vl_[2 * tp][0] = r0; vl_[2 * tp][1] = r1;
                vl_[2 * tp + 1][0] = r2; vl_[2 * tp + 1][1] = r3;
            }
            // sweep 1: Ph * Vh
#pragma unroll
            for (int nt = 0; nt < 8; nt++)
                mma16816(o_[nt], ah[0], ah[1], ah[2], ah[3], vh_[nt][0], vh_[nt][1]);
            // sweep 2: Ph * Vl
#pragma unroll
            for (int nt = 0; nt < 8; nt++)
                mma16816(o_[nt], ah[0], ah[1], ah[2], ah[3], vl_[nt][0], vl_[nt][1]);
            // sweep 3: Pl * Vh
#pragma unroll
            for (int nt = 0; nt < 8; nt++)
                mma16816(o_[nt], al_[0], al_[1], al_[2], al_[3], vh_[nt][0], vh_[nt][1]);
        }
    }

    const int bat = bh >> 4, head = bh & 15;
    const float i0 = 1.0f / lst0;
    const float i1 = 1.0f / lst1;
    const int row0 = qi * 128 + rlo;
#pragma unroll
    for (int nt = 0; nt < 8; nt++) {
        const int d = head * 64 + nt * 8 + (lane & 3) * 2;
        {
            const float x = o_[nt][0] * i0, y = o_[nt][1] * i0;
            const u32 hh = cvt2bf(x, y), ll = resid2(hh, x, y);
            const long a = ((long)(bat * S_LEN + row0) << 10) + d;
            *(u32*)&g_Ah[a] = hh;
            *(u32*)&g_Al[a] = ll;
        }
        {
            const float x = o_[nt][2] * i1, y = o_[nt][3] * i1;
            const u32 hh = cvt2bf(x, y), ll = resid2(hh, x, y);
            const long a = ((long)(bat * S_LEN + row0 + 8) << 10) + d;
            *(u32*)&g_Ah[a] = hh;
            *(u32*)&g_Al[a] = ll;
        }
    }
}

// ---------------------------------------------------------------------------
extern "C" void kernel_launch(void* const* d_in, const int* in_sizes, int n_in,
                              void* d_out, int out_size)
{
    const float* x  = (const float*)d_in[0];
    const float* Wq = (const float*)d_in[1];
    const float* bq = (const float*)d_in[2];
    const float* Wk = (const float*)d_in[3];
    const float* bk = (const float*)d_in[4];
    const float* W0 = (const float*)d_in[5];
    const float* b0 = (const float*)d_in[6];
    float* out = (float*)d_out;

    __nv_bfloat16 *dAh, *dAl;
    cudaGetSymbolAddress((void**)&dAh, g_Ah);
    cudaGetSymbolAddress((void**)&dAl, g_Al);

    cudaFuncSetAttribute(attn_tc, cudaFuncAttributeMaxDynamicSharedMemorySize, AT_SMEM);
    cudaFuncSetAttribute(qk_gemm_tc, cudaFuncAttributeMaxDynamicSharedMemorySize, GSMEM);
    cudaFuncSetAttribute(out_gemm_tc, cudaFuncAttributeMaxDynamicSharedMemorySize, GSMEM);

    // 1) decompose x and all weights
    decomp_A<<<M_TOK * D_MODEL / 1024, 256>>>(x, dAh, dAl);
    dim3 wt_grid(32, 32, 3);
    decomp_WT3<<<wt_grid, 256>>>(Wq, Wk, W0);

    // 2) Q & K projections -> bf16 hi/lo head layout
    dim3 qk_grid(D_MODEL / 64, M_TOK / 128, 2);    // (16, 32, 2)
    qk_gemm_tc<<<qk_grid, 256, GSMEM>>>(bq, bk);

    // 3) attention (tensor cores) -> g_Ah/g_Al
    dim3 attn_grid(S_LEN / 128, BATCH * NHEAD);     // (16, 32)
    attn_tc<<<attn_grid, 256, AT_SMEM>>>();

    // 4) output projection
    dim3 o_grid(D_MODEL / 64, M_TOK / 128);         // (16, 32)
    out_gemm_tc<<<o_grid, 256, GSMEM>>>(b0, out);
}

// round 10
// speedup vs baseline: 3.5073x; 1.1908x over previous
#include <cuda_runtime.h>
#include <cuda_fp16.h>

#define S_LEN   2048
#define D_MODEL 1024
#define NHEAD   16
#define DKH     64
#define BATCH   2
#define M_TOK   (BATCH * S_LEN)   // 4096

typedef unsigned long long u64;
typedef unsigned int u32;

// ------------------------------- scratch -----------------------------------
__device__ __half g_Qh[BATCH * NHEAD * S_LEN * DKH];  // [B,H,S,DK] hi
__device__ __half g_Ql[BATCH * NHEAD * S_LEN * DKH];  // lo
__device__ __half g_Kh[BATCH * NHEAD * S_LEN * DKH];
__device__ __half g_Kl[BATCH * NHEAD * S_LEN * DKH];
__device__ __half g_Ah[M_TOK * D_MODEL];              // A hi (x, then att)
__device__ __half g_Al[M_TOK * D_MODEL];              // A lo
__device__ __half g_WT[3][D_MODEL * D_MODEL];         // W^T fp16 (single): q,k,o

// --------------------------- small helpers ---------------------------------
__device__ __forceinline__ u32 smem_u32(const void* p) {
    u32 a; asm("{ .reg .u64 t; cvta.to.shared.u64 t, %1; cvt.u32.u64 %0, t; }" : "=r"(a) : "l"(p));
    return a;
}

#define CP_ASYNC16(dst, src) \
    asm volatile("cp.async.cg.shared.global [%0], [%1], 16;" :: "r"(dst), "l"(src))
#define CP_COMMIT()  asm volatile("cp.async.commit_group;" ::: "memory")
#define CP_WAIT2()   asm volatile("cp.async.wait_group 2;" ::: "memory")
#define CP_WAIT0()   asm volatile("cp.async.wait_group 0;" ::: "memory")

__device__ __forceinline__ void ldsm_x4(u32& r0, u32& r1, u32& r2, u32& r3, u32 addr) {
    asm volatile("ldmatrix.sync.aligned.m8n8.x4.shared.b16 {%0,%1,%2,%3}, [%4];"
                 : "=r"(r0), "=r"(r1), "=r"(r2), "=r"(r3) : "r"(addr));
}
__device__ __forceinline__ void ldsm_x4t(u32& r0, u32& r1, u32& r2, u32& r3, u32 addr) {
    asm volatile("ldmatrix.sync.aligned.m8n8.x4.trans.shared.b16 {%0,%1,%2,%3}, [%4];"
                 : "=r"(r0), "=r"(r1), "=r"(r2), "=r"(r3) : "r"(addr));
}

__device__ __forceinline__ void mma16816(float* d, u32 a0, u32 a1, u32 a2, u32 a3,
                                         u32 b0, u32 b1) {
    asm volatile("mma.sync.aligned.m16n8k16.row.col.f32.f16.f16.f32 "
                 "{%0,%1,%2,%3}, {%4,%5,%6,%7}, {%8,%9}, {%0,%1,%2,%3};"
                 : "+f"(d[0]), "+f"(d[1]), "+f"(d[2]), "+f"(d[3])
                 : "r"(a0), "r"(a1), "r"(a2), "r"(a3), "r"(b0), "r"(b1));
}

__device__ __forceinline__ float ex2(float x) {
    float y; asm("ex2.approx.f32 %0, %1;" : "=f"(y) : "f"(x)); return y;
}

__device__ __forceinline__ u32 cvt2h(float x, float y) {
    __half2 t = __floats2half2_rn(x, y);
    return *reinterpret_cast<u32*>(&t);
}
__device__ __forceinline__ u32 resid2h(u32 h, float x, float y) {
    __half2 hh = *reinterpret_cast<__half2*>(&h);
    return cvt2h(x - __low2float(hh), y - __high2float(hh));
}

// ------------------------- fp32 -> fp16 hi/lo split -------------------------
__global__ __launch_bounds__(256) void decomp_A(const float* __restrict__ src,
                                                __half* __restrict__ hi,
                                                __half* __restrict__ lo)
{
    const int i = (blockIdx.x * 256 + threadIdx.x) * 4;
    float4 v = *(const float4*)(src + i);
    __half h0 = __float2half_rn(v.x);
    __half h1 = __float2half_rn(v.y);
    __half h2 = __float2half_rn(v.z);
    __half h3 = __float2half_rn(v.w);
    __half l0 = __float2half_rn(v.x - __half2float(h0));
    __half l1 = __float2half_rn(v.y - __half2float(h1));
    __half l2 = __float2half_rn(v.z - __half2float(h2));
    __half l3 = __float2half_rn(v.w - __half2float(h3));
    __half2 hA(h0, h1), hB(h2, h3), lA(l0, l1), lB(l2, l3);
    *(uint2*)(hi + i) = make_uint2(*(u32*)&hA, *(u32*)&hB);
    *(uint2*)(lo + i) = make_uint2(*(u32*)&lA, *(u32*)&lB);
}

// all three W [K,N] fp32 -> W^T fp16 (single precision piece), z = matrix id
__global__ __launch_bounds__(256) void decomp_WT3(const float* __restrict__ Wq,
                                                  const float* __restrict__ Wk,
                                                  const float* __restrict__ W0)
{
    const int z = blockIdx.z;
    const float* W = (z == 0) ? Wq : (z == 1) ? Wk : W0;
    __half* hiT = g_WT[z];

    __shared__ float t[32][33];
    const int tx = threadIdx.x & 31, ty = threadIdx.x >> 5;   // (32, 8)
    const int n0 = blockIdx.x * 32, k0 = blockIdx.y * 32;
#pragma unroll
    for (int i = 0; i < 4; i++)
        t[ty + 8 * i][tx] = W[(k0 + ty + 8 * i) * D_MODEL + n0 + tx];
    __syncthreads();
#pragma unroll
    for (int i = 0; i < 4; i++) {
        float v = t[tx][ty + 8 * i];
        hiT[(long)(n0 + ty + 8 * i) * D_MODEL + k0 + tx] = __float2half_rn(v);
    }
}

// ---------------------------------------------------------------------------
// 2-pass split-fp16 GEMM: C = (Ah + Al) @ Wf + bias   (W single fp16)
// BM=128, BN=64, BK=32, 256 threads (8 warps 4x2), warp tile 32x32.
// 3-stage cp.async, 2 CTAs/SM.
//   MODE 0: write fp16 hi/lo into head layout [B,H,S,DK]
//   MODE 1: write fp32 row-major [M,N]
// ---------------------------------------------------------------------------
#define ROWB  80                       // 64 data bytes + 16 pad
#define ATILE (128 * ROWB)             // 10240
#define BTILE (64 * ROWB)              // 5120
#define STAGE (2 * ATILE + BTILE)      // 25600 : [Ah][Al][Bh]
#define GSMEM (3 * STAGE)              // 76800

template <int MODE>
__device__ __forceinline__ void tc_gemm_body(const __half* __restrict__ Ah,
                                             const __half* __restrict__ Al,
                                             const __half* __restrict__ BT,
                                             const float* __restrict__ bias,
                                             float* __restrict__ out,
                                             __half* __restrict__ outh,
                                             __half* __restrict__ outl)
{
    extern __shared__ __align__(16) char smg[];
    const u32 sb = smem_u32(smg);

    const int tid = threadIdx.x;
    const int wid = tid >> 5;
    const int lane = tid & 31;
    const int warp_m = wid & 3;           // 0..3  (32 rows each)
    const int warp_n = wid >> 2;          // 0..1  (32 cols each)
    const int m0 = blockIdx.y * 128;
    const int n0 = blockIdx.x * 64;

    const int a_row = (lane & 15);
    const int a_kh  = (lane >> 4);
    const u32 aoff = (u32)((warp_m * 32 + a_row) * ROWB + a_kh * 16);
    const int b_row = (lane & 7) + ((lane >> 4) << 3);
    const int b_kh  = (lane >> 3) & 1;
    const u32 boff = (u32)((warp_n * 32 + b_row) * ROWB + b_kh * 16);

    float acc[2][4][4] = {};

    const __half* aS[2] = { Ah + ((long)m0 << 10), Al + ((long)m0 << 10) };
    const __half* bP = BT + ((long)n0 << 10);

    auto issue = [&](int kc, int p) {
        const u32 dst = sb + (u32)p * STAGE;
        const int row_b = tid >> 2, ch = tid & 3;
#pragma unroll
        for (int t = 0; t < 2; t++) {
#pragma unroll
            for (int i = 0; i < 2; i++) {
                const int f = i * 256 + tid;               // 0..511
                const int r = f >> 2, cc = f & 3;
                CP_ASYNC16(dst + t * ATILE + r * ROWB + cc * 16,
                           aS[t] + ((long)r << 10) + kc * 32 + cc * 8);
            }
        }
        CP_ASYNC16(dst + 2 * ATILE + row_b * ROWB + ch * 16,
                   bP + ((long)row_b << 10) + kc * 32 + ch * 8);
    };

    issue(0, 0); CP_COMMIT();
    issue(1, 1); CP_COMMIT();
    issue(2, 2); CP_COMMIT();

    for (int c = 0; c < 32; c++) {
        const int p = c - (c / 3) * 3;          // c % 3
        CP_WAIT2();
        __syncthreads();

        const u32 base = sb + (u32)p * STAGE;
#pragma unroll
        for (int ks = 0; ks < 2; ks++) {
            u32 ah[2][4], al[2][4];
#pragma unroll
            for (int mt = 0; mt < 2; mt++) {
                const u32 a = base + aoff + mt * (16 * ROWB) + ks * 32;
                ldsm_x4(ah[mt][0], ah[mt][1], ah[mt][2], ah[mt][3], a);
                ldsm_x4(al[mt][0], al[mt][1], al[mt][2], al[mt][3], a + ATILE);
            }
            u32 bh[4][2];
#pragma unroll
            for (int nt2 = 0; nt2 < 2; nt2++) {
                u32 r0, r1, r2, r3;
                ldsm_x4(r0, r1, r2, r3,
                        base + 2 * ATILE + boff + nt2 * (16 * ROWB) + ks * 32);
                bh[nt2 * 2 + 0][0] = r0; bh[nt2 * 2 + 0][1] = r1;
                bh[nt2 * 2 + 1][0] = r2; bh[nt2 * 2 + 1][1] = r3;
            }
            // sweep 1: Ah * B
#pragma unroll
            for (int mt = 0; mt < 2; mt++)
#pragma unroll
                for (int nt = 0; nt < 4; nt++)
                    mma16816(acc[mt][nt], ah[mt][0], ah[mt][1], ah[mt][2], ah[mt][3],
                             bh[nt][0], bh[nt][1]);
            // sweep 2: Al * B
#pragma unroll
            for (int mt = 0; mt < 2; mt++)
#pragma unroll
                for (int nt = 0; nt < 4; nt++)
                    mma16816(acc[mt][nt], al[mt][0], al[mt][1], al[mt][2], al[mt][3],
                             bh[nt][0], bh[nt][1]);
        }
        __syncthreads();
        if (c + 3 < 32) issue(c + 3, p);
        CP_COMMIT();
    }

    // epilogue
#pragma unroll
    for (int mt = 0; mt < 2; mt++) {
#pragma unroll
        for (int nt = 0; nt < 4; nt++) {
            const int m = m0 + warp_m * 32 + mt * 16 + (lane >> 2);
            const int n = n0 + warp_n * 32 + nt * 8 + (lane & 3) * 2;
            const float bx = bias[n], by = bias[n + 1];
#pragma unroll
            for (int half = 0; half < 2; half++) {
                const int mm = m + half * 8;
                const float vx = acc[mt][nt][half * 2 + 0] + bx;
                const float vy = acc[mt][nt][half * 2 + 1] + by;
                if (MODE == 1) {
                    *(float2*)&out[(long)mm * D_MODEL + n] = make_float2(vx, vy);
                } else {
                    const int b = mm >> 11, s = mm & 2047;
                    const int hd = n >> 6, dk = n & 63;
                    const long o = (((long)(b * NHEAD + hd) * S_LEN + s) << 6) + dk;
                    const u32 hh = cvt2h(vx, vy);
                    const u32 ll = resid2h(hh, vx, vy);
                    *(u32*)&outh[o] = hh;
                    *(u32*)&outl[o] = ll;
                }
            }
        }
    }
}

__global__ __launch_bounds__(256, 2) void qk_gemm_tc(const float* __restrict__ bq,
                                                     const float* __restrict__ bk)
{
    if (blockIdx.z == 0)
        tc_gemm_body<0>(g_Ah, g_Al, g_WT[0], bq, nullptr, g_Qh, g_Ql);
    else
        tc_gemm_body<0>(g_Ah, g_Al, g_WT[1], bk, nullptr, g_Kh, g_Kl);
}

__global__ __launch_bounds__(256, 2) void out_gemm_tc(const float* __restrict__ b0,
                                                      float* __restrict__ out)
{
    tc_gemm_body<1>(g_Ah, g_Al, g_WT[2], b0, out, nullptr, nullptr);
}

// ---------------------------------------------------------------------------
// Flash attention on mma.sync fp16, causal, V = Q.
// S-phase: fp16 split 3-pass (Qh·Kh + Ql·Kh + Qh·Kl) — errors ~2^-22.
// PV-phase: P single fp16 (round err 2^-12), V hi+lo 2-pass.
// ---------------------------------------------------------------------------
#define PITCH   144
#define TILE_B  (128 * PITCH)
#define OFF_KV0 (2 * TILE_B)
#define KV_SZ   (4 * TILE_B)
#define AT_SMEM (OFF_KV0 + 2 * KV_SZ)

#define SCALE_LOG2 0.18033688011112043f   // (1/8) * log2(e)

__global__ __launch_bounds__(256, 1) void attn_tc()
{
    extern __shared__ char smc[];
    const u32 sb = smem_u32(smc);
    const int tid  = threadIdx.x;
    const int lane = tid & 31;
    const int w    = tid >> 5;
    const int qi = (int)gridDim.x - 1 - (int)blockIdx.x;
    const int bh = blockIdx.y;

    const int lrow = lane & 15;
    const int lch  = lane >> 4;
    const int rlo  = w * 16 + (lane >> 2);
    const int rhi  = rlo + 8;

    {
        const long qb = ((long)bh * S_LEN + (long)qi * 128) * DKH;
#pragma unroll
        for (int i = 0; i < 8; i++) {
            const int t = i >> 2;
            const int idx = (i & 3) * 256 + tid;
            const int r = idx >> 3, c = idx & 7;
            const __half* src = (t == 0 ? g_Qh : g_Ql) + qb + r * 64 + c * 8;
            CP_ASYNC16(sb + t * TILE_B + r * PITCH + c * 16, src);
        }
        const long kb = ((long)bh * S_LEN) * DKH;
#pragma unroll
        for (int i = 0; i < 16; i++) {
            const int t = i >> 2;
            const int idx = (i & 3) * 256 + tid;
            const int r = idx >> 3, c = idx & 7;
            const __half* src =
                (t == 0 ? g_Kh : t == 1 ? g_Kl : t == 2 ? g_Qh : g_Ql) + kb + r * 64 + c * 8;
            CP_ASYNC16(sb + OFF_KV0 + t * TILE_B + r * PITCH + c * 16, src);
        }
        CP_COMMIT();
    }

    u32 aQh[4][4], aQl[4][4];
    float o_[8][4] = {};
    float mst0 = -1e30f, mst1 = -1e30f;
    float lst0 = 0.0f, lst1 = 0.0f;

    for (int j = 0; j <= qi; j++) {
        CP_WAIT0();
        __syncthreads();
        const u32 buf = sb + OFF_KV0 + (u32)(j & 1) * KV_SZ;

        if (j == 0) {
#pragma unroll
            for (int s = 0; s < 4; s++) {
                const u32 a = (u32)((w * 16 + lrow) * PITCH + s * 32 + lch * 16);
                ldsm_x4(aQh[s][0], aQh[s][1], aQh[s][2], aQh[s][3], sb + a);
                ldsm_x4(aQl[s][0], aQl[s][1], aQl[s][2], aQl[s][3], sb + TILE_B + a);
            }
        }
        if (j < qi) {
            const long kb = ((long)bh * S_LEN + (long)(j + 1) * 128) * DKH;
            const u32 nbuf = sb + OFF_KV0 + (u32)((j + 1) & 1) * KV_SZ;
#pragma unroll
            for (int i = 0; i < 16; i++) {
                const int t = i >> 2;
                const int idx = (i & 3) * 256 + tid;
                const int r = idx >> 3, c = idx & 7;
                const __half* src =
                    (t == 0 ? g_Kh : t == 1 ? g_Kl : t == 2 ? g_Qh : g_Ql) + kb + r * 64 + c * 8;
                CP_ASYNC16(nbuf + t * TILE_B + r * PITCH + c * 16, src);
            }
            CP_COMMIT();
        }

        // ---- S = Q K^T : fused 3-pass fp16 ----
        float s_[16][4] = {};
        const u32 bbase = buf + (u32)(lrow * PITCH + lch * 16);

#pragma unroll
        for (int ks = 0; ks < 4; ks++) {
            const u32 tb = bbase + ks * 32;
#pragma unroll
            for (int nc = 0; nc < 8; nc++) {
                u32 h0, h1, h2, h3, l0, l1, l2, l3;
                ldsm_x4(h0, h1, h2, h3, tb + nc * (16 * PITCH));
                ldsm_x4(l0, l1, l2, l3, tb + nc * (16 * PITCH) + TILE_B);
                mma16816(s_[2 * nc],     aQh[ks][0], aQh[ks][1], aQh[ks][2], aQh[ks][3], h0, h2);
                mma16816(s_[2 * nc + 1], aQh[ks][0], aQh[ks][1], aQh[ks][2], aQh[ks][3], h1, h3);
                mma16816(s_[2 * nc],     aQl[ks][0], aQl[ks][1], aQl[ks][2], aQl[ks][3], h0, h2);
                mma16816(s_[2 * nc + 1], aQl[ks][0], aQl[ks][1], aQl[ks][2], aQl[ks][3], h1, h3);
                mma16816(s_[2 * nc],     aQh[ks][0], aQh[ks][1], aQh[ks][2], aQh[ks][3], l0, l2);
                mma16816(s_[2 * nc + 1], aQh[ks][0], aQh[ks][1], aQh[ks][2], aQh[ks][3], l1, l3);
            }
        }

        // ---- online softmax (log2 domain) ----
        float rmx0 = -1e30f, rmx1 = -1e30f;
#pragma unroll
        for (int nt = 0; nt < 16; nt++) {
#pragma unroll
            for (int q = 0; q < 4; q++) s_[nt][q] *= SCALE_LOG2;
            if (j == qi) {
                const int c0 = nt * 8 + (lane & 3) * 2;
                if (c0 > rlo)     s_[nt][0] = -1e30f;
                if (c0 + 1 > rlo) s_[nt][1] = -1e30f;
                if (c0 > rhi)     s_[nt][2] = -1e30f;
                if (c0 + 1 > rhi) s_[nt][3] = -1e30f;
            }
            rmx0 = fmaxf(rmx0, fmaxf(s_[nt][0], s_[nt][1]));
            rmx1 = fmaxf(rmx1, fmaxf(s_[nt][2], s_[nt][3]));
        }
        rmx0 = fmaxf(rmx0, __shfl_xor_sync(0xffffffffu, rmx0, 1));
        rmx0 = fmaxf(rmx0, __shfl_xor_sync(0xffffffffu, rmx0, 2));
        rmx1 = fmaxf(rmx1, __shfl_xor_sync(0xffffffffu, rmx1, 1));
        rmx1 = fmaxf(rmx1, __shfl_xor_sync(0xffffffffu, rmx1, 2));
        const float mn0 = fmaxf(mst0, rmx0);
        const float mn1 = fmaxf(mst1, rmx1);
        const float al0 = ex2(mst0 - mn0);
        const float al1 = ex2(mst1 - mn1);
        float sum0 = 0.0f, sum1 = 0.0f;
#pragma unroll
        for (int nt = 0; nt < 16; nt++) {
            s_[nt][0] = ex2(s_[nt][0] - mn0);
            s_[nt][1] = ex2(s_[nt][1] - mn0);
            s_[nt][2] = ex2(s_[nt][2] - mn1);
            s_[nt][3] = ex2(s_[nt][3] - mn1);
            sum0 += s_[nt][0] + s_[nt][1];
            sum1 += s_[nt][2] + s_[nt][3];
        }
        sum0 += __shfl_xor_sync(0xffffffffu, sum0, 1);
        sum0 += __shfl_xor_sync(0xffffffffu, sum0, 2);
        sum1 += __shfl_xor_sync(0xffffffffu, sum1, 1);
        sum1 += __shfl_xor_sync(0xffffffffu, sum1, 2);
        lst0 = lst0 * al0 + sum0;
        lst1 = lst1 * al1 + sum1;
        mst0 = mn0;
        mst1 = mn1;
#pragma unroll
        for (int nt = 0; nt < 8; nt++) {
            o_[nt][0] *= al0; o_[nt][1] *= al0;
            o_[nt][2] *= al1; o_[nt][3] *= al1;
        }

        // ---- O += P V : P single fp16, V hi+lo (2 sweeps) ----
        const u32 vh_b = buf + 2 * TILE_B;
#pragma unroll
        for (int s = 0; s < 8; s++) {
            u32 pf[4];
            pf[0] = cvt2h(s_[2 * s][0], s_[2 * s][1]);
            pf[1] = cvt2h(s_[2 * s][2], s_[2 * s][3]);
            pf[2] = cvt2h(s_[2 * s + 1][0], s_[2 * s + 1][1]);
            pf[3] = cvt2h(s_[2 * s + 1][2], s_[2 * s + 1][3]);

            u32 vh_[8][2], vl_[8][2];
#pragma unroll
            for (int tp = 0; tp < 4; tp++) {
                const u32 a = vh_b + (u32)((s * 16 + lrow) * PITCH + (tp * 2 + lch) * 16);
                u32 r0, r1, r2, r3;
                ldsm_x4t(r0, r1, r2, r3, a);
                vh_[2 * tp][0] = r0; vh_[2 * tp][1] = r1;
                vh_[2 * tp + 1][0] = r2; vh_[2 * tp + 1][1] = r3;
                ldsm_x4t(r0, r1, r2, r3, a + TILE_B);
                vl_[2 * tp][0] = r0; vl_[2 * tp][1] = r1;
                vl_[2 * tp + 1][0] = r2; vl_[2 * tp + 1][1] = r3;
            }
            // sweep 1: P * Vh
#pragma unroll
            for (int nt = 0; nt < 8; nt++)
                mma16816(o_[nt], pf[0], pf[1], pf[2], pf[3], vh_[nt][0], vh_[nt][1]);
            // sweep 2: P * Vl
#pragma unroll
            for (int nt = 0; nt < 8; nt++)
                mma16816(o_[nt], pf[0], pf[1], pf[2], pf[3], vl_[nt][0], vl_[nt][1]);
        }
    }

    const int bat = bh >> 4, head = bh & 15;
    const float i0 = 1.0f / lst0;
    const float i1 = 1.0f / lst1;
    const int row0 = qi * 128 + rlo;
#pragma unroll
    for (int nt = 0; nt < 8; nt++) {
        const int d = head * 64 + nt * 8 + (lane & 3) * 2;
        {
            const float x = o_[nt][0] * i0, y = o_[nt][1] * i0;
            const u32 hh = cvt2h(x, y), ll = resid2h(hh, x, y);
            const long a = ((long)(bat * S_LEN + row0) << 10) + d;
            *(u32*)&g_Ah[a] = hh;
            *(u32*)&g_Al[a] = ll;
        }
        {
            const float x = o_[nt][2] * i1, y = o_[nt][3] * i1;
            const u32 hh = cvt2h(x, y), ll = resid2h(hh, x, y);
            const long a = ((long)(bat * S_LEN + row0 + 8) << 10) + d;
            *(u32*)&g_Ah[a] = hh;
            *(u32*)&g_Al[a] = ll;
        }
    }
}

// ---------------------------------------------------------------------------
extern "C" void kernel_launch(void* const* d_in, const int* in_sizes, int n_in,
                              void* d_out, int out_size)
{
    const float* x  = (const float*)d_in[0];
    const float* Wq = (const float*)d_in[1];
    const float* bq = (const float*)d_in[2];
    const float* Wk = (const float*)d_in[3];
    const float* bk = (const float*)d_in[4];
    const float* W0 = (const float*)d_in[5];
    const float* b0 = (const float*)d_in[6];
    float* out = (float*)d_out;

    __half *dAh, *dAl;
    cudaGetSymbolAddress((void**)&dAh, g_Ah);
    cudaGetSymbolAddress((void**)&dAl, g_Al);

    cudaFuncSetAttribute(attn_tc, cudaFuncAttributeMaxDynamicSharedMemorySize, AT_SMEM);
    cudaFuncSetAttribute(qk_gemm_tc, cudaFuncAttributeMaxDynamicSharedMemorySize, GSMEM);
    cudaFuncSetAttribute(out_gemm_tc, cudaFuncAttributeMaxDynamicSharedMemorySize, GSMEM);

    // 1) decompose x and all weights
    decomp_A<<<M_TOK * D_MODEL / 1024, 256>>>(x, dAh, dAl);
    dim3 wt_grid(32, 32, 3);
    decomp_WT3<<<wt_grid, 256>>>(Wq, Wk, W0);

    // 2) Q & K projections -> fp16 hi/lo head layout
    dim3 qk_grid(D_MODEL / 64, M_TOK / 128, 2);    // (16, 32, 2)
    qk_gemm_tc<<<qk_grid, 256, GSMEM>>>(bq, bk);

    // 3) attention (tensor cores) -> g_Ah/g_Al
    dim3 attn_grid(S_LEN / 128, BATCH * NHEAD);     // (16, 32)
    attn_tc<<<attn_grid, 256, AT_SMEM>>>();

    // 4) output projection
    dim3 o_grid(D_MODEL / 64, M_TOK / 128);         // (16, 32)
    out_gemm_tc<<<o_grid, 256, GSMEM>>>(b0, out);
}

// round 11
// speedup vs baseline: 4.4292x; 1.2628x over previous
#include <cuda_runtime.h>
#include <cuda_fp16.h>

#define S_LEN   2048
#define D_MODEL 1024
#define NHEAD   16
#define DKH     64
#define BATCH   2
#define M_TOK   (BATCH * S_LEN)   // 4096

typedef unsigned long long u64;
typedef unsigned int u32;

// ------------------------------- scratch -----------------------------------
__device__ __half g_Qh[BATCH * NHEAD * S_LEN * DKH];  // [B,H,S,DK] hi
__device__ __half g_Ql[BATCH * NHEAD * S_LEN * DKH];  // lo (V residual)
__device__ __half g_Kh[BATCH * NHEAD * S_LEN * DKH];  // K single fp16
__device__ __half g_Ah[M_TOK * D_MODEL];              // A hi (x, then att)
__device__ __half g_Al[M_TOK * D_MODEL];              // A lo
__device__ __half g_WT[3][D_MODEL * D_MODEL];         // W^T fp16 (single): q,k,o

// --------------------------- small helpers ---------------------------------
__device__ __forceinline__ u32 smem_u32(const void* p) {
    u32 a; asm("{ .reg .u64 t; cvta.to.shared.u64 t, %1; cvt.u32.u64 %0, t; }" : "=r"(a) : "l"(p));
    return a;
}

#define CP_ASYNC16(dst, src) \
    asm volatile("cp.async.cg.shared.global [%0], [%1], 16;" :: "r"(dst), "l"(src))
#define CP_COMMIT()  asm volatile("cp.async.commit_group;" ::: "memory")
#define CP_WAIT2()   asm volatile("cp.async.wait_group 2;" ::: "memory")
#define CP_WAIT0()   asm volatile("cp.async.wait_group 0;" ::: "memory")

__device__ __forceinline__ void ldsm_x4(u32& r0, u32& r1, u32& r2, u32& r3, u32 addr) {
    asm volatile("ldmatrix.sync.aligned.m8n8.x4.shared.b16 {%0,%1,%2,%3}, [%4];"
                 : "=r"(r0), "=r"(r1), "=r"(r2), "=r"(r3) : "r"(addr));
}
__device__ __forceinline__ void ldsm_x4t(u32& r0, u32& r1, u32& r2, u32& r3, u32 addr) {
    asm volatile("ldmatrix.sync.aligned.m8n8.x4.trans.shared.b16 {%0,%1,%2,%3}, [%4];"
                 : "=r"(r0), "=r"(r1), "=r"(r2), "=r"(r3) : "r"(addr));
}

__device__ __forceinline__ void mma16816(float* d, u32 a0, u32 a1, u32 a2, u32 a3,
                                         u32 b0, u32 b1) {
    asm volatile("mma.sync.aligned.m16n8k16.row.col.f32.f16.f16.f32 "
                 "{%0,%1,%2,%3}, {%4,%5,%6,%7}, {%8,%9}, {%0,%1,%2,%3};"
                 : "+f"(d[0]), "+f"(d[1]), "+f"(d[2]), "+f"(d[3])
                 : "r"(a0), "r"(a1), "r"(a2), "r"(a3), "r"(b0), "r"(b1));
}

__device__ __forceinline__ float ex2(float x) {
    float y; asm("ex2.approx.f32 %0, %1;" : "=f"(y) : "f"(x)); return y;
}

__device__ __forceinline__ u32 cvt2h(float x, float y) {
    __half2 t = __floats2half2_rn(x, y);
    return *reinterpret_cast<u32*>(&t);
}
__device__ __forceinline__ u32 resid2h(u32 h, float x, float y) {
    __half2 hh = *reinterpret_cast<__half2*>(&h);
    return cvt2h(x - __low2float(hh), y - __high2float(hh));
}

// ------------------------- fp32 -> fp16 hi/lo split -------------------------
__global__ __launch_bounds__(256) void decomp_A(const float* __restrict__ src,
                                                __half* __restrict__ hi,
                                                __half* __restrict__ lo)
{
    const int i = (blockIdx.x * 256 + threadIdx.x) * 4;
    float4 v = *(const float4*)(src + i);
    __half h0 = __float2half_rn(v.x);
    __half h1 = __float2half_rn(v.y);
    __half h2 = __float2half_rn(v.z);
    __half h3 = __float2half_rn(v.w);
    __half l0 = __float2half_rn(v.x - __half2float(h0));
    __half l1 = __float2half_rn(v.y - __half2float(h1));
    __half l2 = __float2half_rn(v.z - __half2float(h2));
    __half l3 = __float2half_rn(v.w - __half2float(h3));
    __half2 hA(h0, h1), hB(h2, h3), lA(l0, l1), lB(l2, l3);
    *(uint2*)(hi + i) = make_uint2(*(u32*)&hA, *(u32*)&hB);
    *(uint2*)(lo + i) = make_uint2(*(u32*)&lA, *(u32*)&lB);
}

// all three W [K,N] fp32 -> W^T fp16 (single precision piece), z = matrix id
__global__ __launch_bounds__(256) void decomp_WT3(const float* __restrict__ Wq,
                                                  const float* __restrict__ Wk,
                                                  const float* __restrict__ W0)
{
    const int z = blockIdx.z;
    const float* W = (z == 0) ? Wq : (z == 1) ? Wk : W0;
    __half* hiT = g_WT[z];

    __shared__ float t[32][33];
    const int tx = threadIdx.x & 31, ty = threadIdx.x >> 5;   // (32, 8)
    const int n0 = blockIdx.x * 32, k0 = blockIdx.y * 32;
#pragma unroll
    for (int i = 0; i < 4; i++)
        t[ty + 8 * i][tx] = W[(k0 + ty + 8 * i) * D_MODEL + n0 + tx];
    __syncthreads();
#pragma unroll
    for (int i = 0; i < 4; i++) {
        float v = t[tx][ty + 8 * i];
        hiT[(long)(n0 + ty + 8 * i) * D_MODEL + k0 + tx] = __float2half_rn(v);
    }
}

// ---------------------------------------------------------------------------
// split-fp16 GEMM: C = (Ah [+ Al]) @ Wf + bias
// BM=128, BN=64, BK=32, 256 threads (8 warps 4x2), warp tile 32x32.
// 3-stage cp.async, 2 CTAs/SM.
//   MODE 0: head layout, write fp16 hi + lo
//   MODE 1: row-major fp32
//   MODE 2: head layout, write fp16 hi only
//   NPASS 1: Ah only ; NPASS 2: Ah + Al
// ---------------------------------------------------------------------------
#define ROWB  80                       // 64 data bytes + 16 pad
#define ATILE (128 * ROWB)             // 10240
#define BTILE (64 * ROWB)              // 5120
#define STAGE (2 * ATILE + BTILE)      // 25600 : [Ah][Al][B]
#define GSMEM (3 * STAGE)              // 76800

template <int MODE, int NPASS>
__device__ __forceinline__ void tc_gemm_body(const __half* __restrict__ Ah,
                                             const __half* __restrict__ Al,
                                             const __half* __restrict__ BT,
                                             const float* __restrict__ bias,
                                             float* __restrict__ out,
                                             __half* __restrict__ outh,
                                             __half* __restrict__ outl)
{
    extern __shared__ __align__(16) char smg[];
    const u32 sb = smem_u32(smg);

    const int tid = threadIdx.x;
    const int wid = tid >> 5;
    const int lane = tid & 31;
    const int warp_m = wid & 3;           // 0..3  (32 rows each)
    const int warp_n = wid >> 2;          // 0..1  (32 cols each)
    const int m0 = blockIdx.y * 128;
    const int n0 = blockIdx.x * 64;

    const int a_row = (lane & 15);
    const int a_kh  = (lane >> 4);
    const u32 aoff = (u32)((warp_m * 32 + a_row) * ROWB + a_kh * 16);
    const int b_row = (lane & 7) + ((lane >> 4) << 3);
    const int b_kh  = (lane >> 3) & 1;
    const u32 boff = (u32)((warp_n * 32 + b_row) * ROWB + b_kh * 16);

    float acc[2][4][4] = {};

    const __half* aS[2] = { Ah + ((long)m0 << 10), Al + ((long)m0 << 10) };
    const __half* bP = BT + ((long)n0 << 10);

    auto issue = [&](int kc, int p) {
        const u32 dst = sb + (u32)p * STAGE;
        const int row_b = tid >> 2, ch = tid & 3;
#pragma unroll
        for (int t = 0; t < NPASS; t++) {
#pragma unroll
            for (int i = 0; i < 2; i++) {
                const int f = i * 256 + tid;               // 0..511
                const int r = f >> 2, cc = f & 3;
                CP_ASYNC16(dst + t * ATILE + r * ROWB + cc * 16,
                           aS[t] + ((long)r << 10) + kc * 32 + cc * 8);
            }
        }
        CP_ASYNC16(dst + 2 * ATILE + row_b * ROWB + ch * 16,
                   bP + ((long)row_b << 10) + kc * 32 + ch * 8);
    };

    issue(0, 0); CP_COMMIT();
    issue(1, 1); CP_COMMIT();
    issue(2, 2); CP_COMMIT();

    for (int c = 0; c < 32; c++) {
        const int p = c - (c / 3) * 3;          // c % 3
        CP_WAIT2();
        __syncthreads();

        const u32 base = sb + (u32)p * STAGE;
#pragma unroll
        for (int ks = 0; ks < 2; ks++) {
            u32 ah[2][4], al[2][4];
#pragma unroll
            for (int mt = 0; mt < 2; mt++) {
                const u32 a = base + aoff + mt * (16 * ROWB) + ks * 32;
                ldsm_x4(ah[mt][0], ah[mt][1], ah[mt][2], ah[mt][3], a);
                if (NPASS == 2)
                    ldsm_x4(al[mt][0], al[mt][1], al[mt][2], al[mt][3], a + ATILE);
            }
            u32 bh[4][2];
#pragma unroll
            for (int nt2 = 0; nt2 < 2; nt2++) {
                u32 r0, r1, r2, r3;
                ldsm_x4(r0, r1, r2, r3,
                        base + 2 * ATILE + boff + nt2 * (16 * ROWB) + ks * 32);
                bh[nt2 * 2 + 0][0] = r0; bh[nt2 * 2 + 0][1] = r1;
                bh[nt2 * 2 + 1][0] = r2; bh[nt2 * 2 + 1][1] = r3;
            }
            // sweep 1: Ah * B
#pragma unroll
            for (int mt = 0; mt < 2; mt++)
#pragma unroll
                for (int nt = 0; nt < 4; nt++)
                    mma16816(acc[mt][nt], ah[mt][0], ah[mt][1], ah[mt][2], ah[mt][3],
                             bh[nt][0], bh[nt][1]);
            // sweep 2: Al * B
            if (NPASS == 2) {
#pragma unroll
                for (int mt = 0; mt < 2; mt++)
#pragma unroll
                    for (int nt = 0; nt < 4; nt++)
                        mma16816(acc[mt][nt], al[mt][0], al[mt][1], al[mt][2], al[mt][3],
                                 bh[nt][0], bh[nt][1]);
            }
        }
        __syncthreads();
        if (c + 3 < 32) issue(c + 3, p);
        CP_COMMIT();
    }

    // epilogue
#pragma unroll
    for (int mt = 0; mt < 2; mt++) {
#pragma unroll
        for (int nt = 0; nt < 4; nt++) {
            const int m = m0 + warp_m * 32 + mt * 16 + (lane >> 2);
            const int n = n0 + warp_n * 32 + nt * 8 + (lane & 3) * 2;
            const float bx = bias[n], by = bias[n + 1];
#pragma unroll
            for (int half = 0; half < 2; half++) {
                const int mm = m + half * 8;
                const float vx = acc[mt][nt][half * 2 + 0] + bx;
                const float vy = acc[mt][nt][half * 2 + 1] + by;
                if (MODE == 1) {
                    *(float2*)&out[(long)mm * D_MODEL + n] = make_float2(vx, vy);
                } else {
                    const int b = mm >> 11, s = mm & 2047;
                    const int hd = n >> 6, dk = n & 63;
                    const long o = (((long)(b * NHEAD + hd) * S_LEN + s) << 6) + dk;
                    const u32 hh = cvt2h(vx, vy);
                    *(u32*)&outh[o] = hh;
                    if (MODE == 0) {
                        const u32 ll = resid2h(hh, vx, vy);
                        *(u32*)&outl[o] = ll;
                    }
                }
            }
        }
    }
}

__global__ __launch_bounds__(256, 2) void qk_gemm_tc(const float* __restrict__ bq,
                                                     const float* __restrict__ bk)
{
    if (blockIdx.z == 0)   // Q (=V): full 2-pass, hi+lo out
        tc_gemm_body<0, 2>(g_Ah, g_Al, g_WT[0], bq, nullptr, g_Qh, g_Ql);
    else                   // K: single-pass, hi only
        tc_gemm_body<2, 1>(g_Ah, g_Al, g_WT[1], bk, nullptr, g_Kh, nullptr);
}

__global__ __launch_bounds__(256, 2) void out_gemm_tc(const float* __restrict__ b0,
                                                      float* __restrict__ out)
{
    tc_gemm_body<1, 2>(g_Ah, g_Al, g_WT[2], b0, out, nullptr, nullptr);
}

// ---------------------------------------------------------------------------
// Flash attention on mma.sync fp16, causal, V = Q.
// S-phase: SINGLE pass Qh·Kh (logit-error ~1e-4, harmless to softmax).
// PV-phase: P single fp16, V = (Qh + Ql) 2-pass (output-critical).
// smem: [Qh tile][2 x (Kh, Vh, Vl)] -- 7 tiles total.
// ---------------------------------------------------------------------------
#define PITCH   144
#define TILE_B  (128 * PITCH)          // 18432
#define OFF_KV0 (TILE_B)
#define KV_SZ   (3 * TILE_B)
#define AT_SMEM (OFF_KV0 + 2 * KV_SZ)  // 129024

#define SCALE_LOG2 0.18033688011112043f   // (1/8) * log2(e)

__global__ __launch_bounds__(256, 1) void attn_tc()
{
    extern __shared__ char smc[];
    const u32 sb = smem_u32(smc);
    const int tid  = threadIdx.x;
    const int lane = tid & 31;
    const int w    = tid >> 5;
    const int qi = (int)gridDim.x - 1 - (int)blockIdx.x;
    const int bh = blockIdx.y;

    const int lrow = lane & 15;
    const int lch  = lane >> 4;
    const int rlo  = w * 16 + (lane >> 2);
    const int rhi  = rlo + 8;

    {
        const long qb = ((long)bh * S_LEN + (long)qi * 128) * DKH;
#pragma unroll
        for (int i = 0; i < 4; i++) {
            const int idx = i * 256 + tid;
            const int r = idx >> 3, c = idx & 7;
            CP_ASYNC16(sb + r * PITCH + c * 16, g_Qh + qb + r * 64 + c * 8);
        }
        const long kb = ((long)bh * S_LEN) * DKH;   // j = 0
#pragma unroll
        for (int i = 0; i < 12; i++) {
            const int t = i >> 2;                   // 0:Kh 1:Vh(=Qh) 2:Vl(=Ql)
            const int idx = (i & 3) * 256 + tid;
            const int r = idx >> 3, c = idx & 7;
            const __half* src =
                (t == 0 ? g_Kh : t == 1 ? g_Qh : g_Ql) + kb + r * 64 + c * 8;
            CP_ASYNC16(sb + OFF_KV0 + t * TILE_B + r * PITCH + c * 16, src);
        }
        CP_COMMIT();
    }

    u32 aQh[4][4];
    float o_[8][4] = {};
    float mst0 = -1e30f, mst1 = -1e30f;
    float lst0 = 0.0f, lst1 = 0.0f;

    for (int j = 0; j <= qi; j++) {
        CP_WAIT0();
        __syncthreads();
        const u32 buf = sb + OFF_KV0 + (u32)(j & 1) * KV_SZ;

        if (j == 0) {
#pragma unroll
            for (int s = 0; s < 4; s++) {
                const u32 a = (u32)((w * 16 + lrow) * PITCH + s * 32 + lch * 16);
                ldsm_x4(aQh[s][0], aQh[s][1], aQh[s][2], aQh[s][3], sb + a);
            }
        }
        if (j < qi) {
            const long kb = ((long)bh * S_LEN + (long)(j + 1) * 128) * DKH;
            const u32 nbuf = sb + OFF_KV0 + (u32)((j + 1) & 1) * KV_SZ;
#pragma unroll
            for (int i = 0; i < 12; i++) {
                const int t = i >> 2;
                const int idx = (i & 3) * 256 + tid;
                const int r = idx >> 3, c = idx & 7;
                const __half* src =
                    (t == 0 ? g_Kh : t == 1 ? g_Qh : g_Ql) + kb + r * 64 + c * 8;
                CP_ASYNC16(nbuf + t * TILE_B + r * PITCH + c * 16, src);
            }
            CP_COMMIT();
        }

        // ---- S = Qh Kh^T : single pass ----
        float s_[16][4] = {};
        const u32 bbase = buf + (u32)(lrow * PITCH + lch * 16);

#pragma unroll
        for (int ks = 0; ks < 4; ks++) {
            const u32 tb = bbase + ks * 32;
#pragma unroll
            for (int nc = 0; nc < 8; nc++) {
                u32 h0, h1, h2, h3;
                ldsm_x4(h0, h1, h2, h3, tb + nc * (16 * PITCH));
                mma16816(s_[2 * nc],     aQh[ks][0], aQh[ks][1], aQh[ks][2], aQh[ks][3], h0, h2);
                mma16816(s_[2 * nc + 1], aQh[ks][0], aQh[ks][1], aQh[ks][2], aQh[ks][3], h1, h3);
            }
        }

        // ---- online softmax (log2 domain) ----
        float rmx0 = -1e30f, rmx1 = -1e30f;
#pragma unroll
        for (int nt = 0; nt < 16; nt++) {
#pragma unroll
            for (int q = 0; q < 4; q++) s_[nt][q] *= SCALE_LOG2;
            if (j == qi) {
                const int c0 = nt * 8 + (lane & 3) * 2;
                if (c0 > rlo)     s_[nt][0] = -1e30f;
                if (c0 + 1 > rlo) s_[nt][1] = -1e30f;
                if (c0 > rhi)     s_[nt][2] = -1e30f;
                if (c0 + 1 > rhi) s_[nt][3] = -1e30f;
            }
            rmx0 = fmaxf(rmx0, fmaxf(s_[nt][0], s_[nt][1]));
            rmx1 = fmaxf(rmx1, fmaxf(s_[nt][2], s_[nt][3]));
        }
        rmx0 = fmaxf(rmx0, __shfl_xor_sync(0xffffffffu, rmx0, 1));
        rmx0 = fmaxf(rmx0, __shfl_xor_sync(0xffffffffu, rmx0, 2));
        rmx1 = fmaxf(rmx1, __shfl_xor_sync(0xffffffffu, rmx1, 1));
        rmx1 = fmaxf(rmx1, __shfl_xor_sync(0xffffffffu, rmx1, 2));
        const float mn0 = fmaxf(mst0, rmx0);
        const float mn1 = fmaxf(mst1, rmx1);
        const float al0 = ex2(mst0 - mn0);
        const float al1 = ex2(mst1 - mn1);
        float sum0 = 0.0f, sum1 = 0.0f;
#pragma unroll
        for (int nt = 0; nt < 16; nt++) {
            s_[nt][0] = ex2(s_[nt][0] - mn0);
            s_[nt][1] = ex2(s_[nt][1] - mn0);
            s_[nt][2] = ex2(s_[nt][2] - mn1);
            s_[nt][3] = ex2(s_[nt][3] - mn1);
            sum0 += s_[nt][0] + s_[nt][1];
            sum1 += s_[nt][2] + s_[nt][3];
        }
        sum0 += __shfl_xor_sync(0xffffffffu, sum0, 1);
        sum0 += __shfl_xor_sync(0xffffffffu, sum0, 2);
        sum1 += __shfl_xor_sync(0xffffffffu, sum1, 1);
        sum1 += __shfl_xor_sync(0xffffffffu, sum1, 2);
        lst0 = lst0 * al0 + sum0;
        lst1 = lst1 * al1 + sum1;
        mst0 = mn0;
        mst1 = mn1;
#pragma unroll
        for (int nt = 0; nt < 8; nt++) {
            o_[nt][0] *= al0; o_[nt][1] *= al0;
            o_[nt][2] *= al1; o_[nt][3] *= al1;
        }

        // ---- O += P V : P single fp16, V hi+lo (2 sweeps) ----
        const u32 vh_b = buf + TILE_B;
#pragma unroll
        for (int s = 0; s < 8; s++) {
            u32 pf[4];
            pf[0] = cvt2h(s_[2 * s][0], s_[2 * s][1]);
            pf[1] = cvt2h(s_[2 * s][2], s_[2 * s][3]);
            pf[2] = cvt2h(s_[2 * s + 1][0], s_[2 * s + 1][1]);
            pf[3] = cvt2h(s_[2 * s + 1][2], s_[2 * s + 1][3]);

            u32 vh_[8][2], vl_[8][2];
#pragma unroll
            for (int tp = 0; tp < 4; tp++) {
                const u32 a = vh_b + (u32)((s * 16 + lrow) * PITCH + (tp * 2 + lch) * 16);
                u32 r0, r1, r2, r3;
                ldsm_x4t(r0, r1, r2, r3, a);
                vh_[2 * tp][0] = r0; vh_[2 * tp][1] = r1;
                vh_[2 * tp + 1][0] = r2; vh_[2 * tp + 1][1] = r3;
                ldsm_x4t(r0, r1, r2, r3, a + TILE_B);
                vl_[2 * tp][0] = r0; vl_[2 * tp][1] = r1;
                vl_[2 * tp + 1][0] = r2; vl_[2 * tp + 1][1] = r3;
            }
            // sweep 1: P * Vh
#pragma unroll
            for (int nt = 0; nt < 8; nt++)
                mma16816(o_[nt], pf[0], pf[1], pf[2], pf[3], vh_[nt][0], vh_[nt][1]);
            // sweep 2: P * Vl
#pragma unroll
            for (int nt = 0; nt < 8; nt++)
                mma16816(o_[nt], pf[0], pf[1], pf[2], pf[3], vl_[nt][0], vl_[nt][1]);
        }
    }

    const int bat = bh >> 4, head = bh & 15;
    const float i0 = 1.0f / lst0;
    const float i1 = 1.0f / lst1;
    const int row0 = qi * 128 + rlo;
#pragma unroll
    for (int nt = 0; nt < 8; nt++) {
        const int d = head * 64 + nt * 8 + (lane & 3) * 2;
        {
            const float x = o_[nt][0] * i0, y = o_[nt][1] * i0;
            const u32 hh = cvt2h(x, y), ll = resid2h(hh, x, y);
            const long a = ((long)(bat * S_LEN + row0) << 10) + d;
            *(u32*)&g_Ah[a] = hh;
            *(u32*)&g_Al[a] = ll;
        }
        {
            const float x = o_[nt][2] * i1, y = o_[nt][3] * i1;
            const u32 hh = cvt2h(x, y), ll = resid2h(hh, x, y);
            const long a = ((long)(bat * S_LEN + row0 + 8) << 10) + d;
            *(u32*)&g_Ah[a] = hh;
            *(u32*)&g_Al[a] = ll;
        }
    }
}

// ---------------------------------------------------------------------------
extern "C" void kernel_launch(void* const* d_in, const int* in_sizes, int n_in,
                              void* d_out, int out_size)
{
    const float* x  = (const float*)d_in[0];
    const float* Wq = (const float*)d_in[1];
    const float* bq = (const float*)d_in[2];
    const float* Wk = (const float*)d_in[3];
    const float* bk = (const float*)d_in[4];
    const float* W0 = (const float*)d_in[5];
    const float* b0 = (const float*)d_in[6];
    float* out = (float*)d_out;

    __half *dAh, *dAl;
    cudaGetSymbolAddress((void**)&dAh, g_Ah);
    cudaGetSymbolAddress((void**)&dAl, g_Al);

    cudaFuncSetAttribute(attn_tc, cudaFuncAttributeMaxDynamicSharedMemorySize, AT_SMEM);
    cudaFuncSetAttribute(qk_gemm_tc, cudaFuncAttributeMaxDynamicSharedMemorySize, GSMEM);
    cudaFuncSetAttribute(out_gemm_tc, cudaFuncAttributeMaxDynamicSharedMemorySize, GSMEM);

    // 1) decompose x and all weights
    decomp_A<<<M_TOK * D_MODEL / 1024, 256>>>(x, dAh, dAl);
    dim3 wt_grid(32, 32, 3);
    decomp_WT3<<<wt_grid, 256>>>(Wq, Wk, W0);

    // 2) Q (2-pass) & K (1-pass) projections -> fp16 head layout
    dim3 qk_grid(D_MODEL / 64, M_TOK / 128, 2);    // (16, 32, 2)
    qk_gemm_tc<<<qk_grid, 256, GSMEM>>>(bq, bk);

    // 3) attention (tensor cores) -> g_Ah/g_Al
    dim3 attn_grid(S_LEN / 128, BATCH * NHEAD);     // (16, 32)
    attn_tc<<<attn_grid, 256, AT_SMEM>>>();

    // 4) output projection (2-pass)
    dim3 o_grid(D_MODEL / 64, M_TOK / 128);         // (16, 32)
    out_gemm_tc<<<o_grid, 256, GSMEM>>>(b0, out);
}

// round 12
// speedup vs baseline: 5.4401x; 1.2282x over previous
#include <cuda_runtime.h>
#include <cuda_fp16.h>

#define S_LEN   2048
#define D_MODEL 1024
#define NHEAD   16
#define DKH     64
#define BATCH   2
#define M_TOK   (BATCH * S_LEN)   // 4096

typedef unsigned long long u64;
typedef unsigned int u32;

// ------------------------------- scratch -----------------------------------
__device__ __half g_Qh[BATCH * NHEAD * S_LEN * DKH];  // [B,H,S,DK] Q (=V) fp16
__device__ __half g_Kh[BATCH * NHEAD * S_LEN * DKH];  // K fp16
__device__ __half g_Ah[M_TOK * D_MODEL];              // A hi (x, then att)
__device__ __half g_Al[M_TOK * D_MODEL];              // A lo
__device__ __half g_WT[3][D_MODEL * D_MODEL];         // W^T fp16: q,k,o

// --------------------------- small helpers ---------------------------------
__device__ __forceinline__ u32 smem_u32(const void* p) {
    u32 a; asm("{ .reg .u64 t; cvta.to.shared.u64 t, %1; cvt.u32.u64 %0, t; }" : "=r"(a) : "l"(p));
    return a;
}

#define CP_ASYNC16(dst, src) \
    asm volatile("cp.async.cg.shared.global [%0], [%1], 16;" :: "r"(dst), "l"(src))
#define CP_COMMIT()  asm volatile("cp.async.commit_group;" ::: "memory")
#define CP_WAIT2()   asm volatile("cp.async.wait_group 2;" ::: "memory")
#define CP_WAIT0()   asm volatile("cp.async.wait_group 0;" ::: "memory")

__device__ __forceinline__ void ldsm_x4(u32& r0, u32& r1, u32& r2, u32& r3, u32 addr) {
    asm volatile("ldmatrix.sync.aligned.m8n8.x4.shared.b16 {%0,%1,%2,%3}, [%4];"
                 : "=r"(r0), "=r"(r1), "=r"(r2), "=r"(r3) : "r"(addr));
}
__device__ __forceinline__ void ldsm_x4t(u32& r0, u32& r1, u32& r2, u32& r3, u32 addr) {
    asm volatile("ldmatrix.sync.aligned.m8n8.x4.trans.shared.b16 {%0,%1,%2,%3}, [%4];"
                 : "=r"(r0), "=r"(r1), "=r"(r2), "=r"(r3) : "r"(addr));
}

__device__ __forceinline__ void mma16816(float* d, u32 a0, u32 a1, u32 a2, u32 a3,
                                         u32 b0, u32 b1) {
    asm volatile("mma.sync.aligned.m16n8k16.row.col.f32.f16.f16.f32 "
                 "{%0,%1,%2,%3}, {%4,%5,%6,%7}, {%8,%9}, {%0,%1,%2,%3};"
                 : "+f"(d[0]), "+f"(d[1]), "+f"(d[2]), "+f"(d[3])
                 : "r"(a0), "r"(a1), "r"(a2), "r"(a3), "r"(b0), "r"(b1));
}

__device__ __forceinline__ float ex2(float x) {
    float y; asm("ex2.approx.f32 %0, %1;" : "=f"(y) : "f"(x)); return y;
}

__device__ __forceinline__ u32 cvt2h(float x, float y) {
    __half2 t = __floats2half2_rn(x, y);
    return *reinterpret_cast<u32*>(&t);
}
__device__ __forceinline__ u32 resid2h(u32 h, float x, float y) {
    __half2 hh = *reinterpret_cast<__half2*>(&h);
    return cvt2h(x - __low2float(hh), y - __high2float(hh));
}

// ------------------------- fp32 -> fp16 hi/lo split -------------------------
__global__ __launch_bounds__(256) void decomp_A(const float* __restrict__ src,
                                                __half* __restrict__ hi,
                                                __half* __restrict__ lo)
{
    const int i = (blockIdx.x * 256 + threadIdx.x) * 4;
    float4 v = *(const float4*)(src + i);
    __half h0 = __float2half_rn(v.x);
    __half h1 = __float2half_rn(v.y);
    __half h2 = __float2half_rn(v.z);
    __half h3 = __float2half_rn(v.w);
    __half l0 = __float2half_rn(v.x - __half2float(h0));
    __half l1 = __float2half_rn(v.y - __half2float(h1));
    __half l2 = __float2half_rn(v.z - __half2float(h2));
    __half l3 = __float2half_rn(v.w - __half2float(h3));
    __half2 hA(h0, h1), hB(h2, h3), lA(l0, l1), lB(l2, l3);
    *(uint2*)(hi + i) = make_uint2(*(u32*)&hA, *(u32*)&hB);
    *(uint2*)(lo + i) = make_uint2(*(u32*)&lA, *(u32*)&lB);
}

// all three W [K,N] fp32 -> W^T fp16, z = matrix id
__global__ __launch_bounds__(256) void decomp_WT3(const float* __restrict__ Wq,
                                                  const float* __restrict__ Wk,
                                                  const float* __restrict__ W0)
{
    const int z = blockIdx.z;
    const float* W = (z == 0) ? Wq : (z == 1) ? Wk : W0;
    __half* hiT = g_WT[z];

    __shared__ float t[32][33];
    const int tx = threadIdx.x & 31, ty = threadIdx.x >> 5;   // (32, 8)
    const int n0 = blockIdx.x * 32, k0 = blockIdx.y * 32;
#pragma unroll
    for (int i = 0; i < 4; i++)
        t[ty + 8 * i][tx] = W[(k0 + ty + 8 * i) * D_MODEL + n0 + tx];
    __syncthreads();
#pragma unroll
    for (int i = 0; i < 4; i++) {
        float v = t[tx][ty + 8 * i];
        hiT[(long)(n0 + ty + 8 * i) * D_MODEL + k0 + tx] = __float2half_rn(v);
    }
}

// ---------------------------------------------------------------------------
// split-fp16 GEMM: C = (Ah [+ Al]) @ Wf + bias
// BM=128, BN=64, BK=32, 256 threads (8 warps 4x2), warp tile 32x32.
// 3-stage cp.async, 2 CTAs/SM.
//   MODE 1: row-major fp32 ; MODE 2: head layout, fp16 hi only
//   NPASS 1: Ah only ; NPASS 2: Ah + Al
// ---------------------------------------------------------------------------
#define ROWB  80                       // 64 data bytes + 16 pad
#define ATILE (128 * ROWB)             // 10240
#define BTILE (64 * ROWB)              // 5120
#define STAGE (2 * ATILE + BTILE)      // 25600 : [Ah][Al][B]
#define GSMEM (3 * STAGE)              // 76800

template <int MODE, int NPASS>
__device__ __forceinline__ void tc_gemm_body(const __half* __restrict__ Ah,
                                             const __half* __restrict__ Al,
                                             const __half* __restrict__ BT,
                                             const float* __restrict__ bias,
                                             float* __restrict__ out,
                                             __half* __restrict__ outh)
{
    extern __shared__ __align__(16) char smg[];
    const u32 sb = smem_u32(smg);

    const int tid = threadIdx.x;
    const int wid = tid >> 5;
    const int lane = tid & 31;
    const int warp_m = wid & 3;           // 0..3  (32 rows each)
    const int warp_n = wid >> 2;          // 0..1  (32 cols each)
    const int m0 = blockIdx.y * 128;
    const int n0 = blockIdx.x * 64;

    const int a_row = (lane & 15);
    const int a_kh  = (lane >> 4);
    const u32 aoff = (u32)((warp_m * 32 + a_row) * ROWB + a_kh * 16);
    const int b_row = (lane & 7) + ((lane >> 4) << 3);
    const int b_kh  = (lane >> 3) & 1;
    const u32 boff = (u32)((warp_n * 32 + b_row) * ROWB + b_kh * 16);

    float acc[2][4][4] = {};

    const __half* aS[2] = { Ah + ((long)m0 << 10), Al + ((long)m0 << 10) };
    const __half* bP = BT + ((long)n0 << 10);

    auto issue = [&](int kc, int p) {
        const u32 dst = sb + (u32)p * STAGE;
        const int row_b = tid >> 2, ch = tid & 3;
#pragma unroll
        for (int t = 0; t < NPASS; t++) {
#pragma unroll
            for (int i = 0; i < 2; i++) {
                const int f = i * 256 + tid;               // 0..511
                const int r = f >> 2, cc = f & 3;
                CP_ASYNC16(dst + t * ATILE + r * ROWB + cc * 16,
                           aS[t] + ((long)r << 10) + kc * 32 + cc * 8);
            }
        }
        CP_ASYNC16(dst + 2 * ATILE + row_b * ROWB + ch * 16,
                   bP + ((long)row_b << 10) + kc * 32 + ch * 8);
    };

    issue(0, 0); CP_COMMIT();
    issue(1, 1); CP_COMMIT();
    issue(2, 2); CP_COMMIT();

    for (int c = 0; c < 32; c++) {
        const int p = c - (c / 3) * 3;          // c % 3
        CP_WAIT2();
        __syncthreads();

        const u32 base = sb + (u32)p * STAGE;
#pragma unroll
        for (int ks = 0; ks < 2; ks++) {
            u32 ah[2][4], al[2][4];
#pragma unroll
            for (int mt = 0; mt < 2; mt++) {
                const u32 a = base + aoff + mt * (16 * ROWB) + ks * 32;
                ldsm_x4(ah[mt][0], ah[mt][1], ah[mt][2], ah[mt][3], a);
                if (NPASS == 2)
                    ldsm_x4(al[mt][0], al[mt][1], al[mt][2], al[mt][3], a + ATILE);
            }
            u32 bh[4][2];
#pragma unroll
            for (int nt2 = 0; nt2 < 2; nt2++) {
                u32 r0, r1, r2, r3;
                ldsm_x4(r0, r1, r2, r3,
                        base + 2 * ATILE + boff + nt2 * (16 * ROWB) + ks * 32);
                bh[nt2 * 2 + 0][0] = r0; bh[nt2 * 2 + 0][1] = r1;
                bh[nt2 * 2 + 1][0] = r2; bh[nt2 * 2 + 1][1] = r3;
            }
#pragma unroll
            for (int mt = 0; mt < 2; mt++)
#pragma unroll
                for (int nt = 0; nt < 4; nt++)
                    mma16816(acc[mt][nt], ah[mt][0], ah[mt][1], ah[mt][2], ah[mt][3],
                             bh[nt][0], bh[nt][1]);
            if (NPASS == 2) {
#pragma unroll
                for (int mt = 0; mt < 2; mt++)
#pragma unroll
                    for (int nt = 0; nt < 4; nt++)
                        mma16816(acc[mt][nt], al[mt][0], al[mt][1], al[mt][2], al[mt][3],
                                 bh[nt][0], bh[nt][1]);
            }
        }
        __syncthreads();
        if (c + 3 < 32) issue(c + 3, p);
        CP_COMMIT();
    }

    // epilogue
#pragma unroll
    for (int mt = 0; mt < 2; mt++) {
#pragma unroll
        for (int nt = 0; nt < 4; nt++) {
            const int m = m0 + warp_m * 32 + mt * 16 + (lane >> 2);
            const int n = n0 + warp_n * 32 + nt * 8 + (lane & 3) * 2;
            const float bx = bias[n], by = bias[n + 1];
#pragma unroll
            for (int half = 0; half < 2; half++) {
                const int mm = m + half * 8;
                const float vx = acc[mt][nt][half * 2 + 0] + bx;
                const float vy = acc[mt][nt][half * 2 + 1] + by;
                if (MODE == 1) {
                    *(float2*)&out[(long)mm * D_MODEL + n] = make_float2(vx, vy);
                } else {
                    const int b = mm >> 11, s = mm & 2047;
                    const int hd = n >> 6, dk = n & 63;
                    const long o = (((long)(b * NHEAD + hd) * S_LEN + s) << 6) + dk;
                    *(u32*)&outh[o] = cvt2h(vx, vy);
                }
            }
        }
    }
}

__global__ __launch_bounds__(256, 2) void qk_gemm_tc(const float* __restrict__ bq,
                                                     const float* __restrict__ bk)
{
    if (blockIdx.z == 0)   // Q (=V): single-pass, fp16 out
        tc_gemm_body<2, 1>(g_Ah, g_Al, g_WT[0], bq, nullptr, g_Qh);
    else                   // K: single-pass, fp16 out
        tc_gemm_body<2, 1>(g_Ah, g_Al, g_WT[1], bk, nullptr, g_Kh);
}

__global__ __launch_bounds__(256, 2) void out_gemm_tc(const float* __restrict__ b0,
                                                      float* __restrict__ out)
{
    tc_gemm_body<1, 2>(g_Ah, g_Al, g_WT[2], b0, out, nullptr);
}

// ---------------------------------------------------------------------------
// Flash attention on mma.sync fp16, causal, V = Q.
// S-phase: single pass Qh·Kh. PV-phase: P fp16 x V fp16 (single sweep).
// smem: [Qh tile][2 x (Kh, Vh)] -- 5 tiles.
// Output written fp16 hi+lo into g_Ah/g_Al (out-projection keeps 2-pass).
// ---------------------------------------------------------------------------
#define PITCH   144
#define TILE_B  (128 * PITCH)          // 18432
#define OFF_KV0 (TILE_B)
#define KV_SZ   (2 * TILE_B)
#define AT_SMEM (OFF_KV0 + 2 * KV_SZ)  // 92160

#define SCALE_LOG2 0.18033688011112043f   // (1/8) * log2(e)

__global__ __launch_bounds__(256, 1) void attn_tc()
{
    extern __shared__ char smc[];
    const u32 sb = smem_u32(smc);
    const int tid  = threadIdx.x;
    const int lane = tid & 31;
    const int w    = tid >> 5;
    const int qi = (int)gridDim.x - 1 - (int)blockIdx.x;
    const int bh = blockIdx.y;

    const int lrow = lane & 15;
    const int lch  = lane >> 4;
    const int rlo  = w * 16 + (lane >> 2);
    const int rhi  = rlo + 8;

    {
        const long qb = ((long)bh * S_LEN + (long)qi * 128) * DKH;
#pragma unroll
        for (int i = 0; i < 4; i++) {
            const int idx = i * 256 + tid;
            const int r = idx >> 3, c = idx & 7;
            CP_ASYNC16(sb + r * PITCH + c * 16, g_Qh + qb + r * 64 + c * 8);
        }
        const long kb = ((long)bh * S_LEN) * DKH;   // j = 0
#pragma unroll
        for (int i = 0; i < 8; i++) {
            const int t = i >> 2;                   // 0:Kh 1:Vh(=Qh)
            const int idx = (i & 3) * 256 + tid;
            const int r = idx >> 3, c = idx & 7;
            const __half* src = (t == 0 ? g_Kh : g_Qh) + kb + r * 64 + c * 8;
            CP_ASYNC16(sb + OFF_KV0 + t * TILE_B + r * PITCH + c * 16, src);
        }
        CP_COMMIT();
    }

    u32 aQh[4][4];
    float o_[8][4] = {};
    float mst0 = -1e30f, mst1 = -1e30f;
    float lst0 = 0.0f, lst1 = 0.0f;

    for (int j = 0; j <= qi; j++) {
        CP_WAIT0();
        __syncthreads();
        const u32 buf = sb + OFF_KV0 + (u32)(j & 1) * KV_SZ;

        if (j == 0) {
#pragma unroll
            for (int s = 0; s < 4; s++) {
                const u32 a = (u32)((w * 16 + lrow) * PITCH + s * 32 + lch * 16);
                ldsm_x4(aQh[s][0], aQh[s][1], aQh[s][2], aQh[s][3], sb + a);
            }
        }
        if (j < qi) {
            const long kb = ((long)bh * S_LEN + (long)(j + 1) * 128) * DKH;
            const u32 nbuf = sb + OFF_KV0 + (u32)((j + 1) & 1) * KV_SZ;
#pragma unroll
            for (int i = 0; i < 8; i++) {
                const int t = i >> 2;
                const int idx = (i & 3) * 256 + tid;
                const int r = idx >> 3, c = idx & 7;
                const __half* src = (t == 0 ? g_Kh : g_Qh) + kb + r * 64 + c * 8;
                CP_ASYNC16(nbuf + t * TILE_B + r * PITCH + c * 16, src);
            }
            CP_COMMIT();
        }

        // ---- S = Qh Kh^T : single pass ----
        float s_[16][4] = {};
        const u32 bbase = buf + (u32)(lrow * PITCH + lch * 16);

#pragma unroll
        for (int ks = 0; ks < 4; ks++) {
            const u32 tb = bbase + ks * 32;
#pragma unroll
            for (int nc = 0; nc < 8; nc++) {
                u32 h0, h1, h2, h3;
                ldsm_x4(h0, h1, h2, h3, tb + nc * (16 * PITCH));
                mma16816(s_[2 * nc],     aQh[ks][0], aQh[ks][1], aQh[ks][2], aQh[ks][3], h0, h2);
                mma16816(s_[2 * nc + 1], aQh[ks][0], aQh[ks][1], aQh[ks][2], aQh[ks][3], h1, h3);
            }
        }

        // ---- online softmax (log2 domain) ----
        float rmx0 = -1e30f, rmx1 = -1e30f;
#pragma unroll
        for (int nt = 0; nt < 16; nt++) {
#pragma unroll
            for (int q = 0; q < 4; q++) s_[nt][q] *= SCALE_LOG2;
            if (j == qi) {
                const int c0 = nt * 8 + (lane & 3) * 2;
                if (c0 > rlo)     s_[nt][0] = -1e30f;
                if (c0 + 1 > rlo) s_[nt][1] = -1e30f;
                if (c0 > rhi)     s_[nt][2] = -1e30f;
                if (c0 + 1 > rhi) s_[nt][3] = -1e30f;
            }
            rmx0 = fmaxf(rmx0, fmaxf(s_[nt][0], s_[nt][1]));
            rmx1 = fmaxf(rmx1, fmaxf(s_[nt][2], s_[nt][3]));
        }
        rmx0 = fmaxf(rmx0, __shfl_xor_sync(0xffffffffu, rmx0, 1));
        rmx0 = fmaxf(rmx0, __shfl_xor_sync(0xffffffffu, rmx0, 2));
        rmx1 = fmaxf(rmx1, __shfl_xor_sync(0xffffffffu, rmx1, 1));
        rmx1 = fmaxf(rmx1, __shfl_xor_sync(0xffffffffu, rmx1, 2));
        const float mn0 = fmaxf(mst0, rmx0);
        const float mn1 = fmaxf(mst1, rmx1);
        const float al0 = ex2(mst0 - mn0);
        const float al1 = ex2(mst1 - mn1);
        float sum0 = 0.0f, sum1 = 0.0f;
#pragma unroll
        for (int nt = 0; nt < 16; nt++) {
            s_[nt][0] = ex2(s_[nt][0] - mn0);
            s_[nt][1] = ex2(s_[nt][1] - mn0);
            s_[nt][2] = ex2(s_[nt][2] - mn1);
            s_[nt][3] = ex2(s_[nt][3] - mn1);
            sum0 += s_[nt][0] + s_[nt][1];
            sum1 += s_[nt][2] + s_[nt][3];
        }
        sum0 += __shfl_xor_sync(0xffffffffu, sum0, 1);
        sum0 += __shfl_xor_sync(0xffffffffu, sum0, 2);
        sum1 += __shfl_xor_sync(0xffffffffu, sum1, 1);
        sum1 += __shfl_xor_sync(0xffffffffu, sum1, 2);
        lst0 = lst0 * al0 + sum0;
        lst1 = lst1 * al1 + sum1;
        mst0 = mn0;
        mst1 = mn1;
#pragma unroll
        for (int nt = 0; nt < 8; nt++) {
            o_[nt][0] *= al0; o_[nt][1] *= al0;
            o_[nt][2] *= al1; o_[nt][3] *= al1;
        }

        // ---- O += P V : P fp16, V fp16 single sweep ----
        const u32 vh_b = buf + TILE_B;
#pragma unroll
        for (int s = 0; s < 8; s++) {
            u32 pf[4];
            pf[0] = cvt2h(s_[2 * s][0], s_[2 * s][1]);
            pf[1] = cvt2h(s_[2 * s][2], s_[2 * s][3]);
            pf[2] = cvt2h(s_[2 * s + 1][0], s_[2 * s + 1][1]);
            pf[3] = cvt2h(s_[2 * s + 1][2], s_[2 * s + 1][3]);

            u32 vh_[8][2];
#pragma unroll
            for (int tp = 0; tp < 4; tp++) {
                const u32 a = vh_b + (u32)((s * 16 + lrow) * PITCH + (tp * 2 + lch) * 16);
                u32 r0, r1, r2, r3;
                ldsm_x4t(r0, r1, r2, r3, a);
                vh_[2 * tp][0] = r0; vh_[2 * tp][1] = r1;
                vh_[2 * tp + 1][0] = r2; vh_[2 * tp + 1][1] = r3;
            }
#pragma unroll
            for (int nt = 0; nt < 8; nt++)
                mma16816(o_[nt], pf[0], pf[1], pf[2], pf[3], vh_[nt][0], vh_[nt][1]);
        }
    }

    const int bat = bh >> 4, head = bh & 15;
    const float i0 = 1.0f / lst0;
    const float i1 = 1.0f / lst1;
    const int row0 = qi * 128 + rlo;
#pragma unroll
    for (int nt = 0; nt < 8; nt++) {
        const int d = head * 64 + nt * 8 + (lane & 3) * 2;
        {
            const float x = o_[nt][0] * i0, y = o_[nt][1] * i0;
            const u32 hh = cvt2h(x, y), ll = resid2h(hh, x, y);
            const long a = ((long)(bat * S_LEN + row0) << 10) + d;
            *(u32*)&g_Ah[a] = hh;
            *(u32*)&g_Al[a] = ll;
        }
        {
            const float x = o_[nt][2] * i1, y = o_[nt][3] * i1;
            const u32 hh = cvt2h(x, y), ll = resid2h(hh, x, y);
            const long a = ((long)(bat * S_LEN + row0 + 8) << 10) + d;
            *(u32*)&g_Ah[a] = hh;
            *(u32*)&g_Al[a] = ll;
        }
    }
}

// ---------------------------------------------------------------------------
extern "C" void kernel_launch(void* const* d_in, const int* in_sizes, int n_in,
                              void* d_out, int out_size)
{
    const float* x  = (const float*)d_in[0];
    const float* Wq = (const float*)d_in[1];
    const float* bq = (const float*)d_in[2];
    const float* Wk = (const float*)d_in[3];
    const float* bk = (const float*)d_in[4];
    const float* W0 = (const float*)d_in[5];
    const float* b0 = (const float*)d_in[6];
    float* out = (float*)d_out;

    __half *dAh, *dAl;
    cudaGetSymbolAddress((void**)&dAh, g_Ah);
    cudaGetSymbolAddress((void**)&dAl, g_Al);

    cudaFuncSetAttribute(attn_tc, cudaFuncAttributeMaxDynamicSharedMemorySize, AT_SMEM);
    cudaFuncSetAttribute(qk_gemm_tc, cudaFuncAttributeMaxDynamicSharedMemorySize, GSMEM);
    cudaFuncSetAttribute(out_gemm_tc, cudaFuncAttributeMaxDynamicSharedMemorySize, GSMEM);

    // 1) decompose x (hi/lo) and weights (fp16)
    decomp_A<<<M_TOK * D_MODEL / 1024, 256>>>(x, dAh, dAl);
    dim3 wt_grid(32, 32, 3);
    decomp_WT3<<<wt_grid, 256>>>(Wq, Wk, W0);

    // 2) Q & K projections (both single-pass) -> fp16 head layout
    dim3 qk_grid(D_MODEL / 64, M_TOK / 128, 2);    // (16, 32, 2)
    qk_gemm_tc<<<qk_grid, 256, GSMEM>>>(bq, bk);

    // 3) attention (tensor cores) -> g_Ah/g_Al (hi+lo)
    dim3 attn_grid(S_LEN / 128, BATCH * NHEAD);     // (16, 32)
    attn_tc<<<attn_grid, 256, AT_SMEM>>>();

    // 4) output projection (2-pass, output-critical)
    dim3 o_grid(D_MODEL / 64, M_TOK / 128);         // (16, 32)
    out_gemm_tc<<<o_grid, 256, GSMEM>>>(b0, out);
}

// round 13
// speedup vs baseline: 6.4050x; 1.1774x over previous
#include <cuda_runtime.h>
#include <cuda_fp16.h>

#define S_LEN   2048
#define D_MODEL 1024
#define NHEAD   16
#define DKH     64
#define BATCH   2
#define M_TOK   (BATCH * S_LEN)   // 4096

typedef unsigned long long u64;
typedef unsigned int u32;

#define SCALE_LOG2 0.18033688011112043f   // (1/8) * log2(e)  (folded into K)

// ------------------------------- scratch -----------------------------------
__device__ __half g_Qh[BATCH * NHEAD * S_LEN * DKH];  // [B,H,S,DK] Q (=V) fp16
__device__ __half g_Kh[BATCH * NHEAD * S_LEN * DKH];  // K fp16 (pre-scaled)
__device__ __half g_Ah[M_TOK * D_MODEL];              // A fp16 (x, then att)
__device__ __half g_WT[3][D_MODEL * D_MODEL];         // W^T fp16: q,k,o

// --------------------------- small helpers ---------------------------------
__device__ __forceinline__ u32 smem_u32(const void* p) {
    u32 a; asm("{ .reg .u64 t; cvta.to.shared.u64 t, %1; cvt.u32.u64 %0, t; }" : "=r"(a) : "l"(p));
    return a;
}

#define CP_ASYNC16(dst, src) \
    asm volatile("cp.async.cg.shared.global [%0], [%1], 16;" :: "r"(dst), "l"(src))
#define CP_COMMIT()  asm volatile("cp.async.commit_group;" ::: "memory")
#define CP_WAIT2()   asm volatile("cp.async.wait_group 2;" ::: "memory")
#define CP_WAIT0()   asm volatile("cp.async.wait_group 0;" ::: "memory")

__device__ __forceinline__ void ldsm_x4(u32& r0, u32& r1, u32& r2, u32& r3, u32 addr) {
    asm volatile("ldmatrix.sync.aligned.m8n8.x4.shared.b16 {%0,%1,%2,%3}, [%4];"
                 : "=r"(r0), "=r"(r1), "=r"(r2), "=r"(r3) : "r"(addr));
}
__device__ __forceinline__ void ldsm_x4t(u32& r0, u32& r1, u32& r2, u32& r3, u32 addr) {
    asm volatile("ldmatrix.sync.aligned.m8n8.x4.trans.shared.b16 {%0,%1,%2,%3}, [%4];"
                 : "=r"(r0), "=r"(r1), "=r"(r2), "=r"(r3) : "r"(addr));
}

__device__ __forceinline__ void mma16816(float* d, u32 a0, u32 a1, u32 a2, u32 a3,
                                         u32 b0, u32 b1) {
    asm volatile("mma.sync.aligned.m16n8k16.row.col.f32.f16.f16.f32 "
                 "{%0,%1,%2,%3}, {%4,%5,%6,%7}, {%8,%9}, {%0,%1,%2,%3};"
                 : "+f"(d[0]), "+f"(d[1]), "+f"(d[2]), "+f"(d[3])
                 : "r"(a0), "r"(a1), "r"(a2), "r"(a3), "r"(b0), "r"(b1));
}

__device__ __forceinline__ float ex2(float x) {
    float y; asm("ex2.approx.f32 %0, %1;" : "=f"(y) : "f"(x)); return y;
}

__device__ __forceinline__ u32 cvt2h(float x, float y) {
    __half2 t = __floats2half2_rn(x, y);
    return *reinterpret_cast<u32*>(&t);
}

// ------------------------- fp32 -> fp16 convert -----------------------------
__global__ __launch_bounds__(256) void conv_A(const float* __restrict__ src,
                                              __half* __restrict__ hi)
{
    const int i = (blockIdx.x * 256 + threadIdx.x) * 4;
    float4 v = *(const float4*)(src + i);
    __half2 hA = __floats2half2_rn(v.x, v.y);
    __half2 hB = __floats2half2_rn(v.z, v.w);
    *(uint2*)(hi + i) = make_uint2(*(u32*)&hA, *(u32*)&hB);
}

// all three W [K,N] fp32 -> W^T fp16; K's weight pre-scaled by SCALE_LOG2
__global__ __launch_bounds__(256) void decomp_WT3(const float* __restrict__ Wq,
                                                  const float* __restrict__ Wk,
                                                  const float* __restrict__ W0)
{
    const int z = blockIdx.z;
    const float* W = (z == 0) ? Wq : (z == 1) ? Wk : W0;
    const float scl = (z == 1) ? SCALE_LOG2 : 1.0f;
    __half* hiT = g_WT[z];

    __shared__ float t[32][33];
    const int tx = threadIdx.x & 31, ty = threadIdx.x >> 5;   // (32, 8)
    const int n0 = blockIdx.x * 32, k0 = blockIdx.y * 32;
#pragma unroll
    for (int i = 0; i < 4; i++)
        t[ty + 8 * i][tx] = W[(k0 + ty + 8 * i) * D_MODEL + n0 + tx];
    __syncthreads();
#pragma unroll
    for (int i = 0; i < 4; i++) {
        float v = t[tx][ty + 8 * i] * scl;
        hiT[(long)(n0 + ty + 8 * i) * D_MODEL + k0 + tx] = __float2half_rn(v);
    }
}

// ---------------------------------------------------------------------------
// fp16 GEMM: C = A @ Wf + bias*bscale   (single pass)
// BM=128, BN=64, BK=32, 256 threads (8 warps 4x2), warp tile 32x32.
// 3-stage cp.async, 2 CTAs/SM.
//   MODE 1: row-major fp32 ; MODE 2: head layout, fp16
// ---------------------------------------------------------------------------
#define ROWB  80                       // 64 data bytes + 16 pad
#define ATILE (128 * ROWB)             // 10240
#define BTILE (64 * ROWB)              // 5120
#define STAGE (ATILE + BTILE)          // 15360 : [A][B]
#define GSMEM (3 * STAGE)              // 46080

template <int MODE>
__device__ __forceinline__ void tc_gemm_body(const __half* __restrict__ Ah,
                                             const __half* __restrict__ BT,
                                             const float* __restrict__ bias,
                                             float bscale,
                                             float* __restrict__ out,
                                             __half* __restrict__ outh)
{
    extern __shared__ __align__(16) char smg[];
    const u32 sb = smem_u32(smg);

    const int tid = threadIdx.x;
    const int wid = tid >> 5;
    const int lane = tid & 31;
    const int warp_m = wid & 3;           // 0..3  (32 rows each)
    const int warp_n = wid >> 2;          // 0..1  (32 cols each)
    const int m0 = blockIdx.y * 128;
    const int n0 = blockIdx.x * 64;

    const int a_row = (lane & 15);
    const int a_kh  = (lane >> 4);
    const u32 aoff = (u32)((warp_m * 32 + a_row) * ROWB + a_kh * 16);
    const int b_row = (lane & 7) + ((lane >> 4) << 3);
    const int b_kh  = (lane >> 3) & 1;
    const u32 boff = (u32)((warp_n * 32 + b_row) * ROWB + b_kh * 16);

    float acc[2][4][4] = {};

    const __half* aP = Ah + ((long)m0 << 10);
    const __half* bP = BT + ((long)n0 << 10);

    auto issue = [&](int kc, int p) {
        const u32 dst = sb + (u32)p * STAGE;
        const int row_b = tid >> 2, ch = tid & 3;
#pragma unroll
        for (int i = 0; i < 2; i++) {
            const int f = i * 256 + tid;               // 0..511
            const int r = f >> 2, cc = f & 3;
            CP_ASYNC16(dst + r * ROWB + cc * 16,
                       aP + ((long)r << 10) + kc * 32 + cc * 8);
        }
        CP_ASYNC16(dst + ATILE + row_b * ROWB + ch * 16,
                   bP + ((long)row_b << 10) + kc * 32 + ch * 8);
    };

    issue(0, 0); CP_COMMIT();
    issue(1, 1); CP_COMMIT();
    issue(2, 2); CP_COMMIT();

    for (int c = 0; c < 32; c++) {
        const int p = c - (c / 3) * 3;          // c % 3
        CP_WAIT2();
        __syncthreads();

        const u32 base = sb + (u32)p * STAGE;
#pragma unroll
        for (int ks = 0; ks < 2; ks++) {
            u32 ah[2][4];
#pragma unroll
            for (int mt = 0; mt < 2; mt++) {
                const u32 a = base + aoff + mt * (16 * ROWB) + ks * 32;
                ldsm_x4(ah[mt][0], ah[mt][1], ah[mt][2], ah[mt][3], a);
            }
            u32 bh[4][2];
#pragma unroll
            for (int nt2 = 0; nt2 < 2; nt2++) {
                u32 r0, r1, r2, r3;
                ldsm_x4(r0, r1, r2, r3,
                        base + ATILE + boff + nt2 * (16 * ROWB) + ks * 32);
                bh[nt2 * 2 + 0][0] = r0; bh[nt2 * 2 + 0][1] = r1;
                bh[nt2 * 2 + 1][0] = r2; bh[nt2 * 2 + 1][1] = r3;
            }
#pragma unroll
            for (int mt = 0; mt < 2; mt++)
#pragma unroll
                for (int nt = 0; nt < 4; nt++)
                    mma16816(acc[mt][nt], ah[mt][0], ah[mt][1], ah[mt][2], ah[mt][3],
                             bh[nt][0], bh[nt][1]);
        }
        __syncthreads();
        if (c + 3 < 32) issue(c + 3, p);
        CP_COMMIT();
    }

    // epilogue
#pragma unroll
    for (int mt = 0; mt < 2; mt++) {
#pragma unroll
        for (int nt = 0; nt < 4; nt++) {
            const int m = m0 + warp_m * 32 + mt * 16 + (lane >> 2);
            const int n = n0 + warp_n * 32 + nt * 8 + (lane & 3) * 2;
            const float bx = bias[n] * bscale, by = bias[n + 1] * bscale;
#pragma unroll
            for (int half = 0; half < 2; half++) {
                const int mm = m + half * 8;
                const float vx = acc[mt][nt][half * 2 + 0] + bx;
                const float vy = acc[mt][nt][half * 2 + 1] + by;
                if (MODE == 1) {
                    *(float2*)&out[(long)mm * D_MODEL + n] = make_float2(vx, vy);
                } else {
                    const int b = mm >> 11, s = mm & 2047;
                    const int hd = n >> 6, dk = n & 63;
                    const long o = (((long)(b * NHEAD + hd) * S_LEN + s) << 6) + dk;
                    *(u32*)&outh[o] = cvt2h(vx, vy);
                }
            }
        }
    }
}

__global__ __launch_bounds__(256, 2) void qk_gemm_tc(const float* __restrict__ bq,
                                                     const float* __restrict__ bk)
{
    if (blockIdx.z == 0)   // Q (=V)
        tc_gemm_body<2>(g_Ah, g_WT[0], bq, 1.0f, nullptr, g_Qh);
    else                   // K (weight & bias pre-scaled by SCALE_LOG2)
        tc_gemm_body<2>(g_Ah, g_WT[1], bk, SCALE_LOG2, nullptr, g_Kh);
}

__global__ __launch_bounds__(256, 2) void out_gemm_tc(const float* __restrict__ b0,
                                                      float* __restrict__ out)
{
    tc_gemm_body<1>(g_Ah, g_WT[2], b0, 1.0f, out, nullptr);
}

// ---------------------------------------------------------------------------
// Flash attention on mma.sync fp16, causal, V = Q.
// S = Qh Kh^T already in log2 softmax domain (scale folded into K).
// PV single sweep. Output written single fp16 into g_Ah.
// smem: [Qh tile][2 x (Kh, Vh)] -- 5 tiles, 92 KB.
// ---------------------------------------------------------------------------
#define PITCH   144
#define TILE_B  (128 * PITCH)          // 18432
#define OFF_KV0 (TILE_B)
#define KV_SZ   (2 * TILE_B)
#define AT_SMEM (OFF_KV0 + 2 * KV_SZ)  // 92160

__global__ __launch_bounds__(256, 1) void attn_tc()
{
    extern __shared__ char smc[];
    const u32 sb = smem_u32(smc);
    const int tid  = threadIdx.x;
    const int lane = tid & 31;
    const int w    = tid >> 5;
    const int qi = (int)gridDim.x - 1 - (int)blockIdx.x;
    const int bh = blockIdx.y;

    const int lrow = lane & 15;
    const int lch  = lane >> 4;
    const int rlo  = w * 16 + (lane >> 2);
    const int rhi  = rlo + 8;

    {
        const long qb = ((long)bh * S_LEN + (long)qi * 128) * DKH;
#pragma unroll
        for (int i = 0; i < 4; i++) {
            const int idx = i * 256 + tid;
            const int r = idx >> 3, c = idx & 7;
            CP_ASYNC16(sb + r * PITCH + c * 16, g_Qh + qb + r * 64 + c * 8);
        }
        const long kb = ((long)bh * S_LEN) * DKH;   // j = 0
#pragma unroll
        for (int i = 0; i < 8; i++) {
            const int t = i >> 2;                   // 0:Kh 1:Vh(=Qh)
            const int idx = (i & 3) * 256 + tid;
            const int r = idx >> 3, c = idx & 7;
            const __half* src = (t == 0 ? g_Kh : g_Qh) + kb + r * 64 + c * 8;
            CP_ASYNC16(sb + OFF_KV0 + t * TILE_B + r * PITCH + c * 16, src);
        }
        CP_COMMIT();
    }

    u32 aQh[4][4];
    float o_[8][4] = {};
    float mst0 = -1e30f, mst1 = -1e30f;
    float lst0 = 0.0f, lst1 = 0.0f;

    for (int j = 0; j <= qi; j++) {
        CP_WAIT0();
        __syncthreads();
        const u32 buf = sb + OFF_KV0 + (u32)(j & 1) * KV_SZ;

        if (j == 0) {
#pragma unroll
            for (int s = 0; s < 4; s++) {
                const u32 a = (u32)((w * 16 + lrow) * PITCH + s * 32 + lch * 16);
                ldsm_x4(aQh[s][0], aQh[s][1], aQh[s][2], aQh[s][3], sb + a);
            }
        }
        if (j < qi) {
            const long kb = ((long)bh * S_LEN + (long)(j + 1) * 128) * DKH;
            const u32 nbuf = sb + OFF_KV0 + (u32)((j + 1) & 1) * KV_SZ;
#pragma unroll
            for (int i = 0; i < 8; i++) {
                const int t = i >> 2;
                const int idx = (i & 3) * 256 + tid;
                const int r = idx >> 3, c = idx & 7;
                const __half* src = (t == 0 ? g_Kh : g_Qh) + kb + r * 64 + c * 8;
                CP_ASYNC16(nbuf + t * TILE_B + r * PITCH + c * 16, src);
            }
            CP_COMMIT();
        }

        // ---- S = Qh Kh^T (already log2-scaled) ----
        float s_[16][4] = {};
        const u32 bbase = buf + (u32)(lrow * PITCH + lch * 16);

#pragma unroll
        for (int ks = 0; ks < 4; ks++) {
            const u32 tb = bbase + ks * 32;
#pragma unroll
            for (int nc = 0; nc < 8; nc++) {
                u32 h0, h1, h2, h3;
                ldsm_x4(h0, h1, h2, h3, tb + nc * (16 * PITCH));
                mma16816(s_[2 * nc],     aQh[ks][0], aQh[ks][1], aQh[ks][2], aQh[ks][3], h0, h2);
                mma16816(s_[2 * nc + 1], aQh[ks][0], aQh[ks][1], aQh[ks][2], aQh[ks][3], h1, h3);
            }
        }

        // ---- online softmax (log2 domain, no scale multiply) ----
        float rmx0 = -1e30f, rmx1 = -1e30f;
#pragma unroll
        for (int nt = 0; nt < 16; nt++) {
            if (j == qi) {
                const int c0 = nt * 8 + (lane & 3) * 2;
                if (c0 > rlo)     s_[nt][0] = -1e30f;
                if (c0 + 1 > rlo) s_[nt][1] = -1e30f;
                if (c0 > rhi)     s_[nt][2] = -1e30f;
                if (c0 + 1 > rhi) s_[nt][3] = -1e30f;
            }
            rmx0 = fmaxf(rmx0, fmaxf(s_[nt][0], s_[nt][1]));
            rmx1 = fmaxf(rmx1, fmaxf(s_[nt][2], s_[nt][3]));
        }
        rmx0 = fmaxf(rmx0, __shfl_xor_sync(0xffffffffu, rmx0, 1));
        rmx0 = fmaxf(rmx0, __shfl_xor_sync(0xffffffffu, rmx0, 2));
        rmx1 = fmaxf(rmx1, __shfl_xor_sync(0xffffffffu, rmx1, 1));
        rmx1 = fmaxf(rmx1, __shfl_xor_sync(0xffffffffu, rmx1, 2));
        const float mn0 = fmaxf(mst0, rmx0);
        const float mn1 = fmaxf(mst1, rmx1);
        const float al0 = ex2(mst0 - mn0);
        const float al1 = ex2(mst1 - mn1);
        float sum0 = 0.0f, sum1 = 0.0f;
#pragma unroll
        for (int nt = 0; nt < 16; nt++) {
            s_[nt][0] = ex2(s_[nt][0] - mn0);
            s_[nt][1] = ex2(s_[nt][1] - mn0);
            s_[nt][2] = ex2(s_[nt][2] - mn1);
            s_[nt][3] = ex2(s_[nt][3] - mn1);
            sum0 += s_[nt][0] + s_[nt][1];
            sum1 += s_[nt][2] + s_[nt][3];
        }
        sum0 += __shfl_xor_sync(0xffffffffu, sum0, 1);
        sum0 += __shfl_xor_sync(0xffffffffu, sum0, 2);
        sum1 += __shfl_xor_sync(0xffffffffu, sum1, 1);
        sum1 += __shfl_xor_sync(0xffffffffu, sum1, 2);
        lst0 = lst0 * al0 + sum0;
        lst1 = lst1 * al1 + sum1;
        mst0 = mn0;
        mst1 = mn1;
#pragma unroll
        for (int nt = 0; nt < 8; nt++) {
            o_[nt][0] *= al0; o_[nt][1] *= al0;
            o_[nt][2] *= al1; o_[nt][3] *= al1;
        }

        // ---- O += P V : P fp16, V fp16 single sweep ----
        const u32 vh_b = buf + TILE_B;
#pragma unroll
        for (int s = 0; s < 8; s++) {
            u32 pf[4];
            pf[0] = cvt2h(s_[2 * s][0], s_[2 * s][1]);
            pf[1] = cvt2h(s_[2 * s][2], s_[2 * s][3]);
            pf[2] = cvt2h(s_[2 * s + 1][0], s_[2 * s + 1][1]);
            pf[3] = cvt2h(s_[2 * s + 1][2], s_[2 * s + 1][3]);

            u32 vh_[8][2];
#pragma unroll
            for (int tp = 0; tp < 4; tp++) {
                const u32 a = vh_b + (u32)((s * 16 + lrow) * PITCH + (tp * 2 + lch) * 16);
                u32 r0, r1, r2, r3;
                ldsm_x4t(r0, r1, r2, r3, a);
                vh_[2 * tp][0] = r0; vh_[2 * tp][1] = r1;
                vh_[2 * tp + 1][0] = r2; vh_[2 * tp + 1][1] = r3;
            }
#pragma unroll
            for (int nt = 0; nt < 8; nt++)
                mma16816(o_[nt], pf[0], pf[1], pf[2], pf[3], vh_[nt][0], vh_[nt][1]);
        }
    }

    const int bat = bh >> 4, head = bh & 15;
    const float i0 = 1.0f / lst0;
    const float i1 = 1.0f / lst1;
    const int row0 = qi * 128 + rlo;
#pragma unroll
    for (int nt = 0; nt < 8; nt++) {
        const int d = head * 64 + nt * 8 + (lane & 3) * 2;
        {
            const long a = ((long)(bat * S_LEN + row0) << 10) + d;
            *(u32*)&g_Ah[a] = cvt2h(o_[nt][0] * i0, o_[nt][1] * i0);
        }
        {
            const long a = ((long)(bat * S_LEN + row0 + 8) << 10) + d;
            *(u32*)&g_Ah[a] = cvt2h(o_[nt][2] * i1, o_[nt][3] * i1);
        }
    }
}

// ---------------------------------------------------------------------------
extern "C" void kernel_launch(void* const* d_in, const int* in_sizes, int n_in,
                              void* d_out, int out_size)
{
    const float* x  = (const float*)d_in[0];
    const float* Wq = (const float*)d_in[1];
    const float* bq = (const float*)d_in[2];
    const float* Wk = (const float*)d_in[3];
    const float* bk = (const float*)d_in[4];
    const float* W0 = (const float*)d_in[5];
    const float* b0 = (const float*)d_in[6];
    float* out = (float*)d_out;

    __half* dAh;
    cudaGetSymbolAddress((void**)&dAh, g_Ah);

    cudaFuncSetAttribute(attn_tc, cudaFuncAttributeMaxDynamicSharedMemorySize, AT_SMEM);
    cudaFuncSetAttribute(qk_gemm_tc, cudaFuncAttributeMaxDynamicSharedMemorySize, GSMEM);
    cudaFuncSetAttribute(out_gemm_tc, cudaFuncAttributeMaxDynamicSharedMemorySize, GSMEM);

    // 1) convert x -> fp16, weights -> fp16^T (K pre-scaled)
    conv_A<<<M_TOK * D_MODEL / 1024, 256>>>(x, dAh);
    dim3 wt_grid(32, 32, 3);
    decomp_WT3<<<wt_grid, 256>>>(Wq, Wk, W0);

    // 2) Q & K projections (single-pass) -> fp16 head layout
    dim3 qk_grid(D_MODEL / 64, M_TOK / 128, 2);    // (16, 32, 2)
    qk_gemm_tc<<<qk_grid, 256, GSMEM>>>(bq, bk);

    // 3) attention -> g_Ah (fp16)
    dim3 attn_grid(S_LEN / 128, BATCH * NHEAD);     // (16, 32)
    attn_tc<<<attn_grid, 256, AT_SMEM>>>();

    // 4) output projection (single-pass)
    dim3 o_grid(D_MODEL / 64, M_TOK / 128);         // (16, 32)
    out_gemm_tc<<<o_grid, 256, GSMEM>>>(b0, out);
}

// round 14
// speedup vs baseline: 6.6434x; 1.0372x over previous
#include <cuda_runtime.h>
#include <cuda_fp16.h>

#define S_LEN   2048
#define D_MODEL 1024
#define NHEAD   16
#define DKH     64
#define BATCH   2
#define M_TOK   (BATCH * S_LEN)   // 4096

typedef unsigned long long u64;
typedef unsigned int u32;

#define SCALE_LOG2 0.18033688011112043f   // (1/8) * log2(e)  (folded into K)

// ------------------------------- scratch -----------------------------------
__device__ __half g_Qh[BATCH * NHEAD * S_LEN * DKH];  // [B,H,S,DK] Q (=V) fp16
__device__ __half g_Kh[BATCH * NHEAD * S_LEN * DKH];  // K fp16 (pre-scaled)
__device__ __half g_Ah[M_TOK * D_MODEL];              // A fp16 (x, then att)
__device__ __half g_WT[3][D_MODEL * D_MODEL];         // W^T fp16: q,k,o

// --------------------------- small helpers ---------------------------------
__device__ __forceinline__ u32 smem_u32(const void* p) {
    u32 a; asm("{ .reg .u64 t; cvta.to.shared.u64 t, %1; cvt.u32.u64 %0, t; }" : "=r"(a) : "l"(p));
    return a;
}

#define CP_ASYNC16(dst, src) \
    asm volatile("cp.async.cg.shared.global [%0], [%1], 16;" :: "r"(dst), "l"(src))
#define CP_COMMIT()  asm volatile("cp.async.commit_group;" ::: "memory")
#define CP_WAIT2()   asm volatile("cp.async.wait_group 2;" ::: "memory")
#define CP_WAIT0()   asm volatile("cp.async.wait_group 0;" ::: "memory")

__device__ __forceinline__ void ldsm_x4(u32& r0, u32& r1, u32& r2, u32& r3, u32 addr) {
    asm volatile("ldmatrix.sync.aligned.m8n8.x4.shared.b16 {%0,%1,%2,%3}, [%4];"
                 : "=r"(r0), "=r"(r1), "=r"(r2), "=r"(r3) : "r"(addr));
}
__device__ __forceinline__ void ldsm_x4t(u32& r0, u32& r1, u32& r2, u32& r3, u32 addr) {
    asm volatile("ldmatrix.sync.aligned.m8n8.x4.trans.shared.b16 {%0,%1,%2,%3}, [%4];"
                 : "=r"(r0), "=r"(r1), "=r"(r2), "=r"(r3) : "r"(addr));
}

__device__ __forceinline__ void mma16816(float* d, u32 a0, u32 a1, u32 a2, u32 a3,
                                         u32 b0, u32 b1) {
    asm volatile("mma.sync.aligned.m16n8k16.row.col.f32.f16.f16.f32 "
                 "{%0,%1,%2,%3}, {%4,%5,%6,%7}, {%8,%9}, {%0,%1,%2,%3};"
                 : "+f"(d[0]), "+f"(d[1]), "+f"(d[2]), "+f"(d[3])
                 : "r"(a0), "r"(a1), "r"(a2), "r"(a3), "r"(b0), "r"(b1));
}

__device__ __forceinline__ float ex2(float x) {
    float y; asm("ex2.approx.f32 %0, %1;" : "=f"(y) : "f"(x)); return y;
}

__device__ __forceinline__ u32 cvt2h(float x, float y) {
    __half2 t = __floats2half2_rn(x, y);
    return *reinterpret_cast<u32*>(&t);
}

// ------------------------- fp32 -> fp16 convert -----------------------------
__global__ __launch_bounds__(256) void conv_A(const float* __restrict__ src,
                                              __half* __restrict__ hi)
{
    const int i = (blockIdx.x * 256 + threadIdx.x) * 4;
    float4 v = *(const float4*)(src + i);
    __half2 hA = __floats2half2_rn(v.x, v.y);
    __half2 hB = __floats2half2_rn(v.z, v.w);
    *(uint2*)(hi + i) = make_uint2(*(u32*)&hA, *(u32*)&hB);
}

// all three W [K,N] fp32 -> W^T fp16; K's weight pre-scaled by SCALE_LOG2
__global__ __launch_bounds__(256) void decomp_WT3(const float* __restrict__ Wq,
                                                  const float* __restrict__ Wk,
                                                  const float* __restrict__ W0)
{
    const int z = blockIdx.z;
    const float* W = (z == 0) ? Wq : (z == 1) ? Wk : W0;
    const float scl = (z == 1) ? SCALE_LOG2 : 1.0f;
    __half* hiT = g_WT[z];

    __shared__ float t[32][33];
    const int tx = threadIdx.x & 31, ty = threadIdx.x >> 5;   // (32, 8)
    const int n0 = blockIdx.x * 32, k0 = blockIdx.y * 32;
#pragma unroll
    for (int i = 0; i < 4; i++)
        t[ty + 8 * i][tx] = W[(k0 + ty + 8 * i) * D_MODEL + n0 + tx];
    __syncthreads();
#pragma unroll
    for (int i = 0; i < 4; i++) {
        float v = t[tx][ty + 8 * i] * scl;
        hiT[(long)(n0 + ty + 8 * i) * D_MODEL + k0 + tx] = __float2half_rn(v);
    }
}

// ---------------------------------------------------------------------------
// fp16 GEMM: C = A @ Wf + bias*bscale   (single pass) — unchanged (at roofline)
// ---------------------------------------------------------------------------
#define ROWB  80
#define ATILE (128 * ROWB)
#define BTILE (64 * ROWB)
#define STAGE (ATILE + BTILE)
#define GSMEM (3 * STAGE)

template <int MODE>
__device__ __forceinline__ void tc_gemm_body(const __half* __restrict__ Ah,
                                             const __half* __restrict__ BT,
                                             const float* __restrict__ bias,
                                             float bscale,
                                             float* __restrict__ out,
                                             __half* __restrict__ outh)
{
    extern __shared__ __align__(16) char smg[];
    const u32 sb = smem_u32(smg);

    const int tid = threadIdx.x;
    const int wid = tid >> 5;
    const int lane = tid & 31;
    const int warp_m = wid & 3;
    const int warp_n = wid >> 2;
    const int m0 = blockIdx.y * 128;
    const int n0 = blockIdx.x * 64;

    const int a_row = (lane & 15);
    const int a_kh  = (lane >> 4);
    const u32 aoff = (u32)((warp_m * 32 + a_row) * ROWB + a_kh * 16);
    const int b_row = (lane & 7) + ((lane >> 4) << 3);
    const int b_kh  = (lane >> 3) & 1;
    const u32 boff = (u32)((warp_n * 32 + b_row) * ROWB + b_kh * 16);

    float acc[2][4][4] = {};

    const __half* aP = Ah + ((long)m0 << 10);
    const __half* bP = BT + ((long)n0 << 10);

    auto issue = [&](int kc, int p) {
        const u32 dst = sb + (u32)p * STAGE;
        const int row_b = tid >> 2, ch = tid & 3;
#pragma unroll
        for (int i = 0; i < 2; i++) {
            const int f = i * 256 + tid;
            const int r = f >> 2, cc = f & 3;
            CP_ASYNC16(dst + r * ROWB + cc * 16,
                       aP + ((long)r << 10) + kc * 32 + cc * 8);
        }
        CP_ASYNC16(dst + ATILE + row_b * ROWB + ch * 16,
                   bP + ((long)row_b << 10) + kc * 32 + ch * 8);
    };

    issue(0, 0); CP_COMMIT();
    issue(1, 1); CP_COMMIT();
    issue(2, 2); CP_COMMIT();

    for (int c = 0; c < 32; c++) {
        const int p = c - (c / 3) * 3;
        CP_WAIT2();
        __syncthreads();

        const u32 base = sb + (u32)p * STAGE;
#pragma unroll
        for (int ks = 0; ks < 2; ks++) {
            u32 ah[2][4];
#pragma unroll
            for (int mt = 0; mt < 2; mt++) {
                const u32 a = base + aoff + mt * (16 * ROWB) + ks * 32;
                ldsm_x4(ah[mt][0], ah[mt][1], ah[mt][2], ah[mt][3], a);
            }
            u32 bh[4][2];
#pragma unroll
            for (int nt2 = 0; nt2 < 2; nt2++) {
                u32 r0, r1, r2, r3;
                ldsm_x4(r0, r1, r2, r3,
                        base + ATILE + boff + nt2 * (16 * ROWB) + ks * 32);
                bh[nt2 * 2 + 0][0] = r0; bh[nt2 * 2 + 0][1] = r1;
                bh[nt2 * 2 + 1][0] = r2; bh[nt2 * 2 + 1][1] = r3;
            }
#pragma unroll
            for (int mt = 0; mt < 2; mt++)
#pragma unroll
                for (int nt = 0; nt < 4; nt++)
                    mma16816(acc[mt][nt], ah[mt][0], ah[mt][1], ah[mt][2], ah[mt][3],
                             bh[nt][0], bh[nt][1]);
        }
        __syncthreads();
        if (c + 3 < 32) issue(c + 3, p);
        CP_COMMIT();
    }

#pragma unroll
    for (int mt = 0; mt < 2; mt++) {
#pragma unroll
        for (int nt = 0; nt < 4; nt++) {
            const int m = m0 + warp_m * 32 + mt * 16 + (lane >> 2);
            const int n = n0 + warp_n * 32 + nt * 8 + (lane & 3) * 2;
            const float bx = bias[n] * bscale, by = bias[n + 1] * bscale;
#pragma unroll
            for (int half = 0; half < 2; half++) {
                const int mm = m + half * 8;
                const float vx = acc[mt][nt][half * 2 + 0] + bx;
                const float vy = acc[mt][nt][half * 2 + 1] + by;
                if (MODE == 1) {
                    *(float2*)&out[(long)mm * D_MODEL + n] = make_float2(vx, vy);
                } else {
                    const int b = mm >> 11, s = mm & 2047;
                    const int hd = n >> 6, dk = n & 63;
                    const long o = (((long)(b * NHEAD + hd) * S_LEN + s) << 6) + dk;
                    *(u32*)&outh[o] = cvt2h(vx, vy);
                }
            }
        }
    }
}

__global__ __launch_bounds__(256, 2) void qk_gemm_tc(const float* __restrict__ bq,
                                                     const float* __restrict__ bk)
{
    if (blockIdx.z == 0)
        tc_gemm_body<2>(g_Ah, g_WT[0], bq, 1.0f, nullptr, g_Qh);
    else
        tc_gemm_body<2>(g_Ah, g_WT[1], bk, SCALE_LOG2, nullptr, g_Kh);
}

__global__ __launch_bounds__(256, 2) void out_gemm_tc(const float* __restrict__ b0,
                                                      float* __restrict__ out)
{
    tc_gemm_body<1>(g_Ah, g_WT[2], b0, 1.0f, out, nullptr);
}

// ---------------------------------------------------------------------------
// Flash attention, mma.sync fp16, causal, V = Q.
// 128 threads (4 warps x 16 q-rows), BQ=64, BKV=64 -> 3 CTAs/SM.
// S already log2-scaled (K pre-scaled). Single-precision P/V.
// smem per CTA: Q(9K) + 2 x (K+V)(18K) = 46 KB.
// ---------------------------------------------------------------------------
#define PITCH   144
#define QTILE   (64 * PITCH)           // 9216
#define KVTILE  (64 * PITCH)           // 9216
#define KV_SZ   (2 * KVTILE)           // 18432 (K + V per stage)
#define AT_SMEM (QTILE + 2 * KV_SZ)    // 46080

__global__ __launch_bounds__(128, 3) void attn_tc()
{
    extern __shared__ char smc[];
    const u32 sb = smem_u32(smc);
    const int tid  = threadIdx.x;
    const int lane = tid & 31;
    const int w    = tid >> 5;          // 0..3
    const int qi = (int)gridDim.x - 1 - (int)blockIdx.x;   // long tiles first
    const int bh = blockIdx.y;

    const int lrow = lane & 15;
    const int lch  = lane >> 4;
    const int rlo  = w * 16 + (lane >> 2);   // local q row (0..63)
    const int rhi  = rlo + 8;

    {
        const long qb = ((long)bh * S_LEN + (long)qi * 64) * DKH;
#pragma unroll
        for (int i = 0; i < 4; i++) {       // Q: 64 rows x 8 chunks = 512 xfers
            const int idx = i * 128 + tid;
            const int r = idx >> 3, c = idx & 7;
            CP_ASYNC16(sb + r * PITCH + c * 16, g_Qh + qb + r * 64 + c * 8);
        }
        const long kb = ((long)bh * S_LEN) * DKH;   // j = 0
#pragma unroll
        for (int i = 0; i < 8; i++) {       // K + V tiles
            const int t = i >> 2;           // 0:K 1:V(=Qh)
            const int idx = (i & 3) * 128 + tid;
            const int r = idx >> 3, c = idx & 7;
            const __half* src = (t == 0 ? g_Kh : g_Qh) + kb + r * 64 + c * 8;
            CP_ASYNC16(sb + QTILE + t * KVTILE + r * PITCH + c * 16, src);
        }
        CP_COMMIT();
    }

    u32 aQh[4][4];
    float o_[8][4] = {};
    float mst0 = -1e30f, mst1 = -1e30f;
    float lst0 = 0.0f, lst1 = 0.0f;

    for (int j = 0; j <= qi; j++) {
        CP_WAIT0();
        __syncthreads();
        const u32 buf = sb + QTILE + (u32)(j & 1) * KV_SZ;

        if (j == 0) {
#pragma unroll
            for (int s = 0; s < 4; s++) {
                const u32 a = (u32)((w * 16 + lrow) * PITCH + s * 32 + lch * 16);
                ldsm_x4(aQh[s][0], aQh[s][1], aQh[s][2], aQh[s][3], sb + a);
            }
        }
        if (j < qi) {
            const long kb = ((long)bh * S_LEN + (long)(j + 1) * 64) * DKH;
            const u32 nbuf = sb + QTILE + (u32)((j + 1) & 1) * KV_SZ;
#pragma unroll
            for (int i = 0; i < 8; i++) {
                const int t = i >> 2;
                const int idx = (i & 3) * 128 + tid;
                const int r = idx >> 3, c = idx & 7;
                const __half* src = (t == 0 ? g_Kh : g_Qh) + kb + r * 64 + c * 8;
                CP_ASYNC16(nbuf + t * KVTILE + r * PITCH + c * 16, src);
            }
            CP_COMMIT();
        }

        // ---- S = Qh Kh^T (already log2-scaled) : 16 q-rows x 64 kv ----
        float s_[8][4] = {};
        const u32 bbase = buf + (u32)(lrow * PITCH + lch * 16);

#pragma unroll
        for (int ks = 0; ks < 4; ks++) {
            const u32 tb = bbase + ks * 32;
#pragma unroll
            for (int nc = 0; nc < 4; nc++) {
                u32 h0, h1, h2, h3;
                ldsm_x4(h0, h1, h2, h3, tb + nc * (16 * PITCH));
                mma16816(s_[2 * nc],     aQh[ks][0], aQh[ks][1], aQh[ks][2], aQh[ks][3], h0, h2);
                mma16816(s_[2 * nc + 1], aQh[ks][0], aQh[ks][1], aQh[ks][2], aQh[ks][3], h1, h3);
            }
        }

        // ---- online softmax (log2 domain) ----
        float rmx0 = -1e30f, rmx1 = -1e30f;
#pragma unroll
        for (int nt = 0; nt < 8; nt++) {
            if (j == qi) {
                const int c0 = nt * 8 + (lane & 3) * 2;
                if (c0 > rlo)     s_[nt][0] = -1e30f;
                if (c0 + 1 > rlo) s_[nt][1] = -1e30f;
                if (c0 > rhi)     s_[nt][2] = -1e30f;
                if (c0 + 1 > rhi) s_[nt][3] = -1e30f;
            }
            rmx0 = fmaxf(rmx0, fmaxf(s_[nt][0], s_[nt][1]));
            rmx1 = fmaxf(rmx1, fmaxf(s_[nt][2], s_[nt][3]));
        }
        rmx0 = fmaxf(rmx0, __shfl_xor_sync(0xffffffffu, rmx0, 1));
        rmx0 = fmaxf(rmx0, __shfl_xor_sync(0xffffffffu, rmx0, 2));
        rmx1 = fmaxf(rmx1, __shfl_xor_sync(0xffffffffu, rmx1, 1));
        rmx1 = fmaxf(rmx1, __shfl_xor_sync(0xffffffffu, rmx1, 2));
        const float mn0 = fmaxf(mst0, rmx0);
        const float mn1 = fmaxf(mst1, rmx1);
        const float al0 = ex2(mst0 - mn0);
        const float al1 = ex2(mst1 - mn1);
        float sum0 = 0.0f, sum1 = 0.0f;
#pragma unroll
        for (int nt = 0; nt < 8; nt++) {
            s_[nt][0] = ex2(s_[nt][0] - mn0);
            s_[nt][1] = ex2(s_[nt][1] - mn0);
            s_[nt][2] = ex2(s_[nt][2] - mn1);
            s_[nt][3] = ex2(s_[nt][3] - mn1);
            sum0 += s_[nt][0] + s_[nt][1];
            sum1 += s_[nt][2] + s_[nt][3];
        }
        sum0 += __shfl_xor_sync(0xffffffffu, sum0, 1);
        sum0 += __shfl_xor_sync(0xffffffffu, sum0, 2);
        sum1 += __shfl_xor_sync(0xffffffffu, sum1, 1);
        sum1 += __shfl_xor_sync(0xffffffffu, sum1, 2);
        lst0 = lst0 * al0 + sum0;
        lst1 = lst1 * al1 + sum1;
        mst0 = mn0;
        mst1 = mn1;
#pragma unroll
        for (int nt = 0; nt < 8; nt++) {
            o_[nt][0] *= al0; o_[nt][1] *= al0;
            o_[nt][2] *= al1; o_[nt][3] *= al1;
        }

        // ---- O += P V : 64 kv rows, single sweep ----
        const u32 vh_b = buf + KVTILE;
#pragma unroll
        for (int s = 0; s < 4; s++) {
            u32 pf[2];
            pf[0] = cvt2h(s_[2 * s][0], s_[2 * s][1]);
            pf[1] = cvt2h(s_[2 * s][2], s_[2 * s][3]);
            u32 pg0 = cvt2h(s_[2 * s + 1][0], s_[2 * s + 1][1]);
            u32 pg1 = cvt2h(s_[2 * s + 1][2], s_[2 * s + 1][3]);

            u32 vh_[8][2];
#pragma unroll
            for (int tp = 0; tp < 4; tp++) {
                const u32 a = vh_b + (u32)((s * 16 + lrow) * PITCH + (tp * 2 + lch) * 16);
                u32 r0, r1, r2, r3;
                ldsm_x4t(r0, r1, r2, r3, a);
                vh_[2 * tp][0] = r0; vh_[2 * tp][1] = r1;
                vh_[2 * tp + 1][0] = r2; vh_[2 * tp + 1][1] = r3;
            }
#pragma unroll
            for (int nt = 0; nt < 8; nt++)
                mma16816(o_[nt], pf[0], pf[1], pg0, pg1, vh_[nt][0], vh_[nt][1]);
        }
    }

    const int bat = bh >> 4, head = bh & 15;
    const float i0 = 1.0f / lst0;
    const float i1 = 1.0f / lst1;
    const int row0 = qi * 64 + rlo;
#pragma unroll
    for (int nt = 0; nt < 8; nt++) {
        const int d = head * 64 + nt * 8 + (lane & 3) * 2;
        {
            const long a = ((long)(bat * S_LEN + row0) << 10) + d;
            *(u32*)&g_Ah[a] = cvt2h(o_[nt][0] * i0, o_[nt][1] * i0);
        }
        {
            const long a = ((long)(bat * S_LEN + row0 + 8) << 10) + d;
            *(u32*)&g_Ah[a] = cvt2h(o_[nt][2] * i1, o_[nt][3] * i1);
        }
    }
}

// ---------------------------------------------------------------------------
extern "C" void kernel_launch(void* const* d_in, const int* in_sizes, int n_in,
                              void* d_out, int out_size)
{
    const float* x  = (const float*)d_in[0];
    const float* Wq = (const float*)d_in[1];
    const float* bq = (const float*)d_in[2];
    const float* Wk = (const float*)d_in[3];
    const float* bk = (const float*)d_in[4];
    const float* W0 = (const float*)d_in[5];
    const float* b0 = (const float*)d_in[6];
    float* out = (float*)d_out;

    __half* dAh;
    cudaGetSymbolAddress((void**)&dAh, g_Ah);

    cudaFuncSetAttribute(attn_tc, cudaFuncAttributeMaxDynamicSharedMemorySize, AT_SMEM);
    cudaFuncSetAttribute(qk_gemm_tc, cudaFuncAttributeMaxDynamicSharedMemorySize, GSMEM);
    cudaFuncSetAttribute(out_gemm_tc, cudaFuncAttributeMaxDynamicSharedMemorySize, GSMEM);

    // 1) convert x -> fp16, weights -> fp16^T (K pre-scaled)
    conv_A<<<M_TOK * D_MODEL / 1024, 256>>>(x, dAh);
    dim3 wt_grid(32, 32, 3);
    decomp_WT3<<<wt_grid, 256>>>(Wq, Wk, W0);

    // 2) Q & K projections (single-pass) -> fp16 head layout
    dim3 qk_grid(D_MODEL / 64, M_TOK / 128, 2);    // (16, 32, 2)
    qk_gemm_tc<<<qk_grid, 256, GSMEM>>>(bq, bk);

    // 3) attention -> g_Ah (fp16), BQ=64 small CTAs, 3/SM
    dim3 attn_grid(S_LEN / 64, BATCH * NHEAD);      // (32, 32)
    attn_tc<<<attn_grid, 128, AT_SMEM>>>();

    // 4) output projection (single-pass)
    dim3 o_grid(D_MODEL / 64, M_TOK / 128);         // (16, 32)
    out_gemm_tc<<<o_grid, 256, GSMEM>>>(b0, out);
}